// round 8
// baseline (speedup 1.0000x reference)
#include <cuda_runtime.h>
#include <cuda_bf16.h>
#include <cstdint>
#include <cstddef>

#define B 2
#define T 2048
#define D 2048
#define H 16
#define HD 128
#define E 8
#define FH 8192
#define EPSV 1e-6f
#define MT (B*T)

// ---------------- scratch (device globals; no allocation) ----------------
__device__ float g_xn  [(size_t)B*T*D];
__device__ float g_h   [(size_t)B*T*D];
__device__ float g_hn  [(size_t)B*T*D];
__device__ float g_logits[(size_t)B*T*E];
__device__ float g_disp  [(size_t)B*T*E];
__device__ float g_comb  [(size_t)B*T*E];
__device__ float g_slots [(size_t)B*E*D];
__device__ float g_gact  [(size_t)B*E*FH];
#define KS 8
__device__ float g_ypart[(size_t)KS*B*E*D];
__device__ float g_y    [(size_t)B*E*D];
// bf16 split operands
__device__ __nv_bfloat16 g_ah[(size_t)MT*D];
__device__ __nv_bfloat16 g_al[(size_t)MT*D];
__device__ __nv_bfloat16 g_qh[(size_t)MT*D];
__device__ __nv_bfloat16 g_ql[(size_t)MT*D];
__device__ __nv_bfloat16 g_kh[(size_t)MT*D];
__device__ __nv_bfloat16 g_kl[(size_t)MT*D];
__device__ __nv_bfloat16 g_vh[(size_t)MT*D];
__device__ __nv_bfloat16 g_vl[(size_t)MT*D];
__device__ __nv_bfloat16 g_oh[(size_t)MT*D];
__device__ __nv_bfloat16 g_ol[(size_t)MT*D];
__device__ __nv_bfloat16 g_wth[(size_t)4*D*D];
__device__ __nv_bfloat16 g_wtl[(size_t)4*D*D];

// ---------------- helpers ----------------
__device__ __forceinline__ uint32_t smem_u32(const void* p) {
    uint32_t a;
    asm("{ .reg .u64 t; cvta.to.shared.u64 t, %1; cvt.u32.u64 %0, t; }" : "=r"(a) : "l"(p));
    return a;
}
__device__ __forceinline__ void cp_async16(uint32_t saddr, const void* gaddr) {
    asm volatile("cp.async.ca.shared.global [%0], [%1], 16;" :: "r"(saddr), "l"(gaddr));
}
__device__ __forceinline__ void cp_commit() {
    asm volatile("cp.async.commit_group;");
}
template<int N>
__device__ __forceinline__ void cp_wait() {
    asm volatile("cp.async.wait_group %0;" :: "n"(N));
}
__device__ __forceinline__ void ldmx4(uint32_t* r, uint32_t addr) {
    asm volatile("ldmatrix.sync.aligned.m8n8.x4.shared.b16 {%0,%1,%2,%3}, [%4];"
                 : "=r"(r[0]), "=r"(r[1]), "=r"(r[2]), "=r"(r[3]) : "r"(addr));
}
__device__ __forceinline__ void ldmx4t(uint32_t* r, uint32_t addr) {
    asm volatile("ldmatrix.sync.aligned.m8n8.x4.trans.shared.b16 {%0,%1,%2,%3}, [%4];"
                 : "=r"(r[0]), "=r"(r[1]), "=r"(r[2]), "=r"(r[3]) : "r"(addr));
}
__device__ __forceinline__ void mma16816(float* c, const uint32_t* a, uint32_t b0, uint32_t b1) {
    asm volatile(
        "mma.sync.aligned.m16n8k16.row.col.f32.bf16.bf16.f32 "
        "{%0,%1,%2,%3}, {%4,%5,%6,%7}, {%8,%9}, {%0,%1,%2,%3};"
        : "+f"(c[0]), "+f"(c[1]), "+f"(c[2]), "+f"(c[3])
        : "r"(a[0]), "r"(a[1]), "r"(a[2]), "r"(a[3]), "r"(b0), "r"(b1));
}
// software exp2: FFMA-pipe only, rel err ~2.4e-6
__device__ __forceinline__ float fex2(float x) {
    x = fmaxf(x, -126.f);
    float t = x + 12582912.f;                    // RN to integer in low mantissa bits
    int ti = __float_as_int(t);
    float f = x - (t - 12582912.f);              // frac in [-0.5, 0.5]
    float p = 0.00133335581f;
    p = fmaf(p, f, 0.00961812911f);
    p = fmaf(p, f, 0.05550410866f);
    p = fmaf(p, f, 0.24022650696f);
    p = fmaf(p, f, 0.69314718056f);
    p = fmaf(p, f, 1.0f);
    return __int_as_float(__float_as_int(p) + (ti << 23));
}
__device__ __forceinline__ void packsplit(float p0, float p1, uint32_t& hi, uint32_t& lo) {
    __nv_bfloat16 h0 = __float2bfloat16_rn(p0), h1 = __float2bfloat16_rn(p1);
    __nv_bfloat162 hv(h0, h1);
    hi = *reinterpret_cast<uint32_t*>(&hv);
    __nv_bfloat162 lv(__float2bfloat16_rn(p0 - __bfloat162float(h0)),
                      __float2bfloat16_rn(p1 - __bfloat162float(h1)));
    lo = *reinterpret_cast<uint32_t*>(&lv);
}

// ---------------- rmsnorm (optional fused bf16 hi/lo split) ----------------
__global__ void rmsnorm_kernel(const float* __restrict__ x, const float* __restrict__ w,
                               float* __restrict__ out,
                               __nv_bfloat16* __restrict__ hi, __nv_bfloat16* __restrict__ lo) {
    int row = blockIdx.x;
    const float* xp = x + (size_t)row * D;
    float v[8];
    float ss = 0.f;
#pragma unroll
    for (int i = 0; i < 8; i++) { v[i] = xp[threadIdx.x + i*256]; ss += v[i]*v[i]; }
    __shared__ float red[256];
    red[threadIdx.x] = ss; __syncthreads();
    for (int s = 128; s > 0; s >>= 1) {
        if (threadIdx.x < s) red[threadIdx.x] += red[threadIdx.x + s];
        __syncthreads();
    }
    float rms = rsqrtf(red[0] / (float)D + EPSV);
    float* op = out + (size_t)row * D;
#pragma unroll
    for (int i = 0; i < 8; i++) {
        int d = threadIdx.x + i*256;
        float o = v[i]*rms*w[d];
        op[d] = o;
        if (hi) {
            __nv_bfloat16 hb = __float2bfloat16_rn(o);
            hi[(size_t)row*D + d] = hb;
            lo[(size_t)row*D + d] = __float2bfloat16_rn(o - __bfloat162float(hb));
        }
    }
}

// ---------------- transpose + split weights: W[K,N] -> WT[N,K] hi/lo bf16 ----------------
__global__ void wsplit_kernel(const float* __restrict__ W,
                              __nv_bfloat16* __restrict__ th, __nv_bfloat16* __restrict__ tl) {
    __shared__ float t[32][33];
    int n0 = blockIdx.x * 32, k0 = blockIdx.y * 32;
    int tx = threadIdx.x, ty = threadIdx.y;   // 32 x 8
#pragma unroll
    for (int i = 0; i < 4; i++)
        t[ty + 8*i][tx] = W[(size_t)(k0 + ty + 8*i) * D + n0 + tx];
    __syncthreads();
#pragma unroll
    for (int i = 0; i < 4; i++) {
        float v = t[tx][ty + 8*i];
        size_t o = (size_t)(n0 + ty + 8*i) * D + k0 + tx;
        __nv_bfloat16 hv = __float2bfloat16_rn(v);
        th[o] = hv;
        tl[o] = __float2bfloat16_rn(v - __bfloat162float(hv));
    }
}

// ---------------- mma.sync GEMM: C[M,N] = A[M,K] @ B^T (B given [N,K]) ----------------
// mode 0: fp32 C (+Res). mode 1: rope + bf16 hi/lo split. mode 2: bf16 hi/lo split.
#define GM 128
#define GN 128
#define GK 32
#define TSTR 40
#define TILE_B2 (128*TSTR*2)
#define STG_B2 (4*TILE_B2)
#define MMA_SMEM (2*STG_B2)

__global__ __launch_bounds__(256, 2)
void mma_gemm_kernel(const __nv_bfloat16* __restrict__ Ah, const __nv_bfloat16* __restrict__ Al,
                     const __nv_bfloat16* __restrict__ Bh, const __nv_bfloat16* __restrict__ Bl,
                     const float* __restrict__ Res, float* __restrict__ C,
                     int mode, const float* __restrict__ fc,
                     __nv_bfloat16* __restrict__ Chi, __nv_bfloat16* __restrict__ Clo,
                     int Mdim, int Ndim, int Kdim) {
    extern __shared__ char smem[];
    uint32_t sb = smem_u32(smem);
    int tid = threadIdx.x, lane = tid & 31, warp = tid >> 5;
    int wm = warp & 3, wn = warp >> 2;
    int m0 = blockIdx.y * GM, n0 = blockIdx.x * GN;

    int lrow[2], lcol[2];
    uint32_t sdst[2];
#pragma unroll
    for (int p = 0; p < 2; p++) {
        int idx = tid + p*256;
        lrow[p] = idx >> 2;
        lcol[p] = (idx & 3) * 8;
        sdst[p] = (uint32_t)(lrow[p]*TSTR + lcol[p]) * 2;
    }

    const int nkt = Kdim / GK;

    auto issue = [&](int kt, int stage) {
        uint32_t s0 = sb + stage * STG_B2;
        const __nv_bfloat16* srcs[4] = {
            Ah + (size_t)m0 * Kdim, Al + (size_t)m0 * Kdim,
            Bh + (size_t)n0 * Kdim, Bl + (size_t)n0 * Kdim };
#pragma unroll
        for (int tl = 0; tl < 4; tl++) {
#pragma unroll
            for (int p = 0; p < 2; p++) {
                const __nv_bfloat16* g = srcs[tl] + (size_t)lrow[p] * Kdim + kt*GK + lcol[p];
                cp_async16(s0 + tl*TILE_B2 + sdst[p], g);
            }
        }
        cp_commit();
    };

    float acc[2][8][4];
#pragma unroll
    for (int mi = 0; mi < 2; mi++)
#pragma unroll
        for (int nj = 0; nj < 8; nj++)
#pragma unroll
            for (int c = 0; c < 4; c++) acc[mi][nj][c] = 0.f;

    int lr = lane & 15, lc8 = (lane >> 4) << 3;

    issue(0, 0);

    for (int kt = 0; kt < nkt; kt++) {
        int stage = kt & 1;
        if (kt + 1 < nkt) { issue(kt + 1, stage ^ 1); cp_wait<1>(); }
        else              { cp_wait<0>(); }
        __syncthreads();

        uint32_t s0 = sb + stage * STG_B2;
        uint32_t sAh = s0, sAl = s0 + TILE_B2, sBh = s0 + 2*TILE_B2, sBl = s0 + 3*TILE_B2;

#pragma unroll
        for (int ks = 0; ks < 2; ks++) {
            int kc = ks*16 + lc8;
            uint32_t ah[2][4], al[2][4], bh[4][4], bl[4][4];
#pragma unroll
            for (int mi = 0; mi < 2; mi++)
                ldmx4(ah[mi], sAh + (uint32_t)((wm*32 + mi*16 + lr)*TSTR + kc) * 2);
#pragma unroll
            for (int njp = 0; njp < 4; njp++)
                ldmx4(bh[njp], sBh + (uint32_t)((wn*64 + njp*16 + lr)*TSTR + kc) * 2);
#pragma unroll
            for (int mi = 0; mi < 2; mi++)
#pragma unroll
                for (int njp = 0; njp < 4; njp++) {
                    mma16816(acc[mi][2*njp+0], ah[mi], bh[njp][0], bh[njp][2]);
                    mma16816(acc[mi][2*njp+1], ah[mi], bh[njp][1], bh[njp][3]);
                }
#pragma unroll
            for (int mi = 0; mi < 2; mi++)
                ldmx4(al[mi], sAl + (uint32_t)((wm*32 + mi*16 + lr)*TSTR + kc) * 2);
#pragma unroll
            for (int mi = 0; mi < 2; mi++)
#pragma unroll
                for (int njp = 0; njp < 4; njp++) {
                    mma16816(acc[mi][2*njp+0], al[mi], bh[njp][0], bh[njp][2]);
                    mma16816(acc[mi][2*njp+1], al[mi], bh[njp][1], bh[njp][3]);
                }
#pragma unroll
            for (int njp = 0; njp < 4; njp++)
                ldmx4(bl[njp], sBl + (uint32_t)((wn*64 + njp*16 + lr)*TSTR + kc) * 2);
#pragma unroll
            for (int mi = 0; mi < 2; mi++)
#pragma unroll
                for (int njp = 0; njp < 4; njp++) {
                    mma16816(acc[mi][2*njp+0], ah[mi], bl[njp][0], bl[njp][2]);
                    mma16816(acc[mi][2*njp+1], ah[mi], bl[njp][1], bl[njp][3]);
                }
        }
        __syncthreads();
    }

    int g = lane >> 2, tg = lane & 3;
    if (mode == 0) {
#pragma unroll
        for (int mi = 0; mi < 2; mi++) {
            size_t row0 = (size_t)(m0 + wm*32 + mi*16 + g);
#pragma unroll
            for (int nj = 0; nj < 8; nj++) {
                size_t col = (size_t)(n0 + wn*64 + nj*8 + tg*2);
                float2 v0 = make_float2(acc[mi][nj][0], acc[mi][nj][1]);
                float2 v1 = make_float2(acc[mi][nj][2], acc[mi][nj][3]);
                if (Res) {
                    float2 r0 = *(const float2*)(Res + row0*Ndim + col);
                    float2 r1 = *(const float2*)(Res + (row0+8)*Ndim + col);
                    v0.x += r0.x; v0.y += r0.y; v1.x += r1.x; v1.y += r1.y;
                }
                *(float2*)(C + row0*Ndim + col) = v0;
                *(float2*)(C + (row0+8)*Ndim + col) = v1;
            }
        }
    } else {
#pragma unroll
        for (int mi = 0; mi < 2; mi++) {
            size_t row0 = (size_t)(m0 + wm*32 + mi*16 + g);
            size_t row1 = row0 + 8;
#pragma unroll
            for (int nj = 0; nj < 8; nj++) {
                int col = n0 + wn*64 + nj*8 + tg*2;
                float2 v0 = make_float2(acc[mi][nj][0], acc[mi][nj][1]);
                float2 v1 = make_float2(acc[mi][nj][2], acc[mi][nj][3]);
                if (mode == 1) {
                    int cb = col & (HD - 1);               // even: pair base in head
                    float2 c0 = *(const float2*)(fc + (size_t)(row0 & (T-1))*HD + cb);
                    float2 c1 = *(const float2*)(fc + (size_t)(row1 & (T-1))*HD + cb);
                    v0 = make_float2(v0.x*c0.x - v0.y*c0.y, v0.x*c0.y + v0.y*c0.x);
                    v1 = make_float2(v1.x*c1.x - v1.y*c1.y, v1.x*c1.y + v1.y*c1.x);
                }
                uint32_t h0, l0w, h1, l1w;
                packsplit(v0.x, v0.y, h0, l0w);
                packsplit(v1.x, v1.y, h1, l1w);
                *(uint32_t*)(Chi + row0*Ndim + col) = h0;
                *(uint32_t*)(Clo + row0*Ndim + col) = l0w;
                *(uint32_t*)(Chi + row1*Ndim + col) = h1;
                *(uint32_t*)(Clo + row1*Ndim + col) = l1w;
            }
        }
    }
}

// ---------------- flash attention (mma.sync bf16, 3-term split, software exp2) ----------------
#define AQ 128
#define AKV 64
#define ASTRB 272
#define ATILE_B (AKV*ASTRB)
#define ASTG_B (4*ATILE_B)
#define FATTN_SMEM (2*ASTG_B)
#define SCL2 0.12751743867f             // (1/sqrt(128)) * log2(e)

__global__ __launch_bounds__(256)
void fattn_kernel(const __nv_bfloat16* __restrict__ Qh, const __nv_bfloat16* __restrict__ Ql,
                  const __nv_bfloat16* __restrict__ Kh, const __nv_bfloat16* __restrict__ Kl,
                  const __nv_bfloat16* __restrict__ Vh, const __nv_bfloat16* __restrict__ Vl,
                  __nv_bfloat16* __restrict__ Oh, __nv_bfloat16* __restrict__ Ol,
                  const int* __restrict__ causal_flag) {
    extern __shared__ char smem[];
    uint32_t sb = smem_u32(smem);
    int tid = threadIdx.x, lane = tid & 31, warp = tid >> 5;
    int g = lane >> 2, tg = lane & 3;
    int q0 = blockIdx.x * AQ, h = blockIdx.y, b = blockIdx.z;
    bool causal = (*causal_flag) != 0;
    int wrow = q0 + warp * 16;

    uint32_t s0 = sb, s1 = sb + ASTG_B;

    const size_t bbase = ((size_t)b * T) << 11;
    const size_t hbase = (size_t)h * HD;

#pragma unroll
    for (int half = 0; half < 2; half++) {
        const __nv_bfloat16* src = half ? Ql : Qh;
#pragma unroll
        for (int j = 0; j < 8; j++) {
            int c = tid + j*256;
            int r = c >> 4, col = c & 15;
            cp_async16(s0 + half*(AQ*ASTRB) + r*ASTRB + col*16,
                       src + bbase + ((size_t)(q0 + r) << 11) + hbase + col*8);
        }
    }
    cp_commit();

    auto issue_kv = [&](int kvt, uint32_t stg) {
        int k0 = kvt * AKV;
        const __nv_bfloat16* ptrs[4] = {Kh, Kl, Vh, Vl};
#pragma unroll
        for (int tl = 0; tl < 4; tl++) {
#pragma unroll
            for (int j = 0; j < 4; j++) {
                int c = tid + j*256;
                int r = c >> 4, col = c & 15;
                cp_async16(stg + tl*ATILE_B + r*ASTRB + col*16,
                           ptrs[tl] + bbase + ((size_t)(k0 + r) << 11) + hbase + col*8);
            }
        }
        cp_commit();
    };

    int ntile = causal ? (q0 + AQ)/AKV : T/AKV;
    issue_kv(0, s1);

    cp_wait<1>();
    __syncthreads();

    int lr = lane & 15, c8 = (lane >> 4) << 3;
    uint32_t qfh[8][4], qfl[8][4];
#pragma unroll
    for (int ks = 0; ks < 8; ks++) {
        uint32_t a = s0 + (warp*16 + lr)*ASTRB + (ks*16 + c8)*2;
        ldmx4(qfh[ks], a);
        ldmx4(qfl[ks], a + AQ*ASTRB);
    }
    __syncthreads();

    float oa[16][4];
#pragma unroll
    for (int i = 0; i < 16; i++) { oa[i][0]=0.f; oa[i][1]=0.f; oa[i][2]=0.f; oa[i][3]=0.f; }
    float m0 = -1e30f, m1 = -1e30f, l0 = 0.f, l1 = 0.f;

    for (int kvt = 0; kvt < ntile; kvt++) {
        uint32_t cur = (kvt & 1) ? s0 : s1;
        uint32_t nxt = (kvt & 1) ? s1 : s0;
        if (kvt + 1 < ntile) { issue_kv(kvt + 1, nxt); cp_wait<1>(); }
        else                 { cp_wait<0>(); }
        __syncthreads();
        int k0 = kvt * AKV;

        if (!causal || k0 <= wrow + 15) {
            uint32_t KHs = cur, KLs = cur + ATILE_B, VHs = cur + 2*ATILE_B, VLs = cur + 3*ATILE_B;
            float sa[8][4];
#pragma unroll
            for (int nj = 0; nj < 8; nj++) { sa[nj][0]=0.f; sa[nj][1]=0.f; sa[nj][2]=0.f; sa[nj][3]=0.f; }
#pragma unroll
            for (int ks = 0; ks < 8; ks++) {
                uint32_t bh[4][4], bl[4][4];
#pragma unroll
                for (int n4 = 0; n4 < 4; n4++)
                    ldmx4(bh[n4], KHs + (n4*16 + lr)*ASTRB + (ks*16 + c8)*2);
#pragma unroll
                for (int n4 = 0; n4 < 4; n4++) {
                    mma16816(sa[2*n4+0], qfh[ks], bh[n4][0], bh[n4][2]);
                    mma16816(sa[2*n4+1], qfh[ks], bh[n4][1], bh[n4][3]);
                }
#pragma unroll
                for (int n4 = 0; n4 < 4; n4++)
                    ldmx4(bl[n4], KLs + (n4*16 + lr)*ASTRB + (ks*16 + c8)*2);
#pragma unroll
                for (int n4 = 0; n4 < 4; n4++) {
                    mma16816(sa[2*n4+0], qfh[ks], bl[n4][0], bl[n4][2]);
                    mma16816(sa[2*n4+1], qfh[ks], bl[n4][1], bl[n4][3]);
                    mma16816(sa[2*n4+0], qfl[ks], bh[n4][0], bh[n4][2]);
                    mma16816(sa[2*n4+1], qfl[ks], bh[n4][1], bh[n4][3]);
                }
            }
            if (causal && k0 + 63 > wrow) {
#pragma unroll
                for (int nj = 0; nj < 8; nj++) {
                    int col = k0 + nj*8 + 2*tg;
                    if (col     > wrow + g)     sa[nj][0] = -1e30f;
                    if (col + 1 > wrow + g)     sa[nj][1] = -1e30f;
                    if (col     > wrow + g + 8) sa[nj][2] = -1e30f;
                    if (col + 1 > wrow + g + 8) sa[nj][3] = -1e30f;
                }
            }
            float mt0 = -1e30f, mt1 = -1e30f;
#pragma unroll
            for (int nj = 0; nj < 8; nj++) {
                mt0 = fmaxf(mt0, fmaxf(sa[nj][0], sa[nj][1]));
                mt1 = fmaxf(mt1, fmaxf(sa[nj][2], sa[nj][3]));
            }
            mt0 = fmaxf(mt0, __shfl_xor_sync(0xffffffffu, mt0, 1));
            mt0 = fmaxf(mt0, __shfl_xor_sync(0xffffffffu, mt0, 2));
            mt1 = fmaxf(mt1, __shfl_xor_sync(0xffffffffu, mt1, 1));
            mt1 = fmaxf(mt1, __shfl_xor_sync(0xffffffffu, mt1, 2));
            float mn0 = fmaxf(m0, mt0), mn1 = fmaxf(m1, mt1);
            float al0 = fex2((m0 - mn0)*SCL2), al1 = fex2((m1 - mn1)*SCL2);
            float nb0 = mn0 * SCL2, nb1 = mn1 * SCL2;
            float ls0 = 0.f, ls1 = 0.f;
#pragma unroll
            for (int nj = 0; nj < 8; nj++) {
                float p0 = fex2(fmaf(sa[nj][0], SCL2, -nb0));
                float p1 = fex2(fmaf(sa[nj][1], SCL2, -nb0));
                float p2 = fex2(fmaf(sa[nj][2], SCL2, -nb1));
                float p3 = fex2(fmaf(sa[nj][3], SCL2, -nb1));
                sa[nj][0]=p0; sa[nj][1]=p1; sa[nj][2]=p2; sa[nj][3]=p3;
                ls0 += p0 + p1; ls1 += p2 + p3;
            }
            ls0 += __shfl_xor_sync(0xffffffffu, ls0, 1);
            ls0 += __shfl_xor_sync(0xffffffffu, ls0, 2);
            ls1 += __shfl_xor_sync(0xffffffffu, ls1, 1);
            ls1 += __shfl_xor_sync(0xffffffffu, ls1, 2);
            l0 = l0*al0 + ls0; l1 = l1*al1 + ls1;
            m0 = mn0; m1 = mn1;
#pragma unroll
            for (int i2 = 0; i2 < 16; i2++) {
                oa[i2][0]*=al0; oa[i2][1]*=al0; oa[i2][2]*=al1; oa[i2][3]*=al1;
            }
            uint32_t pfh[4][4], pfl[4][4];
#pragma unroll
            for (int kt = 0; kt < 4; kt++) {
                packsplit(sa[2*kt][0],   sa[2*kt][1],   pfh[kt][0], pfl[kt][0]);
                packsplit(sa[2*kt][2],   sa[2*kt][3],   pfh[kt][1], pfl[kt][1]);
                packsplit(sa[2*kt+1][0], sa[2*kt+1][1], pfh[kt][2], pfl[kt][2]);
                packsplit(sa[2*kt+1][2], sa[2*kt+1][3], pfh[kt][3], pfl[kt][3]);
            }
            int mlane = lane >> 3;
            int kvr = (mlane & 1)*8 + (lane & 7);
            int hdc = (mlane >> 1)*8;
#pragma unroll
            for (int kt = 0; kt < 4; kt++) {
                uint32_t rbase = (uint32_t)((kt*16 + kvr)*ASTRB + hdc*2);
#pragma unroll
                for (int hp = 0; hp < 8; hp++) {
                    uint32_t vfh[4], vfl[4];
                    ldmx4t(vfh, VHs + rbase + hp*32);
                    ldmx4t(vfl, VLs + rbase + hp*32);
                    mma16816(oa[2*hp+0], pfh[kt], vfh[0], vfh[1]);
                    mma16816(oa[2*hp+1], pfh[kt], vfh[2], vfh[3]);
                    mma16816(oa[2*hp+0], pfh[kt], vfl[0], vfl[1]);
                    mma16816(oa[2*hp+1], pfh[kt], vfl[2], vfl[3]);
                    mma16816(oa[2*hp+0], pfl[kt], vfh[0], vfh[1]);
                    mma16816(oa[2*hp+1], pfl[kt], vfh[2], vfh[3]);
                }
            }
        }
        __syncthreads();
    }

    float inv0 = 1.f / l0, inv1 = 1.f / l1;
    size_t off0 = bbase + ((size_t)(wrow + g) << 11) + hbase;
    size_t off1 = bbase + ((size_t)(wrow + g + 8) << 11) + hbase;
#pragma unroll
    for (int hp = 0; hp < 16; hp++) {
        int hd = hp*8 + 2*tg;
        uint32_t h0, l0w, h1, l1w;
        packsplit(oa[hp][0]*inv0, oa[hp][1]*inv0, h0, l0w);
        packsplit(oa[hp][2]*inv1, oa[hp][3]*inv1, h1, l1w);
        *(uint32_t*)(Oh + off0 + hd) = h0;
        *(uint32_t*)(Ol + off0 + hd) = l0w;
        *(uint32_t*)(Oh + off1 + hd) = h1;
        *(uint32_t*)(Ol + off1 + hd) = l1w;
    }
}

// ---------------- router logits: hn @ slots_w (D x E) ----------------
__global__ void logits_kernel(const float* __restrict__ hn, const float* __restrict__ sw,
                              float* __restrict__ out) {
    int row = blockIdx.x;
    const float* hp = hn + (size_t)row * D;
    float acc[E];
#pragma unroll
    for (int e = 0; e < E; e++) acc[e] = 0.f;
#pragma unroll
    for (int i = 0; i < 8; i++) {
        int d = threadIdx.x + i*256;
        float hv = hp[d];
        const float* swp = sw + (size_t)d * E;
#pragma unroll
        for (int e = 0; e < E; e++) acc[e] += hv * swp[e];
    }
#pragma unroll
    for (int e = 0; e < E; e++)
        for (int o = 16; o > 0; o >>= 1) acc[e] += __shfl_xor_sync(0xffffffffu, acc[e], o);
    __shared__ float red[8][E];
    int warp = threadIdx.x >> 5, lane = threadIdx.x & 31;
    if (lane == 0)
#pragma unroll
        for (int e = 0; e < E; e++) red[warp][e] = acc[e];
    __syncthreads();
    if (threadIdx.x < E) {
        float s = 0.f;
#pragma unroll
        for (int w = 0; w < 8; w++) s += red[w][threadIdx.x];
        out[(size_t)row*E + threadIdx.x] = s;
    }
}

// ---------------- dispatch softmax (over T, per (b,e)) ----------------
__global__ void dispatch_softmax_kernel(const float* __restrict__ lg, float* __restrict__ out) {
    int b = blockIdx.x >> 3, e = blockIdx.x & 7;
    const float* lp = lg + (size_t)b*T*E + e;
    float v[8];
    float m = -1e30f;
#pragma unroll
    for (int i = 0; i < 8; i++) {
        v[i] = lp[(size_t)(threadIdx.x + i*256)*E];
        m = fmaxf(m, v[i]);
    }
    __shared__ float red[256];
    red[threadIdx.x] = m; __syncthreads();
    for (int s = 128; s > 0; s >>= 1) {
        if (threadIdx.x < s) red[threadIdx.x] = fmaxf(red[threadIdx.x], red[threadIdx.x + s]);
        __syncthreads();
    }
    m = red[0]; __syncthreads();
    float ssum = 0.f;
#pragma unroll
    for (int i = 0; i < 8; i++) { v[i] = __expf(v[i] - m); ssum += v[i]; }
    red[threadIdx.x] = ssum; __syncthreads();
    for (int s = 128; s > 0; s >>= 1) {
        if (threadIdx.x < s) red[threadIdx.x] += red[threadIdx.x + s];
        __syncthreads();
    }
    float inv = 1.f / red[0];
    float* op = out + (size_t)b*T*E + e;
#pragma unroll
    for (int i = 0; i < 8; i++) op[(size_t)(threadIdx.x + i*256)*E] = v[i]*inv;
}

// ---------------- combine softmax (over E, per (b,t)) ----------------
__global__ void combine_softmax_kernel(const float* __restrict__ lg, float* __restrict__ out) {
    int row = blockIdx.x*256 + threadIdx.x;
    const float* lp = lg + (size_t)row * E;
    float m = -1e30f;
#pragma unroll
    for (int e = 0; e < E; e++) m = fmaxf(m, lp[e]);
    float ve[E]; float s = 0.f;
#pragma unroll
    for (int e = 0; e < E; e++) { ve[e] = __expf(lp[e] - m); s += ve[e]; }
    float inv = 1.f / s;
    float* op = out + (size_t)row * E;
#pragma unroll
    for (int e = 0; e < E; e++) op[e] = ve[e]*inv;
}

// ---------------- slots (all experts in one pass) = dispatch^T @ hn ----------------
__global__ void slots_all_kernel(const float* __restrict__ disp, const float* __restrict__ hn,
                                 float* __restrict__ slots) {
    int d = blockIdx.x*256 + threadIdx.x;
    int b = blockIdx.y;
    __shared__ float sd[256][E];
    float acc[E];
#pragma unroll
    for (int e = 0; e < E; e++) acc[e] = 0.f;
    for (int t0 = 0; t0 < T; t0 += 256) {
        __syncthreads();
        const float4* dp = (const float4*)(disp + ((size_t)b*T + t0 + threadIdx.x)*E);
        float4 d0 = dp[0], d1 = dp[1];
        sd[threadIdx.x][0] = d0.x; sd[threadIdx.x][1] = d0.y;
        sd[threadIdx.x][2] = d0.z; sd[threadIdx.x][3] = d0.w;
        sd[threadIdx.x][4] = d1.x; sd[threadIdx.x][5] = d1.y;
        sd[threadIdx.x][6] = d1.z; sd[threadIdx.x][7] = d1.w;
        __syncthreads();
        const float* hp = hn + ((size_t)b*T + t0)*D + d;
#pragma unroll 4
        for (int tt = 0; tt < 256; tt++) {
            float hv = hp[(size_t)tt*D];
#pragma unroll
            for (int e = 0; e < E; e++) acc[e] += sd[tt][e] * hv;
        }
    }
#pragma unroll
    for (int e = 0; e < E; e++) slots[((size_t)b*E + e)*D + d] = acc[e];
}

// ---------------- expert up-proj: silu(slots@w1) * (slots@w3) ----------------
__global__ void gact_kernel(const float* __restrict__ slots, const float* __restrict__ w1,
                            const float* __restrict__ w3, float* __restrict__ gact) {
    int hcol = blockIdx.x*256 + threadIdx.x;
    int e = blockIdx.y;
    __shared__ float s0[D], s1[D];
    for (int i = threadIdx.x; i < D; i += 256) {
        s0[i] = slots[((size_t)0*E + e)*D + i];
        s1[i] = slots[((size_t)1*E + e)*D + i];
    }
    __syncthreads();
    float a10 = 0.f, a11 = 0.f, a30 = 0.f, a31 = 0.f;
    const float* w1p = w1 + (size_t)e*D*FH + hcol;
    const float* w3p = w3 + (size_t)e*D*FH + hcol;
#pragma unroll 4
    for (int dd = 0; dd < D; dd++) {
        float w1v = w1p[(size_t)dd*FH];
        float w3v = w3p[(size_t)dd*FH];
        a10 += s0[dd]*w1v; a11 += s1[dd]*w1v;
        a30 += s0[dd]*w3v; a31 += s1[dd]*w3v;
    }
    float g0 = a10 / (1.f + __expf(-a10)) * a30;
    float g1 = a11 / (1.f + __expf(-a11)) * a31;
    gact[((size_t)0*E + e)*FH + hcol] = g0;
    gact[((size_t)1*E + e)*FH + hcol] = g1;
}

// ---------------- expert down-proj, split-K partials ----------------
__global__ void w2_kernel(const float* __restrict__ gact, const float* __restrict__ w2,
                          float* __restrict__ ypart) {
    const int CH = FH / KS;
    int d = blockIdx.x*256 + threadIdx.x;
    int e = blockIdx.y;
    int kc = blockIdx.z;
    __shared__ float gg0[FH / KS], gg1[FH / KS];
    for (int i = threadIdx.x; i < CH; i += 256) {
        gg0[i] = gact[((size_t)0*E + e)*FH + kc*CH + i];
        gg1[i] = gact[((size_t)1*E + e)*FH + kc*CH + i];
    }
    __syncthreads();
    float a0 = 0.f, a1 = 0.f;
    const float* w2p = w2 + ((size_t)e*FH + (size_t)kc*CH)*D + d;
#pragma unroll 4
    for (int hh = 0; hh < CH; hh++) {
        float wv = w2p[(size_t)hh*D];
        a0 += gg0[hh]*wv; a1 += gg1[hh]*wv;
    }
    ypart[((size_t)kc*B*E + 0*E + e)*D + d] = a0;
    ypart[((size_t)kc*B*E + 1*E + e)*D + d] = a1;
}

__global__ void yreduce_kernel(const float* __restrict__ ypart, float* __restrict__ y) {
    int i = blockIdx.x*256 + threadIdx.x;
    float s = 0.f;
#pragma unroll
    for (int kc = 0; kc < KS; kc++) s += ypart[(size_t)kc*B*E*D + i];
    y[i] = s;
}

// ---------------- final: out = h + combine @ y ----------------
__global__ void final_kernel(const float* __restrict__ h, const float* __restrict__ comb,
                             const float* __restrict__ y, float* __restrict__ out) {
    int row = blockIdx.x;
    int b = row / T;
    float c[E];
    const float* cp = comb + (size_t)row*E;
#pragma unroll
    for (int e = 0; e < E; e++) c[e] = cp[e];
#pragma unroll
    for (int i = 0; i < 8; i++) {
        int d = threadIdx.x + i*256;
        float acc = h[(size_t)row*D + d];
#pragma unroll
        for (int e = 0; e < E; e++) acc += c[e] * y[((size_t)b*E + e)*D + d];
        out[(size_t)row*D + d] = acc;
    }
}

// ---------------- launch ----------------
extern "C" void kernel_launch(void* const* d_in, const int* in_sizes, int n_in,
                              void* d_out, int out_size) {
    const float* x   = (const float*)d_in[0];
    const float* fc  = (const float*)d_in[3];
    const float* wq  = (const float*)d_in[4];
    const float* wk  = (const float*)d_in[5];
    const float* wv  = (const float*)d_in[6];
    const float* wo  = (const float*)d_in[7];
    const float* sw  = (const float*)d_in[8];
    const float* w1  = (const float*)d_in[9];
    const float* w3  = (const float*)d_in[10];
    const float* w2  = (const float*)d_in[11];
    const float* anw = (const float*)d_in[12];
    const float* fnw = (const float*)d_in[13];
    const int* causal = (const int*)d_in[14];
    float* out = (float*)d_out;

    float *xn, *h, *hn, *logits, *disp, *comb, *slots, *gact, *ypart, *y;
    __nv_bfloat16 *ah, *al, *qh, *ql, *kh, *kl, *vh, *vl, *oh, *ol, *wth, *wtl;
    cudaGetSymbolAddress((void**)&xn,    g_xn);
    cudaGetSymbolAddress((void**)&h,     g_h);
    cudaGetSymbolAddress((void**)&hn,    g_hn);
    cudaGetSymbolAddress((void**)&logits,g_logits);
    cudaGetSymbolAddress((void**)&disp,  g_disp);
    cudaGetSymbolAddress((void**)&comb,  g_comb);
    cudaGetSymbolAddress((void**)&slots, g_slots);
    cudaGetSymbolAddress((void**)&gact,  g_gact);
    cudaGetSymbolAddress((void**)&ypart, g_ypart);
    cudaGetSymbolAddress((void**)&y,     g_y);
    cudaGetSymbolAddress((void**)&ah,    g_ah);
    cudaGetSymbolAddress((void**)&al,    g_al);
    cudaGetSymbolAddress((void**)&qh,    g_qh);
    cudaGetSymbolAddress((void**)&ql,    g_ql);
    cudaGetSymbolAddress((void**)&kh,    g_kh);
    cudaGetSymbolAddress((void**)&kl,    g_kl);
    cudaGetSymbolAddress((void**)&vh,    g_vh);
    cudaGetSymbolAddress((void**)&vl,    g_vl);
    cudaGetSymbolAddress((void**)&oh,    g_oh);
    cudaGetSymbolAddress((void**)&ol,    g_ol);
    cudaGetSymbolAddress((void**)&wth,   g_wth);
    cudaGetSymbolAddress((void**)&wtl,   g_wtl);

    cudaFuncSetAttribute(mma_gemm_kernel, cudaFuncAttributeMaxDynamicSharedMemorySize, MMA_SMEM);
    cudaFuncSetAttribute(fattn_kernel, cudaFuncAttributeMaxDynamicSharedMemorySize, FATTN_SMEM);

    const size_t NK = (size_t)D * D;

    // rmsnorm + fused bf16 split
    rmsnorm_kernel<<<MT, 256>>>(x, anw, xn, ah, al);

    dim3 wgrid(D/32, D/32);
    wsplit_kernel<<<wgrid, dim3(32,8)>>>(wq, wth + 0*NK, wtl + 0*NK);
    wsplit_kernel<<<wgrid, dim3(32,8)>>>(wk, wth + 1*NK, wtl + 1*NK);
    wsplit_kernel<<<wgrid, dim3(32,8)>>>(wv, wth + 2*NK, wtl + 2*NK);
    wsplit_kernel<<<wgrid, dim3(32,8)>>>(wo, wth + 3*NK, wtl + 3*NK);

    dim3 gg(D/GN, MT/GM);
    // QKV GEMMs with fused rope (q,k) / split (v) epilogues
    mma_gemm_kernel<<<gg, 256, MMA_SMEM>>>(ah, al, wth + 0*NK, wtl + 0*NK, nullptr, nullptr,
                                           1, fc, qh, ql, MT, D, D);
    mma_gemm_kernel<<<gg, 256, MMA_SMEM>>>(ah, al, wth + 1*NK, wtl + 1*NK, nullptr, nullptr,
                                           1, fc, kh, kl, MT, D, D);
    mma_gemm_kernel<<<gg, 256, MMA_SMEM>>>(ah, al, wth + 2*NK, wtl + 2*NK, nullptr, nullptr,
                                           2, nullptr, vh, vl, MT, D, D);

    fattn_kernel<<<dim3(T/AQ, H, B), 256, FATTN_SMEM>>>(qh, ql, kh, kl, vh, vl, oh, ol, causal);

    // Wo GEMM + residual
    mma_gemm_kernel<<<gg, 256, MMA_SMEM>>>(oh, ol, wth + 3*NK, wtl + 3*NK, xn, h,
                                           0, nullptr, nullptr, nullptr, MT, D, D);

    rmsnorm_kernel<<<MT, 256>>>(h, fnw, hn, nullptr, nullptr);

    logits_kernel<<<MT, 256>>>(hn, sw, logits);
    dispatch_softmax_kernel<<<B*E, 256>>>(logits, disp);
    combine_softmax_kernel<<<MT/256, 256>>>(logits, comb);

    slots_all_kernel<<<dim3(D/256, B), 256>>>(disp, hn, slots);
    gact_kernel<<<dim3(FH/256, E), 256>>>(slots, w1, w3, gact);
    w2_kernel<<<dim3(D/256, E, KS), 256>>>(gact, w2, ypart);
    yreduce_kernel<<<(B*E*D)/256, 256>>>(ypart, y);

    final_kernel<<<MT, 256>>>(h, comb, y, out);
}

// round 9
// speedup vs baseline: 1.0069x; 1.0069x over previous
#include <cuda_runtime.h>
#include <cuda_bf16.h>
#include <cstdint>
#include <cstddef>

#define B 2
#define T 2048
#define D 2048
#define H 16
#define HD 128
#define E 8
#define FH 8192
#define EPSV 1e-6f
#define MT (B*T)

// ---------------- scratch (device globals; no allocation) ----------------
__device__ float g_xn  [(size_t)B*T*D];
__device__ float g_h   [(size_t)B*T*D];
__device__ float g_hn  [(size_t)B*T*D];
__device__ float g_logits[(size_t)B*T*E];
__device__ float g_disp  [(size_t)B*T*E];
__device__ float g_comb  [(size_t)B*T*E];
__device__ float g_slots [(size_t)B*E*D];
__device__ float g_gact  [(size_t)B*E*FH];
#define KS 8
__device__ float g_ypart[(size_t)KS*B*E*D];
__device__ float g_y    [(size_t)B*E*D];
// bf16 split operands
__device__ __nv_bfloat16 g_ah[(size_t)MT*D];
__device__ __nv_bfloat16 g_al[(size_t)MT*D];
__device__ __nv_bfloat16 g_qh[(size_t)MT*D];
__device__ __nv_bfloat16 g_ql[(size_t)MT*D];
__device__ __nv_bfloat16 g_kh[(size_t)MT*D];
__device__ __nv_bfloat16 g_kl[(size_t)MT*D];
__device__ __nv_bfloat16 g_vh[(size_t)MT*D];
__device__ __nv_bfloat16 g_vl[(size_t)MT*D];
__device__ __nv_bfloat16 g_oh[(size_t)MT*D];
__device__ __nv_bfloat16 g_ol[(size_t)MT*D];
__device__ __nv_bfloat16 g_wth[(size_t)4*D*D];
__device__ __nv_bfloat16 g_wtl[(size_t)4*D*D];

// ---------------- helpers ----------------
__device__ __forceinline__ uint32_t smem_u32(const void* p) {
    uint32_t a;
    asm("{ .reg .u64 t; cvta.to.shared.u64 t, %1; cvt.u32.u64 %0, t; }" : "=r"(a) : "l"(p));
    return a;
}
__device__ __forceinline__ void cp_async16(uint32_t saddr, const void* gaddr) {
    asm volatile("cp.async.ca.shared.global [%0], [%1], 16;" :: "r"(saddr), "l"(gaddr));
}
__device__ __forceinline__ void cp_commit() {
    asm volatile("cp.async.commit_group;");
}
template<int N>
__device__ __forceinline__ void cp_wait() {
    asm volatile("cp.async.wait_group %0;" :: "n"(N));
}
__device__ __forceinline__ void ldmx4(uint32_t* r, uint32_t addr) {
    asm volatile("ldmatrix.sync.aligned.m8n8.x4.shared.b16 {%0,%1,%2,%3}, [%4];"
                 : "=r"(r[0]), "=r"(r[1]), "=r"(r[2]), "=r"(r[3]) : "r"(addr));
}
__device__ __forceinline__ void ldmx4t(uint32_t* r, uint32_t addr) {
    asm volatile("ldmatrix.sync.aligned.m8n8.x4.trans.shared.b16 {%0,%1,%2,%3}, [%4];"
                 : "=r"(r[0]), "=r"(r[1]), "=r"(r[2]), "=r"(r[3]) : "r"(addr));
}
__device__ __forceinline__ void mma16816(float* c, const uint32_t* a, uint32_t b0, uint32_t b1) {
    asm volatile(
        "mma.sync.aligned.m16n8k16.row.col.f32.bf16.bf16.f32 "
        "{%0,%1,%2,%3}, {%4,%5,%6,%7}, {%8,%9}, {%0,%1,%2,%3};"
        : "+f"(c[0]), "+f"(c[1]), "+f"(c[2]), "+f"(c[3])
        : "r"(a[0]), "r"(a[1]), "r"(a[2]), "r"(a[3]), "r"(b0), "r"(b1));
}
// hardware exp2 (MUFU pipe)
__device__ __forceinline__ float hex2(float x) {
    float r; asm("ex2.approx.f32 %0, %1;" : "=f"(r) : "f"(x)); return r;
}
// software exp2 (FMA pipe), rel err ~2.4e-6
__device__ __forceinline__ float fex2(float x) {
    x = fmaxf(x, -126.f);
    float t = x + 12582912.f;
    int ti = __float_as_int(t);
    float f = x - (t - 12582912.f);
    float p = 0.00133335581f;
    p = fmaf(p, f, 0.00961812911f);
    p = fmaf(p, f, 0.05550410866f);
    p = fmaf(p, f, 0.24022650696f);
    p = fmaf(p, f, 0.69314718056f);
    p = fmaf(p, f, 1.0f);
    return __int_as_float(__float_as_int(p) + (ti << 23));
}
__device__ __forceinline__ void packsplit(float p0, float p1, uint32_t& hi, uint32_t& lo) {
    __nv_bfloat16 h0 = __float2bfloat16_rn(p0), h1 = __float2bfloat16_rn(p1);
    __nv_bfloat162 hv(h0, h1);
    hi = *reinterpret_cast<uint32_t*>(&hv);
    __nv_bfloat162 lv(__float2bfloat16_rn(p0 - __bfloat162float(h0)),
                      __float2bfloat16_rn(p1 - __bfloat162float(h1)));
    lo = *reinterpret_cast<uint32_t*>(&lv);
}

// ---------------- rmsnorm (optional fused bf16 hi/lo split) ----------------
__global__ void rmsnorm_kernel(const float* __restrict__ x, const float* __restrict__ w,
                               float* __restrict__ out,
                               __nv_bfloat16* __restrict__ hi, __nv_bfloat16* __restrict__ lo) {
    int row = blockIdx.x;
    const float* xp = x + (size_t)row * D;
    float v[8];
    float ss = 0.f;
#pragma unroll
    for (int i = 0; i < 8; i++) { v[i] = xp[threadIdx.x + i*256]; ss += v[i]*v[i]; }
    __shared__ float red[256];
    red[threadIdx.x] = ss; __syncthreads();
    for (int s = 128; s > 0; s >>= 1) {
        if (threadIdx.x < s) red[threadIdx.x] += red[threadIdx.x + s];
        __syncthreads();
    }
    float rms = rsqrtf(red[0] / (float)D + EPSV);
    float* op = out + (size_t)row * D;
#pragma unroll
    for (int i = 0; i < 8; i++) {
        int d = threadIdx.x + i*256;
        float o = v[i]*rms*w[d];
        op[d] = o;
        if (hi) {
            __nv_bfloat16 hb = __float2bfloat16_rn(o);
            hi[(size_t)row*D + d] = hb;
            lo[(size_t)row*D + d] = __float2bfloat16_rn(o - __bfloat162float(hb));
        }
    }
}

// ---------------- transpose + split weights: W[K,N] -> WT[N,K] hi/lo bf16 ----------------
__global__ void wsplit_kernel(const float* __restrict__ W,
                              __nv_bfloat16* __restrict__ th, __nv_bfloat16* __restrict__ tl) {
    __shared__ float t[32][33];
    int n0 = blockIdx.x * 32, k0 = blockIdx.y * 32;
    int tx = threadIdx.x, ty = threadIdx.y;   // 32 x 8
#pragma unroll
    for (int i = 0; i < 4; i++)
        t[ty + 8*i][tx] = W[(size_t)(k0 + ty + 8*i) * D + n0 + tx];
    __syncthreads();
#pragma unroll
    for (int i = 0; i < 4; i++) {
        float v = t[tx][ty + 8*i];
        size_t o = (size_t)(n0 + ty + 8*i) * D + k0 + tx;
        __nv_bfloat16 hv = __float2bfloat16_rn(v);
        th[o] = hv;
        tl[o] = __float2bfloat16_rn(v - __bfloat162float(hv));
    }
}

// ---------------- mma.sync GEMM: C[M,N] = A[M,K] @ B^T (B given [N,K]) ----------------
// mode 0: fp32 C (+Res). mode 1: rope + bf16 hi/lo split. mode 2: bf16 hi/lo split.
#define GM 128
#define GN 128
#define GK 32
#define TSTR 40
#define TILE_B2 (128*TSTR*2)
#define STG_B2 (4*TILE_B2)
#define MMA_SMEM (2*STG_B2)

__global__ __launch_bounds__(256, 2)
void mma_gemm_kernel(const __nv_bfloat16* __restrict__ Ah, const __nv_bfloat16* __restrict__ Al,
                     const __nv_bfloat16* __restrict__ Bh, const __nv_bfloat16* __restrict__ Bl,
                     const float* __restrict__ Res, float* __restrict__ C,
                     int mode, const float* __restrict__ fc,
                     __nv_bfloat16* __restrict__ Chi, __nv_bfloat16* __restrict__ Clo,
                     int Mdim, int Ndim, int Kdim) {
    extern __shared__ char smem[];
    uint32_t sb = smem_u32(smem);
    int tid = threadIdx.x, lane = tid & 31, warp = tid >> 5;
    int wm = warp & 3, wn = warp >> 2;
    int m0 = blockIdx.y * GM, n0 = blockIdx.x * GN;

    int lrow[2], lcol[2];
    uint32_t sdst[2];
#pragma unroll
    for (int p = 0; p < 2; p++) {
        int idx = tid + p*256;
        lrow[p] = idx >> 2;
        lcol[p] = (idx & 3) * 8;
        sdst[p] = (uint32_t)(lrow[p]*TSTR + lcol[p]) * 2;
    }

    const int nkt = Kdim / GK;

    auto issue = [&](int kt, int stage) {
        uint32_t s0 = sb + stage * STG_B2;
        const __nv_bfloat16* srcs[4] = {
            Ah + (size_t)m0 * Kdim, Al + (size_t)m0 * Kdim,
            Bh + (size_t)n0 * Kdim, Bl + (size_t)n0 * Kdim };
#pragma unroll
        for (int tl = 0; tl < 4; tl++) {
#pragma unroll
            for (int p = 0; p < 2; p++) {
                const __nv_bfloat16* g = srcs[tl] + (size_t)lrow[p] * Kdim + kt*GK + lcol[p];
                cp_async16(s0 + tl*TILE_B2 + sdst[p], g);
            }
        }
        cp_commit();
    };

    float acc[2][8][4];
#pragma unroll
    for (int mi = 0; mi < 2; mi++)
#pragma unroll
        for (int nj = 0; nj < 8; nj++)
#pragma unroll
            for (int c = 0; c < 4; c++) acc[mi][nj][c] = 0.f;

    int lr = lane & 15, lc8 = (lane >> 4) << 3;

    issue(0, 0);

    for (int kt = 0; kt < nkt; kt++) {
        int stage = kt & 1;
        if (kt + 1 < nkt) { issue(kt + 1, stage ^ 1); cp_wait<1>(); }
        else              { cp_wait<0>(); }
        __syncthreads();

        uint32_t s0 = sb + stage * STG_B2;
        uint32_t sAh = s0, sAl = s0 + TILE_B2, sBh = s0 + 2*TILE_B2, sBl = s0 + 3*TILE_B2;

#pragma unroll
        for (int ks = 0; ks < 2; ks++) {
            int kc = ks*16 + lc8;
            uint32_t ah[2][4], al[2][4], bh[4][4], bl[4][4];
#pragma unroll
            for (int mi = 0; mi < 2; mi++)
                ldmx4(ah[mi], sAh + (uint32_t)((wm*32 + mi*16 + lr)*TSTR + kc) * 2);
#pragma unroll
            for (int njp = 0; njp < 4; njp++)
                ldmx4(bh[njp], sBh + (uint32_t)((wn*64 + njp*16 + lr)*TSTR + kc) * 2);
#pragma unroll
            for (int mi = 0; mi < 2; mi++)
#pragma unroll
                for (int njp = 0; njp < 4; njp++) {
                    mma16816(acc[mi][2*njp+0], ah[mi], bh[njp][0], bh[njp][2]);
                    mma16816(acc[mi][2*njp+1], ah[mi], bh[njp][1], bh[njp][3]);
                }
#pragma unroll
            for (int mi = 0; mi < 2; mi++)
                ldmx4(al[mi], sAl + (uint32_t)((wm*32 + mi*16 + lr)*TSTR + kc) * 2);
#pragma unroll
            for (int mi = 0; mi < 2; mi++)
#pragma unroll
                for (int njp = 0; njp < 4; njp++) {
                    mma16816(acc[mi][2*njp+0], al[mi], bh[njp][0], bh[njp][2]);
                    mma16816(acc[mi][2*njp+1], al[mi], bh[njp][1], bh[njp][3]);
                }
#pragma unroll
            for (int njp = 0; njp < 4; njp++)
                ldmx4(bl[njp], sBl + (uint32_t)((wn*64 + njp*16 + lr)*TSTR + kc) * 2);
#pragma unroll
            for (int mi = 0; mi < 2; mi++)
#pragma unroll
                for (int njp = 0; njp < 4; njp++) {
                    mma16816(acc[mi][2*njp+0], ah[mi], bl[njp][0], bl[njp][2]);
                    mma16816(acc[mi][2*njp+1], ah[mi], bl[njp][1], bl[njp][3]);
                }
        }
        __syncthreads();
    }

    int g = lane >> 2, tg = lane & 3;
    if (mode == 0) {
#pragma unroll
        for (int mi = 0; mi < 2; mi++) {
            size_t row0 = (size_t)(m0 + wm*32 + mi*16 + g);
#pragma unroll
            for (int nj = 0; nj < 8; nj++) {
                size_t col = (size_t)(n0 + wn*64 + nj*8 + tg*2);
                float2 v0 = make_float2(acc[mi][nj][0], acc[mi][nj][1]);
                float2 v1 = make_float2(acc[mi][nj][2], acc[mi][nj][3]);
                if (Res) {
                    float2 r0 = *(const float2*)(Res + row0*Ndim + col);
                    float2 r1 = *(const float2*)(Res + (row0+8)*Ndim + col);
                    v0.x += r0.x; v0.y += r0.y; v1.x += r1.x; v1.y += r1.y;
                }
                *(float2*)(C + row0*Ndim + col) = v0;
                *(float2*)(C + (row0+8)*Ndim + col) = v1;
            }
        }
    } else {
#pragma unroll
        for (int mi = 0; mi < 2; mi++) {
            size_t row0 = (size_t)(m0 + wm*32 + mi*16 + g);
            size_t row1 = row0 + 8;
#pragma unroll
            for (int nj = 0; nj < 8; nj++) {
                int col = n0 + wn*64 + nj*8 + tg*2;
                float2 v0 = make_float2(acc[mi][nj][0], acc[mi][nj][1]);
                float2 v1 = make_float2(acc[mi][nj][2], acc[mi][nj][3]);
                if (mode == 1) {
                    int cb = col & (HD - 1);
                    float2 c0 = *(const float2*)(fc + (size_t)(row0 & (T-1))*HD + cb);
                    float2 c1 = *(const float2*)(fc + (size_t)(row1 & (T-1))*HD + cb);
                    v0 = make_float2(v0.x*c0.x - v0.y*c0.y, v0.x*c0.y + v0.y*c0.x);
                    v1 = make_float2(v1.x*c1.x - v1.y*c1.y, v1.x*c1.y + v1.y*c1.x);
                }
                uint32_t h0, l0w, h1, l1w;
                packsplit(v0.x, v0.y, h0, l0w);
                packsplit(v1.x, v1.y, h1, l1w);
                *(uint32_t*)(Chi + row0*Ndim + col) = h0;
                *(uint32_t*)(Clo + row0*Ndim + col) = l0w;
                *(uint32_t*)(Chi + row1*Ndim + col) = h1;
                *(uint32_t*)(Clo + row1*Ndim + col) = l1w;
            }
        }
    }
}

// ---------------- flash attention (mma.sync bf16, 3-term split, hybrid exp) ----------------
#define AQ 128
#define AKV 64
#define ASTRB 272
#define ATILE_B (AKV*ASTRB)
#define ASTG_B (4*ATILE_B)
#define FATTN_SMEM (2*ASTG_B)
#define SCL2 0.12751743867f             // (1/sqrt(128)) * log2(e)

__global__ __launch_bounds__(256)
void fattn_kernel(const __nv_bfloat16* __restrict__ Qh, const __nv_bfloat16* __restrict__ Ql,
                  const __nv_bfloat16* __restrict__ Kh, const __nv_bfloat16* __restrict__ Kl,
                  const __nv_bfloat16* __restrict__ Vh, const __nv_bfloat16* __restrict__ Vl,
                  __nv_bfloat16* __restrict__ Oh, __nv_bfloat16* __restrict__ Ol,
                  const int* __restrict__ causal_flag) {
    extern __shared__ char smem[];
    uint32_t sb = smem_u32(smem);
    int tid = threadIdx.x, lane = tid & 31, warp = tid >> 5;
    int g = lane >> 2, tg = lane & 3;
    int q0 = blockIdx.x * AQ, h = blockIdx.y, b = blockIdx.z;
    bool causal = (*causal_flag) != 0;
    int wrow = q0 + warp * 16;

    uint32_t s0 = sb, s1 = sb + ASTG_B;

    const size_t bbase = ((size_t)b * T) << 11;
    const size_t hbase = (size_t)h * HD;

#pragma unroll
    for (int half = 0; half < 2; half++) {
        const __nv_bfloat16* src = half ? Ql : Qh;
#pragma unroll
        for (int j = 0; j < 8; j++) {
            int c = tid + j*256;
            int r = c >> 4, col = c & 15;
            cp_async16(s0 + half*(AQ*ASTRB) + r*ASTRB + col*16,
                       src + bbase + ((size_t)(q0 + r) << 11) + hbase + col*8);
        }
    }
    cp_commit();

    auto issue_kv = [&](int kvt, uint32_t stg) {
        int k0 = kvt * AKV;
        const __nv_bfloat16* ptrs[4] = {Kh, Kl, Vh, Vl};
#pragma unroll
        for (int tl = 0; tl < 4; tl++) {
#pragma unroll
            for (int j = 0; j < 4; j++) {
                int c = tid + j*256;
                int r = c >> 4, col = c & 15;
                cp_async16(stg + tl*ATILE_B + r*ASTRB + col*16,
                           ptrs[tl] + bbase + ((size_t)(k0 + r) << 11) + hbase + col*8);
            }
        }
        cp_commit();
    };

    int ntile = causal ? (q0 + AQ)/AKV : T/AKV;
    issue_kv(0, s1);

    cp_wait<1>();
    __syncthreads();

    int lr = lane & 15, c8 = (lane >> 4) << 3;
    uint32_t qfh[8][4], qfl[8][4];
#pragma unroll
    for (int ks = 0; ks < 8; ks++) {
        uint32_t a = s0 + (warp*16 + lr)*ASTRB + (ks*16 + c8)*2;
        ldmx4(qfh[ks], a);
        ldmx4(qfl[ks], a + AQ*ASTRB);
    }
    __syncthreads();

    float oa[16][4];
#pragma unroll
    for (int i = 0; i < 16; i++) { oa[i][0]=0.f; oa[i][1]=0.f; oa[i][2]=0.f; oa[i][3]=0.f; }
    float m0 = -1e30f, m1 = -1e30f, l0 = 0.f, l1 = 0.f;

    for (int kvt = 0; kvt < ntile; kvt++) {
        uint32_t cur = (kvt & 1) ? s0 : s1;
        uint32_t nxt = (kvt & 1) ? s1 : s0;
        if (kvt + 1 < ntile) { issue_kv(kvt + 1, nxt); cp_wait<1>(); }
        else                 { cp_wait<0>(); }
        __syncthreads();
        int k0 = kvt * AKV;

        if (!causal || k0 <= wrow + 15) {
            uint32_t KHs = cur, KLs = cur + ATILE_B, VHs = cur + 2*ATILE_B, VLs = cur + 3*ATILE_B;
            float sa[8][4];
#pragma unroll
            for (int nj = 0; nj < 8; nj++) { sa[nj][0]=0.f; sa[nj][1]=0.f; sa[nj][2]=0.f; sa[nj][3]=0.f; }
#pragma unroll
            for (int ks = 0; ks < 8; ks++) {
                uint32_t bh[4][4], bl[4][4];
#pragma unroll
                for (int n4 = 0; n4 < 4; n4++)
                    ldmx4(bh[n4], KHs + (n4*16 + lr)*ASTRB + (ks*16 + c8)*2);
#pragma unroll
                for (int n4 = 0; n4 < 4; n4++) {
                    mma16816(sa[2*n4+0], qfh[ks], bh[n4][0], bh[n4][2]);
                    mma16816(sa[2*n4+1], qfh[ks], bh[n4][1], bh[n4][3]);
                }
#pragma unroll
                for (int n4 = 0; n4 < 4; n4++)
                    ldmx4(bl[n4], KLs + (n4*16 + lr)*ASTRB + (ks*16 + c8)*2);
#pragma unroll
                for (int n4 = 0; n4 < 4; n4++) {
                    mma16816(sa[2*n4+0], qfh[ks], bl[n4][0], bl[n4][2]);
                    mma16816(sa[2*n4+1], qfh[ks], bl[n4][1], bl[n4][3]);
                    mma16816(sa[2*n4+0], qfl[ks], bh[n4][0], bh[n4][2]);
                    mma16816(sa[2*n4+1], qfl[ks], bh[n4][1], bh[n4][3]);
                }
            }
            if (causal && k0 + 63 > wrow) {
#pragma unroll
                for (int nj = 0; nj < 8; nj++) {
                    int col = k0 + nj*8 + 2*tg;
                    if (col     > wrow + g)     sa[nj][0] = -1e30f;
                    if (col + 1 > wrow + g)     sa[nj][1] = -1e30f;
                    if (col     > wrow + g + 8) sa[nj][2] = -1e30f;
                    if (col + 1 > wrow + g + 8) sa[nj][3] = -1e30f;
                }
            }
            float mt0 = -1e30f, mt1 = -1e30f;
#pragma unroll
            for (int nj = 0; nj < 8; nj++) {
                mt0 = fmaxf(mt0, fmaxf(sa[nj][0], sa[nj][1]));
                mt1 = fmaxf(mt1, fmaxf(sa[nj][2], sa[nj][3]));
            }
            mt0 = fmaxf(mt0, __shfl_xor_sync(0xffffffffu, mt0, 1));
            mt0 = fmaxf(mt0, __shfl_xor_sync(0xffffffffu, mt0, 2));
            mt1 = fmaxf(mt1, __shfl_xor_sync(0xffffffffu, mt1, 1));
            mt1 = fmaxf(mt1, __shfl_xor_sync(0xffffffffu, mt1, 2));
            float mn0 = fmaxf(m0, mt0), mn1 = fmaxf(m1, mt1);
            float al0 = hex2((m0 - mn0)*SCL2), al1 = hex2((m1 - mn1)*SCL2);
            float nb0 = mn0 * SCL2, nb1 = mn1 * SCL2;
            float ls0 = 0.f, ls1 = 0.f;
            // hybrid exp: nj<5 on MUFU (ex2.approx), nj>=5 on FMA pipe (poly)
#pragma unroll
            for (int nj = 0; nj < 8; nj++) {
                float p0, p1, p2, p3;
                if (nj < 5) {
                    p0 = hex2(fmaf(sa[nj][0], SCL2, -nb0));
                    p1 = hex2(fmaf(sa[nj][1], SCL2, -nb0));
                    p2 = hex2(fmaf(sa[nj][2], SCL2, -nb1));
                    p3 = hex2(fmaf(sa[nj][3], SCL2, -nb1));
                } else {
                    p0 = fex2(fmaf(sa[nj][0], SCL2, -nb0));
                    p1 = fex2(fmaf(sa[nj][1], SCL2, -nb0));
                    p2 = fex2(fmaf(sa[nj][2], SCL2, -nb1));
                    p3 = fex2(fmaf(sa[nj][3], SCL2, -nb1));
                }
                sa[nj][0]=p0; sa[nj][1]=p1; sa[nj][2]=p2; sa[nj][3]=p3;
                ls0 += p0 + p1; ls1 += p2 + p3;
            }
            ls0 += __shfl_xor_sync(0xffffffffu, ls0, 1);
            ls0 += __shfl_xor_sync(0xffffffffu, ls0, 2);
            ls1 += __shfl_xor_sync(0xffffffffu, ls1, 1);
            ls1 += __shfl_xor_sync(0xffffffffu, ls1, 2);
            l0 = l0*al0 + ls0; l1 = l1*al1 + ls1;
            m0 = mn0; m1 = mn1;
#pragma unroll
            for (int i2 = 0; i2 < 16; i2++) {
                oa[i2][0]*=al0; oa[i2][1]*=al0; oa[i2][2]*=al1; oa[i2][3]*=al1;
            }
            uint32_t pfh[4][4], pfl[4][4];
#pragma unroll
            for (int kt = 0; kt < 4; kt++) {
                packsplit(sa[2*kt][0],   sa[2*kt][1],   pfh[kt][0], pfl[kt][0]);
                packsplit(sa[2*kt][2],   sa[2*kt][3],   pfh[kt][1], pfl[kt][1]);
                packsplit(sa[2*kt+1][0], sa[2*kt+1][1], pfh[kt][2], pfl[kt][2]);
                packsplit(sa[2*kt+1][2], sa[2*kt+1][3], pfh[kt][3], pfl[kt][3]);
            }
            int mlane = lane >> 3;
            int kvr = (mlane & 1)*8 + (lane & 7);
            int hdc = (mlane >> 1)*8;
#pragma unroll
            for (int kt = 0; kt < 4; kt++) {
                uint32_t rbase = (uint32_t)((kt*16 + kvr)*ASTRB + hdc*2);
#pragma unroll
                for (int hp = 0; hp < 8; hp++) {
                    uint32_t vfh[4], vfl[4];
                    ldmx4t(vfh, VHs + rbase + hp*32);
                    ldmx4t(vfl, VLs + rbase + hp*32);
                    mma16816(oa[2*hp+0], pfh[kt], vfh[0], vfh[1]);
                    mma16816(oa[2*hp+1], pfh[kt], vfh[2], vfh[3]);
                    mma16816(oa[2*hp+0], pfh[kt], vfl[0], vfl[1]);
                    mma16816(oa[2*hp+1], pfh[kt], vfl[2], vfl[3]);
                    mma16816(oa[2*hp+0], pfl[kt], vfh[0], vfh[1]);
                    mma16816(oa[2*hp+1], pfl[kt], vfh[2], vfh[3]);
                }
            }
        }
        __syncthreads();
    }

    float inv0 = 1.f / l0, inv1 = 1.f / l1;
    size_t off0 = bbase + ((size_t)(wrow + g) << 11) + hbase;
    size_t off1 = bbase + ((size_t)(wrow + g + 8) << 11) + hbase;
#pragma unroll
    for (int hp = 0; hp < 16; hp++) {
        int hd = hp*8 + 2*tg;
        uint32_t h0, l0w, h1, l1w;
        packsplit(oa[hp][0]*inv0, oa[hp][1]*inv0, h0, l0w);
        packsplit(oa[hp][2]*inv1, oa[hp][3]*inv1, h1, l1w);
        *(uint32_t*)(Oh + off0 + hd) = h0;
        *(uint32_t*)(Ol + off0 + hd) = l0w;
        *(uint32_t*)(Oh + off1 + hd) = h1;
        *(uint32_t*)(Ol + off1 + hd) = l1w;
    }
}

// ---------------- router logits: hn @ slots_w (D x E) ----------------
__global__ void logits_kernel(const float* __restrict__ hn, const float* __restrict__ sw,
                              float* __restrict__ out) {
    int row = blockIdx.x;
    const float* hp = hn + (size_t)row * D;
    float acc[E];
#pragma unroll
    for (int e = 0; e < E; e++) acc[e] = 0.f;
#pragma unroll
    for (int i = 0; i < 8; i++) {
        int d = threadIdx.x + i*256;
        float hv = hp[d];
        const float* swp = sw + (size_t)d * E;
#pragma unroll
        for (int e = 0; e < E; e++) acc[e] += hv * swp[e];
    }
#pragma unroll
    for (int e = 0; e < E; e++)
        for (int o = 16; o > 0; o >>= 1) acc[e] += __shfl_xor_sync(0xffffffffu, acc[e], o);
    __shared__ float red[8][E];
    int warp = threadIdx.x >> 5, lane = threadIdx.x & 31;
    if (lane == 0)
#pragma unroll
        for (int e = 0; e < E; e++) red[warp][e] = acc[e];
    __syncthreads();
    if (threadIdx.x < E) {
        float s = 0.f;
#pragma unroll
        for (int w = 0; w < 8; w++) s += red[w][threadIdx.x];
        out[(size_t)row*E + threadIdx.x] = s;
    }
}

// ---------------- dispatch softmax (over T, per (b,e)) ----------------
__global__ void dispatch_softmax_kernel(const float* __restrict__ lg, float* __restrict__ out) {
    int b = blockIdx.x >> 3, e = blockIdx.x & 7;
    const float* lp = lg + (size_t)b*T*E + e;
    float v[8];
    float m = -1e30f;
#pragma unroll
    for (int i = 0; i < 8; i++) {
        v[i] = lp[(size_t)(threadIdx.x + i*256)*E];
        m = fmaxf(m, v[i]);
    }
    __shared__ float red[256];
    red[threadIdx.x] = m; __syncthreads();
    for (int s = 128; s > 0; s >>= 1) {
        if (threadIdx.x < s) red[threadIdx.x] = fmaxf(red[threadIdx.x], red[threadIdx.x + s]);
        __syncthreads();
    }
    m = red[0]; __syncthreads();
    float ssum = 0.f;
#pragma unroll
    for (int i = 0; i < 8; i++) { v[i] = __expf(v[i] - m); ssum += v[i]; }
    red[threadIdx.x] = ssum; __syncthreads();
    for (int s = 128; s > 0; s >>= 1) {
        if (threadIdx.x < s) red[threadIdx.x] += red[threadIdx.x + s];
        __syncthreads();
    }
    float inv = 1.f / red[0];
    float* op = out + (size_t)b*T*E + e;
#pragma unroll
    for (int i = 0; i < 8; i++) op[(size_t)(threadIdx.x + i*256)*E] = v[i]*inv;
}

// ---------------- combine softmax (over E, per (b,t)) ----------------
__global__ void combine_softmax_kernel(const float* __restrict__ lg, float* __restrict__ out) {
    int row = blockIdx.x*256 + threadIdx.x;
    const float* lp = lg + (size_t)row * E;
    float m = -1e30f;
#pragma unroll
    for (int e = 0; e < E; e++) m = fmaxf(m, lp[e]);
    float ve[E]; float s = 0.f;
#pragma unroll
    for (int e = 0; e < E; e++) { ve[e] = __expf(lp[e] - m); s += ve[e]; }
    float inv = 1.f / s;
    float* op = out + (size_t)row * E;
#pragma unroll
    for (int e = 0; e < E; e++) op[e] = ve[e]*inv;
}

// ---------------- slots (all experts in one pass) = dispatch^T @ hn ----------------
__global__ void slots_all_kernel(const float* __restrict__ disp, const float* __restrict__ hn,
                                 float* __restrict__ slots) {
    int d = blockIdx.x*256 + threadIdx.x;
    int b = blockIdx.y;
    __shared__ float sd[256][E];
    float acc[E];
#pragma unroll
    for (int e = 0; e < E; e++) acc[e] = 0.f;
    for (int t0 = 0; t0 < T; t0 += 256) {
        __syncthreads();
        const float4* dp = (const float4*)(disp + ((size_t)b*T + t0 + threadIdx.x)*E);
        float4 d0 = dp[0], d1 = dp[1];
        sd[threadIdx.x][0] = d0.x; sd[threadIdx.x][1] = d0.y;
        sd[threadIdx.x][2] = d0.z; sd[threadIdx.x][3] = d0.w;
        sd[threadIdx.x][4] = d1.x; sd[threadIdx.x][5] = d1.y;
        sd[threadIdx.x][6] = d1.z; sd[threadIdx.x][7] = d1.w;
        __syncthreads();
        const float* hp = hn + ((size_t)b*T + t0)*D + d;
#pragma unroll 4
        for (int tt = 0; tt < 256; tt++) {
            float hv = hp[(size_t)tt*D];
#pragma unroll
            for (int e = 0; e < E; e++) acc[e] += sd[tt][e] * hv;
        }
    }
#pragma unroll
    for (int e = 0; e < E; e++) slots[((size_t)b*E + e)*D + d] = acc[e];
}

// ---------------- expert up-proj: silu(slots@w1) * (slots@w3) ----------------
__global__ void gact_kernel(const float* __restrict__ slots, const float* __restrict__ w1,
                            const float* __restrict__ w3, float* __restrict__ gact) {
    int hcol = blockIdx.x*256 + threadIdx.x;
    int e = blockIdx.y;
    __shared__ float s0[D], s1[D];
    for (int i = threadIdx.x; i < D; i += 256) {
        s0[i] = slots[((size_t)0*E + e)*D + i];
        s1[i] = slots[((size_t)1*E + e)*D + i];
    }
    __syncthreads();
    float a10 = 0.f, a11 = 0.f, a30 = 0.f, a31 = 0.f;
    const float* w1p = w1 + (size_t)e*D*FH + hcol;
    const float* w3p = w3 + (size_t)e*D*FH + hcol;
#pragma unroll 4
    for (int dd = 0; dd < D; dd++) {
        float w1v = w1p[(size_t)dd*FH];
        float w3v = w3p[(size_t)dd*FH];
        a10 += s0[dd]*w1v; a11 += s1[dd]*w1v;
        a30 += s0[dd]*w3v; a31 += s1[dd]*w3v;
    }
    float g0 = a10 / (1.f + __expf(-a10)) * a30;
    float g1 = a11 / (1.f + __expf(-a11)) * a31;
    gact[((size_t)0*E + e)*FH + hcol] = g0;
    gact[((size_t)1*E + e)*FH + hcol] = g1;
}

// ---------------- expert down-proj, split-K partials ----------------
__global__ void w2_kernel(const float* __restrict__ gact, const float* __restrict__ w2,
                          float* __restrict__ ypart) {
    const int CH = FH / KS;
    int d = blockIdx.x*256 + threadIdx.x;
    int e = blockIdx.y;
    int kc = blockIdx.z;
    __shared__ float gg0[FH / KS], gg1[FH / KS];
    for (int i = threadIdx.x; i < CH; i += 256) {
        gg0[i] = gact[((size_t)0*E + e)*FH + kc*CH + i];
        gg1[i] = gact[((size_t)1*E + e)*FH + kc*CH + i];
    }
    __syncthreads();
    float a0 = 0.f, a1 = 0.f;
    const float* w2p = w2 + ((size_t)e*FH + (size_t)kc*CH)*D + d;
#pragma unroll 4
    for (int hh = 0; hh < CH; hh++) {
        float wv = w2p[(size_t)hh*D];
        a0 += gg0[hh]*wv; a1 += gg1[hh]*wv;
    }
    ypart[((size_t)kc*B*E + 0*E + e)*D + d] = a0;
    ypart[((size_t)kc*B*E + 1*E + e)*D + d] = a1;
}

__global__ void yreduce_kernel(const float* __restrict__ ypart, float* __restrict__ y) {
    int i = blockIdx.x*256 + threadIdx.x;
    float s = 0.f;
#pragma unroll
    for (int kc = 0; kc < KS; kc++) s += ypart[(size_t)kc*B*E*D + i];
    y[i] = s;
}

// ---------------- final: out = h + combine @ y ----------------
__global__ void final_kernel(const float* __restrict__ h, const float* __restrict__ comb,
                             const float* __restrict__ y, float* __restrict__ out) {
    int row = blockIdx.x;
    int b = row / T;
    float c[E];
    const float* cp = comb + (size_t)row*E;
#pragma unroll
    for (int e = 0; e < E; e++) c[e] = cp[e];
#pragma unroll
    for (int i = 0; i < 8; i++) {
        int d = threadIdx.x + i*256;
        float acc = h[(size_t)row*D + d];
#pragma unroll
        for (int e = 0; e < E; e++) acc += c[e] * y[((size_t)b*E + e)*D + d];
        out[(size_t)row*D + d] = acc;
    }
}

// ---------------- launch ----------------
extern "C" void kernel_launch(void* const* d_in, const int* in_sizes, int n_in,
                              void* d_out, int out_size) {
    const float* x   = (const float*)d_in[0];
    const float* fc  = (const float*)d_in[3];
    const float* wq  = (const float*)d_in[4];
    const float* wk  = (const float*)d_in[5];
    const float* wv  = (const float*)d_in[6];
    const float* wo  = (const float*)d_in[7];
    const float* sw  = (const float*)d_in[8];
    const float* w1  = (const float*)d_in[9];
    const float* w3  = (const float*)d_in[10];
    const float* w2  = (const float*)d_in[11];
    const float* anw = (const float*)d_in[12];
    const float* fnw = (const float*)d_in[13];
    const int* causal = (const int*)d_in[14];
    float* out = (float*)d_out;

    float *xn, *h, *hn, *logits, *disp, *comb, *slots, *gact, *ypart, *y;
    __nv_bfloat16 *ah, *al, *qh, *ql, *kh, *kl, *vh, *vl, *oh, *ol, *wth, *wtl;
    cudaGetSymbolAddress((void**)&xn,    g_xn);
    cudaGetSymbolAddress((void**)&h,     g_h);
    cudaGetSymbolAddress((void**)&hn,    g_hn);
    cudaGetSymbolAddress((void**)&logits,g_logits);
    cudaGetSymbolAddress((void**)&disp,  g_disp);
    cudaGetSymbolAddress((void**)&comb,  g_comb);
    cudaGetSymbolAddress((void**)&slots, g_slots);
    cudaGetSymbolAddress((void**)&gact,  g_gact);
    cudaGetSymbolAddress((void**)&ypart, g_ypart);
    cudaGetSymbolAddress((void**)&y,     g_y);
    cudaGetSymbolAddress((void**)&ah,    g_ah);
    cudaGetSymbolAddress((void**)&al,    g_al);
    cudaGetSymbolAddress((void**)&qh,    g_qh);
    cudaGetSymbolAddress((void**)&ql,    g_ql);
    cudaGetSymbolAddress((void**)&kh,    g_kh);
    cudaGetSymbolAddress((void**)&kl,    g_kl);
    cudaGetSymbolAddress((void**)&vh,    g_vh);
    cudaGetSymbolAddress((void**)&vl,    g_vl);
    cudaGetSymbolAddress((void**)&oh,    g_oh);
    cudaGetSymbolAddress((void**)&ol,    g_ol);
    cudaGetSymbolAddress((void**)&wth,   g_wth);
    cudaGetSymbolAddress((void**)&wtl,   g_wtl);

    cudaFuncSetAttribute(mma_gemm_kernel, cudaFuncAttributeMaxDynamicSharedMemorySize, MMA_SMEM);
    cudaFuncSetAttribute(fattn_kernel, cudaFuncAttributeMaxDynamicSharedMemorySize, FATTN_SMEM);

    const size_t NK = (size_t)D * D;

    rmsnorm_kernel<<<MT, 256>>>(x, anw, xn, ah, al);

    dim3 wgrid(D/32, D/32);
    wsplit_kernel<<<wgrid, dim3(32,8)>>>(wq, wth + 0*NK, wtl + 0*NK);
    wsplit_kernel<<<wgrid, dim3(32,8)>>>(wk, wth + 1*NK, wtl + 1*NK);
    wsplit_kernel<<<wgrid, dim3(32,8)>>>(wv, wth + 2*NK, wtl + 2*NK);
    wsplit_kernel<<<wgrid, dim3(32,8)>>>(wo, wth + 3*NK, wtl + 3*NK);

    dim3 gg(D/GN, MT/GM);
    mma_gemm_kernel<<<gg, 256, MMA_SMEM>>>(ah, al, wth + 0*NK, wtl + 0*NK, nullptr, nullptr,
                                           1, fc, qh, ql, MT, D, D);
    mma_gemm_kernel<<<gg, 256, MMA_SMEM>>>(ah, al, wth + 1*NK, wtl + 1*NK, nullptr, nullptr,
                                           1, fc, kh, kl, MT, D, D);
    mma_gemm_kernel<<<gg, 256, MMA_SMEM>>>(ah, al, wth + 2*NK, wtl + 2*NK, nullptr, nullptr,
                                           2, nullptr, vh, vl, MT, D, D);

    fattn_kernel<<<dim3(T/AQ, H, B), 256, FATTN_SMEM>>>(qh, ql, kh, kl, vh, vl, oh, ol, causal);

    mma_gemm_kernel<<<gg, 256, MMA_SMEM>>>(oh, ol, wth + 3*NK, wtl + 3*NK, xn, h,
                                           0, nullptr, nullptr, nullptr, MT, D, D);

    rmsnorm_kernel<<<MT, 256>>>(h, fnw, hn, nullptr, nullptr);

    logits_kernel<<<MT, 256>>>(hn, sw, logits);
    dispatch_softmax_kernel<<<B*E, 256>>>(logits, disp);
    combine_softmax_kernel<<<MT/256, 256>>>(logits, comb);

    slots_all_kernel<<<dim3(D/256, B), 256>>>(disp, hn, slots);
    gact_kernel<<<dim3(FH/256, E), 256>>>(slots, w1, w3, gact);
    w2_kernel<<<dim3(D/256, E, KS), 256>>>(gact, w2, ypart);
    yreduce_kernel<<<(B*E*D)/256, 256>>>(ypart, y);

    final_kernel<<<MT, 256>>>(h, comb, y, out);
}

// round 10
// speedup vs baseline: 1.0309x; 1.0239x over previous
#include <cuda_runtime.h>
#include <cuda_bf16.h>
#include <cstdint>
#include <cstddef>

#define B 2
#define T 2048
#define D 2048
#define H 16
#define HD 128
#define E 8
#define FH 8192
#define EPSV 1e-6f
#define MT (B*T)

// ---------------- scratch (device globals; no allocation) ----------------
__device__ float g_xn  [(size_t)B*T*D];
__device__ float g_h   [(size_t)B*T*D];
__device__ float g_hn  [(size_t)B*T*D];
__device__ float g_logits[(size_t)B*T*E];
__device__ float g_disp  [(size_t)B*T*E];
__device__ float g_comb  [(size_t)B*T*E];
__device__ float g_slots [(size_t)B*E*D];
__device__ float g_gact  [(size_t)B*E*FH];
#define KS 8
__device__ float g_ypart[(size_t)KS*B*E*D];
__device__ float g_y    [(size_t)B*E*D];
// bf16 split operands
__device__ __nv_bfloat16 g_ah[(size_t)MT*D];
__device__ __nv_bfloat16 g_al[(size_t)MT*D];
__device__ __nv_bfloat16 g_qh[(size_t)MT*D];
__device__ __nv_bfloat16 g_ql[(size_t)MT*D];
__device__ __nv_bfloat16 g_kh[(size_t)MT*D];
__device__ __nv_bfloat16 g_kl[(size_t)MT*D];
__device__ __nv_bfloat16 g_vh[(size_t)MT*D];
__device__ __nv_bfloat16 g_vl[(size_t)MT*D];
__device__ __nv_bfloat16 g_oh[(size_t)MT*D];
__device__ __nv_bfloat16 g_ol[(size_t)MT*D];
__device__ __nv_bfloat16 g_wth[(size_t)4*D*D];
__device__ __nv_bfloat16 g_wtl[(size_t)4*D*D];

// ---------------- helpers ----------------
__device__ __forceinline__ uint32_t smem_u32(const void* p) {
    uint32_t a;
    asm("{ .reg .u64 t; cvta.to.shared.u64 t, %1; cvt.u32.u64 %0, t; }" : "=r"(a) : "l"(p));
    return a;
}
__device__ __forceinline__ void cp_async16(uint32_t saddr, const void* gaddr) {
    asm volatile("cp.async.ca.shared.global [%0], [%1], 16;" :: "r"(saddr), "l"(gaddr));
}
__device__ __forceinline__ void cp_commit() {
    asm volatile("cp.async.commit_group;");
}
template<int N>
__device__ __forceinline__ void cp_wait() {
    asm volatile("cp.async.wait_group %0;" :: "n"(N));
}
__device__ __forceinline__ void ldmx4(uint32_t* r, uint32_t addr) {
    asm volatile("ldmatrix.sync.aligned.m8n8.x4.shared.b16 {%0,%1,%2,%3}, [%4];"
                 : "=r"(r[0]), "=r"(r[1]), "=r"(r[2]), "=r"(r[3]) : "r"(addr));
}
__device__ __forceinline__ void ldmx4t(uint32_t* r, uint32_t addr) {
    asm volatile("ldmatrix.sync.aligned.m8n8.x4.trans.shared.b16 {%0,%1,%2,%3}, [%4];"
                 : "=r"(r[0]), "=r"(r[1]), "=r"(r[2]), "=r"(r[3]) : "r"(addr));
}
__device__ __forceinline__ void mma16816(float* c, const uint32_t* a, uint32_t b0, uint32_t b1) {
    asm volatile(
        "mma.sync.aligned.m16n8k16.row.col.f32.bf16.bf16.f32 "
        "{%0,%1,%2,%3}, {%4,%5,%6,%7}, {%8,%9}, {%0,%1,%2,%3};"
        : "+f"(c[0]), "+f"(c[1]), "+f"(c[2]), "+f"(c[3])
        : "r"(a[0]), "r"(a[1]), "r"(a[2]), "r"(a[3]), "r"(b0), "r"(b1));
}
// hardware exp2 (MUFU pipe)
__device__ __forceinline__ float hex2(float x) {
    float r; asm("ex2.approx.f32 %0, %1;" : "=f"(r) : "f"(x)); return r;
}
__device__ __forceinline__ void packsplit(float p0, float p1, uint32_t& hi, uint32_t& lo) {
    __nv_bfloat16 h0 = __float2bfloat16_rn(p0), h1 = __float2bfloat16_rn(p1);
    __nv_bfloat162 hv(h0, h1);
    hi = *reinterpret_cast<uint32_t*>(&hv);
    __nv_bfloat162 lv(__float2bfloat16_rn(p0 - __bfloat162float(h0)),
                      __float2bfloat16_rn(p1 - __bfloat162float(h1)));
    lo = *reinterpret_cast<uint32_t*>(&lv);
}

// ---------------- rmsnorm (optional fused bf16 hi/lo split) ----------------
__global__ void rmsnorm_kernel(const float* __restrict__ x, const float* __restrict__ w,
                               float* __restrict__ out,
                               __nv_bfloat16* __restrict__ hi, __nv_bfloat16* __restrict__ lo) {
    int row = blockIdx.x;
    const float* xp = x + (size_t)row * D;
    float v[8];
    float ss = 0.f;
#pragma unroll
    for (int i = 0; i < 8; i++) { v[i] = xp[threadIdx.x + i*256]; ss += v[i]*v[i]; }
    __shared__ float red[256];
    red[threadIdx.x] = ss; __syncthreads();
    for (int s = 128; s > 0; s >>= 1) {
        if (threadIdx.x < s) red[threadIdx.x] += red[threadIdx.x + s];
        __syncthreads();
    }
    float rms = rsqrtf(red[0] / (float)D + EPSV);
    float* op = out + (size_t)row * D;
#pragma unroll
    for (int i = 0; i < 8; i++) {
        int d = threadIdx.x + i*256;
        float o = v[i]*rms*w[d];
        op[d] = o;
        if (hi) {
            __nv_bfloat16 hb = __float2bfloat16_rn(o);
            hi[(size_t)row*D + d] = hb;
            lo[(size_t)row*D + d] = __float2bfloat16_rn(o - __bfloat162float(hb));
        }
    }
}

// ---------------- transpose + split weights: W[K,N] -> WT[N,K] hi/lo bf16 ----------------
__global__ void wsplit_kernel(const float* __restrict__ W,
                              __nv_bfloat16* __restrict__ th, __nv_bfloat16* __restrict__ tl) {
    __shared__ float t[32][33];
    int n0 = blockIdx.x * 32, k0 = blockIdx.y * 32;
    int tx = threadIdx.x, ty = threadIdx.y;   // 32 x 8
#pragma unroll
    for (int i = 0; i < 4; i++)
        t[ty + 8*i][tx] = W[(size_t)(k0 + ty + 8*i) * D + n0 + tx];
    __syncthreads();
#pragma unroll
    for (int i = 0; i < 4; i++) {
        float v = t[tx][ty + 8*i];
        size_t o = (size_t)(n0 + ty + 8*i) * D + k0 + tx;
        __nv_bfloat16 hv = __float2bfloat16_rn(v);
        th[o] = hv;
        tl[o] = __float2bfloat16_rn(v - __bfloat162float(hv));
    }
}

// ---------------- mma.sync GEMM: C[M,N] = A[M,K] @ B^T (B given [N,K]) ----------------
// mode 0: fp32 C (+Res). mode 1: rope + bf16 hi/lo split. mode 2: bf16 hi/lo split.
#define GM 128
#define GN 128
#define GK 32
#define TSTR 40
#define TILE_B2 (128*TSTR*2)
#define STG_B2 (4*TILE_B2)
#define MMA_SMEM (2*STG_B2)

__global__ __launch_bounds__(256, 2)
void mma_gemm_kernel(const __nv_bfloat16* __restrict__ Ah, const __nv_bfloat16* __restrict__ Al,
                     const __nv_bfloat16* __restrict__ Bh, const __nv_bfloat16* __restrict__ Bl,
                     const float* __restrict__ Res, float* __restrict__ C,
                     int mode, const float* __restrict__ fc,
                     __nv_bfloat16* __restrict__ Chi, __nv_bfloat16* __restrict__ Clo,
                     int Mdim, int Ndim, int Kdim) {
    extern __shared__ char smem[];
    uint32_t sb = smem_u32(smem);
    int tid = threadIdx.x, lane = tid & 31, warp = tid >> 5;
    int wm = warp & 3, wn = warp >> 2;
    int m0 = blockIdx.y * GM, n0 = blockIdx.x * GN;

    int lrow[2], lcol[2];
    uint32_t sdst[2];
#pragma unroll
    for (int p = 0; p < 2; p++) {
        int idx = tid + p*256;
        lrow[p] = idx >> 2;
        lcol[p] = (idx & 3) * 8;
        sdst[p] = (uint32_t)(lrow[p]*TSTR + lcol[p]) * 2;
    }

    const int nkt = Kdim / GK;

    auto issue = [&](int kt, int stage) {
        uint32_t s0 = sb + stage * STG_B2;
        const __nv_bfloat16* srcs[4] = {
            Ah + (size_t)m0 * Kdim, Al + (size_t)m0 * Kdim,
            Bh + (size_t)n0 * Kdim, Bl + (size_t)n0 * Kdim };
#pragma unroll
        for (int tl = 0; tl < 4; tl++) {
#pragma unroll
            for (int p = 0; p < 2; p++) {
                const __nv_bfloat16* g = srcs[tl] + (size_t)lrow[p] * Kdim + kt*GK + lcol[p];
                cp_async16(s0 + tl*TILE_B2 + sdst[p], g);
            }
        }
        cp_commit();
    };

    float acc[2][8][4];
#pragma unroll
    for (int mi = 0; mi < 2; mi++)
#pragma unroll
        for (int nj = 0; nj < 8; nj++)
#pragma unroll
            for (int c = 0; c < 4; c++) acc[mi][nj][c] = 0.f;

    int lr = lane & 15, lc8 = (lane >> 4) << 3;

    issue(0, 0);

    for (int kt = 0; kt < nkt; kt++) {
        int stage = kt & 1;
        if (kt + 1 < nkt) { issue(kt + 1, stage ^ 1); cp_wait<1>(); }
        else              { cp_wait<0>(); }
        __syncthreads();

        uint32_t s0 = sb + stage * STG_B2;
        uint32_t sAh = s0, sAl = s0 + TILE_B2, sBh = s0 + 2*TILE_B2, sBl = s0 + 3*TILE_B2;

#pragma unroll
        for (int ks = 0; ks < 2; ks++) {
            int kc = ks*16 + lc8;
            uint32_t ah[2][4], al[2][4], bh[4][4], bl[4][4];
#pragma unroll
            for (int mi = 0; mi < 2; mi++)
                ldmx4(ah[mi], sAh + (uint32_t)((wm*32 + mi*16 + lr)*TSTR + kc) * 2);
#pragma unroll
            for (int njp = 0; njp < 4; njp++)
                ldmx4(bh[njp], sBh + (uint32_t)((wn*64 + njp*16 + lr)*TSTR + kc) * 2);
#pragma unroll
            for (int mi = 0; mi < 2; mi++)
#pragma unroll
                for (int njp = 0; njp < 4; njp++) {
                    mma16816(acc[mi][2*njp+0], ah[mi], bh[njp][0], bh[njp][2]);
                    mma16816(acc[mi][2*njp+1], ah[mi], bh[njp][1], bh[njp][3]);
                }
#pragma unroll
            for (int mi = 0; mi < 2; mi++)
                ldmx4(al[mi], sAl + (uint32_t)((wm*32 + mi*16 + lr)*TSTR + kc) * 2);
#pragma unroll
            for (int mi = 0; mi < 2; mi++)
#pragma unroll
                for (int njp = 0; njp < 4; njp++) {
                    mma16816(acc[mi][2*njp+0], al[mi], bh[njp][0], bh[njp][2]);
                    mma16816(acc[mi][2*njp+1], al[mi], bh[njp][1], bh[njp][3]);
                }
#pragma unroll
            for (int njp = 0; njp < 4; njp++)
                ldmx4(bl[njp], sBl + (uint32_t)((wn*64 + njp*16 + lr)*TSTR + kc) * 2);
#pragma unroll
            for (int mi = 0; mi < 2; mi++)
#pragma unroll
                for (int njp = 0; njp < 4; njp++) {
                    mma16816(acc[mi][2*njp+0], ah[mi], bl[njp][0], bl[njp][2]);
                    mma16816(acc[mi][2*njp+1], ah[mi], bl[njp][1], bl[njp][3]);
                }
        }
        __syncthreads();
    }

    int g = lane >> 2, tg = lane & 3;
    if (mode == 0) {
#pragma unroll
        for (int mi = 0; mi < 2; mi++) {
            size_t row0 = (size_t)(m0 + wm*32 + mi*16 + g);
#pragma unroll
            for (int nj = 0; nj < 8; nj++) {
                size_t col = (size_t)(n0 + wn*64 + nj*8 + tg*2);
                float2 v0 = make_float2(acc[mi][nj][0], acc[mi][nj][1]);
                float2 v1 = make_float2(acc[mi][nj][2], acc[mi][nj][3]);
                if (Res) {
                    float2 r0 = *(const float2*)(Res + row0*Ndim + col);
                    float2 r1 = *(const float2*)(Res + (row0+8)*Ndim + col);
                    v0.x += r0.x; v0.y += r0.y; v1.x += r1.x; v1.y += r1.y;
                }
                *(float2*)(C + row0*Ndim + col) = v0;
                *(float2*)(C + (row0+8)*Ndim + col) = v1;
            }
        }
    } else {
#pragma unroll
        for (int mi = 0; mi < 2; mi++) {
            size_t row0 = (size_t)(m0 + wm*32 + mi*16 + g);
            size_t row1 = row0 + 8;
#pragma unroll
            for (int nj = 0; nj < 8; nj++) {
                int col = n0 + wn*64 + nj*8 + tg*2;
                float2 v0 = make_float2(acc[mi][nj][0], acc[mi][nj][1]);
                float2 v1 = make_float2(acc[mi][nj][2], acc[mi][nj][3]);
                if (mode == 1) {
                    int cb = col & (HD - 1);
                    float2 c0 = *(const float2*)(fc + (size_t)(row0 & (T-1))*HD + cb);
                    float2 c1 = *(const float2*)(fc + (size_t)(row1 & (T-1))*HD + cb);
                    v0 = make_float2(v0.x*c0.x - v0.y*c0.y, v0.x*c0.y + v0.y*c0.x);
                    v1 = make_float2(v1.x*c1.x - v1.y*c1.y, v1.x*c1.y + v1.y*c1.x);
                }
                uint32_t h0, l0w, h1, l1w;
                packsplit(v0.x, v0.y, h0, l0w);
                packsplit(v1.x, v1.y, h1, l1w);
                *(uint32_t*)(Chi + row0*Ndim + col) = h0;
                *(uint32_t*)(Clo + row0*Ndim + col) = l0w;
                *(uint32_t*)(Chi + row1*Ndim + col) = h1;
                *(uint32_t*)(Clo + row1*Ndim + col) = l1w;
            }
        }
    }
}

// ---------------- flash attention (mma.sync bf16, 3-term split, MUFU exp) ----------------
#define AQ 128
#define AKV 64
#define ASTRB 272
#define ATILE_B (AKV*ASTRB)
#define ASTG_B (4*ATILE_B)
#define FATTN_SMEM (2*ASTG_B)
#define SCL2 0.12751743867f             // (1/sqrt(128)) * log2(e)

__global__ __launch_bounds__(256)
void fattn_kernel(const __nv_bfloat16* __restrict__ Qh, const __nv_bfloat16* __restrict__ Ql,
                  const __nv_bfloat16* __restrict__ Kh, const __nv_bfloat16* __restrict__ Kl,
                  const __nv_bfloat16* __restrict__ Vh, const __nv_bfloat16* __restrict__ Vl,
                  __nv_bfloat16* __restrict__ Oh, __nv_bfloat16* __restrict__ Ol,
                  const int* __restrict__ causal_flag) {
    extern __shared__ char smem[];
    uint32_t sb = smem_u32(smem);
    int tid = threadIdx.x, lane = tid & 31, warp = tid >> 5;
    int g = lane >> 2, tg = lane & 3;
    // heavy causal tiles first for better tail packing
    int q0 = (gridDim.x - 1 - blockIdx.x) * AQ;
    int h = blockIdx.y, b = blockIdx.z;
    bool causal = (*causal_flag) != 0;
    int wrow = q0 + warp * 16;

    uint32_t s0 = sb, s1 = sb + ASTG_B;

    const size_t bbase = ((size_t)b * T) << 11;
    const size_t hbase = (size_t)h * HD;

#pragma unroll
    for (int half = 0; half < 2; half++) {
        const __nv_bfloat16* src = half ? Ql : Qh;
#pragma unroll
        for (int j = 0; j < 8; j++) {
            int c = tid + j*256;
            int r = c >> 4, col = c & 15;
            cp_async16(s0 + half*(AQ*ASTRB) + r*ASTRB + col*16,
                       src + bbase + ((size_t)(q0 + r) << 11) + hbase + col*8);
        }
    }
    cp_commit();

    auto issue_kv = [&](int kvt, uint32_t stg) {
        int k0 = kvt * AKV;
        const __nv_bfloat16* ptrs[4] = {Kh, Kl, Vh, Vl};
#pragma unroll
        for (int tl = 0; tl < 4; tl++) {
#pragma unroll
            for (int j = 0; j < 4; j++) {
                int c = tid + j*256;
                int r = c >> 4, col = c & 15;
                cp_async16(stg + tl*ATILE_B + r*ASTRB + col*16,
                           ptrs[tl] + bbase + ((size_t)(k0 + r) << 11) + hbase + col*8);
            }
        }
        cp_commit();
    };

    int ntile = causal ? (q0 + AQ)/AKV : T/AKV;
    issue_kv(0, s1);

    cp_wait<1>();
    __syncthreads();

    int lr = lane & 15, c8 = (lane >> 4) << 3;
    uint32_t qfh[8][4], qfl[8][4];
#pragma unroll
    for (int ks = 0; ks < 8; ks++) {
        uint32_t a = s0 + (warp*16 + lr)*ASTRB + (ks*16 + c8)*2;
        ldmx4(qfh[ks], a);
        ldmx4(qfl[ks], a + AQ*ASTRB);
    }
    __syncthreads();

    float oa[16][4];
#pragma unroll
    for (int i = 0; i < 16; i++) { oa[i][0]=0.f; oa[i][1]=0.f; oa[i][2]=0.f; oa[i][3]=0.f; }
    float m0 = -1e30f, m1 = -1e30f, l0 = 0.f, l1 = 0.f;

    for (int kvt = 0; kvt < ntile; kvt++) {
        uint32_t cur = (kvt & 1) ? s0 : s1;
        uint32_t nxt = (kvt & 1) ? s1 : s0;
        if (kvt + 1 < ntile) { issue_kv(kvt + 1, nxt); cp_wait<1>(); }
        else                 { cp_wait<0>(); }
        __syncthreads();
        int k0 = kvt * AKV;

        if (!causal || k0 <= wrow + 15) {
            uint32_t KHs = cur, KLs = cur + ATILE_B, VHs = cur + 2*ATILE_B, VLs = cur + 3*ATILE_B;
            float sa[8][4];
#pragma unroll
            for (int nj = 0; nj < 8; nj++) { sa[nj][0]=0.f; sa[nj][1]=0.f; sa[nj][2]=0.f; sa[nj][3]=0.f; }
#pragma unroll
            for (int ks = 0; ks < 8; ks++) {
                uint32_t bh[4][4], bl[4][4];
#pragma unroll
                for (int n4 = 0; n4 < 4; n4++)
                    ldmx4(bh[n4], KHs + (n4*16 + lr)*ASTRB + (ks*16 + c8)*2);
#pragma unroll
                for (int n4 = 0; n4 < 4; n4++) {
                    mma16816(sa[2*n4+0], qfh[ks], bh[n4][0], bh[n4][2]);
                    mma16816(sa[2*n4+1], qfh[ks], bh[n4][1], bh[n4][3]);
                }
#pragma unroll
                for (int n4 = 0; n4 < 4; n4++)
                    ldmx4(bl[n4], KLs + (n4*16 + lr)*ASTRB + (ks*16 + c8)*2);
#pragma unroll
                for (int n4 = 0; n4 < 4; n4++) {
                    mma16816(sa[2*n4+0], qfh[ks], bl[n4][0], bl[n4][2]);
                    mma16816(sa[2*n4+1], qfh[ks], bl[n4][1], bl[n4][3]);
                    mma16816(sa[2*n4+0], qfl[ks], bh[n4][0], bh[n4][2]);
                    mma16816(sa[2*n4+1], qfl[ks], bh[n4][1], bh[n4][3]);
                }
            }
            if (causal && k0 + 63 > wrow) {
#pragma unroll
                for (int nj = 0; nj < 8; nj++) {
                    int col = k0 + nj*8 + 2*tg;
                    if (col     > wrow + g)     sa[nj][0] = -1e30f;
                    if (col + 1 > wrow + g)     sa[nj][1] = -1e30f;
                    if (col     > wrow + g + 8) sa[nj][2] = -1e30f;
                    if (col + 1 > wrow + g + 8) sa[nj][3] = -1e30f;
                }
            }
            float mt0 = -1e30f, mt1 = -1e30f;
#pragma unroll
            for (int nj = 0; nj < 8; nj++) {
                mt0 = fmaxf(mt0, fmaxf(sa[nj][0], sa[nj][1]));
                mt1 = fmaxf(mt1, fmaxf(sa[nj][2], sa[nj][3]));
            }
            mt0 = fmaxf(mt0, __shfl_xor_sync(0xffffffffu, mt0, 1));
            mt0 = fmaxf(mt0, __shfl_xor_sync(0xffffffffu, mt0, 2));
            mt1 = fmaxf(mt1, __shfl_xor_sync(0xffffffffu, mt1, 1));
            mt1 = fmaxf(mt1, __shfl_xor_sync(0xffffffffu, mt1, 2));
            float mn0 = fmaxf(m0, mt0), mn1 = fmaxf(m1, mt1);
            float al0 = hex2((m0 - mn0)*SCL2), al1 = hex2((m1 - mn1)*SCL2);
            float nb0 = mn0 * SCL2, nb1 = mn1 * SCL2;
            float ls0 = 0.f, ls1 = 0.f;
#pragma unroll
            for (int nj = 0; nj < 8; nj++) {
                float p0 = hex2(fmaf(sa[nj][0], SCL2, -nb0));
                float p1 = hex2(fmaf(sa[nj][1], SCL2, -nb0));
                float p2 = hex2(fmaf(sa[nj][2], SCL2, -nb1));
                float p3 = hex2(fmaf(sa[nj][3], SCL2, -nb1));
                sa[nj][0]=p0; sa[nj][1]=p1; sa[nj][2]=p2; sa[nj][3]=p3;
                ls0 += p0 + p1; ls1 += p2 + p3;
            }
            ls0 += __shfl_xor_sync(0xffffffffu, ls0, 1);
            ls0 += __shfl_xor_sync(0xffffffffu, ls0, 2);
            ls1 += __shfl_xor_sync(0xffffffffu, ls1, 1);
            ls1 += __shfl_xor_sync(0xffffffffu, ls1, 2);
            l0 = l0*al0 + ls0; l1 = l1*al1 + ls1;
            m0 = mn0; m1 = mn1;
#pragma unroll
            for (int i2 = 0; i2 < 16; i2++) {
                oa[i2][0]*=al0; oa[i2][1]*=al0; oa[i2][2]*=al1; oa[i2][3]*=al1;
            }
            uint32_t pfh[4][4], pfl[4][4];
#pragma unroll
            for (int kt = 0; kt < 4; kt++) {
                packsplit(sa[2*kt][0],   sa[2*kt][1],   pfh[kt][0], pfl[kt][0]);
                packsplit(sa[2*kt][2],   sa[2*kt][3],   pfh[kt][1], pfl[kt][1]);
                packsplit(sa[2*kt+1][0], sa[2*kt+1][1], pfh[kt][2], pfl[kt][2]);
                packsplit(sa[2*kt+1][2], sa[2*kt+1][3], pfh[kt][3], pfl[kt][3]);
            }
            int mlane = lane >> 3;
            int kvr = (mlane & 1)*8 + (lane & 7);
            int hdc = (mlane >> 1)*8;
#pragma unroll
            for (int kt = 0; kt < 4; kt++) {
                uint32_t rbase = (uint32_t)((kt*16 + kvr)*ASTRB + hdc*2);
#pragma unroll
                for (int hp = 0; hp < 8; hp++) {
                    uint32_t vfh[4], vfl[4];
                    ldmx4t(vfh, VHs + rbase + hp*32);
                    ldmx4t(vfl, VLs + rbase + hp*32);
                    mma16816(oa[2*hp+0], pfh[kt], vfh[0], vfh[1]);
                    mma16816(oa[2*hp+1], pfh[kt], vfh[2], vfh[3]);
                    mma16816(oa[2*hp+0], pfh[kt], vfl[0], vfl[1]);
                    mma16816(oa[2*hp+1], pfh[kt], vfl[2], vfl[3]);
                    mma16816(oa[2*hp+0], pfl[kt], vfh[0], vfh[1]);
                    mma16816(oa[2*hp+1], pfl[kt], vfh[2], vfh[3]);
                }
            }
        }
        __syncthreads();
    }

    float inv0 = 1.f / l0, inv1 = 1.f / l1;
    size_t off0 = bbase + ((size_t)(wrow + g) << 11) + hbase;
    size_t off1 = bbase + ((size_t)(wrow + g + 8) << 11) + hbase;
#pragma unroll
    for (int hp = 0; hp < 16; hp++) {
        int hd = hp*8 + 2*tg;
        uint32_t h0, l0w, h1, l1w;
        packsplit(oa[hp][0]*inv0, oa[hp][1]*inv0, h0, l0w);
        packsplit(oa[hp][2]*inv1, oa[hp][3]*inv1, h1, l1w);
        *(uint32_t*)(Oh + off0 + hd) = h0;
        *(uint32_t*)(Ol + off0 + hd) = l0w;
        *(uint32_t*)(Oh + off1 + hd) = h1;
        *(uint32_t*)(Ol + off1 + hd) = l1w;
    }
}

// ---------------- router logits: hn @ slots_w (D x E) ----------------
__global__ void logits_kernel(const float* __restrict__ hn, const float* __restrict__ sw,
                              float* __restrict__ out) {
    int row = blockIdx.x;
    const float* hp = hn + (size_t)row * D;
    float acc[E];
#pragma unroll
    for (int e = 0; e < E; e++) acc[e] = 0.f;
#pragma unroll
    for (int i = 0; i < 8; i++) {
        int d = threadIdx.x + i*256;
        float hv = hp[d];
        const float* swp = sw + (size_t)d * E;
#pragma unroll
        for (int e = 0; e < E; e++) acc[e] += hv * swp[e];
    }
#pragma unroll
    for (int e = 0; e < E; e++)
        for (int o = 16; o > 0; o >>= 1) acc[e] += __shfl_xor_sync(0xffffffffu, acc[e], o);
    __shared__ float red[8][E];
    int warp = threadIdx.x >> 5, lane = threadIdx.x & 31;
    if (lane == 0)
#pragma unroll
        for (int e = 0; e < E; e++) red[warp][e] = acc[e];
    __syncthreads();
    if (threadIdx.x < E) {
        float s = 0.f;
#pragma unroll
        for (int w = 0; w < 8; w++) s += red[w][threadIdx.x];
        out[(size_t)row*E + threadIdx.x] = s;
    }
}

// ---------------- dispatch softmax (over T, per (b,e)) ----------------
__global__ void dispatch_softmax_kernel(const float* __restrict__ lg, float* __restrict__ out) {
    int b = blockIdx.x >> 3, e = blockIdx.x & 7;
    const float* lp = lg + (size_t)b*T*E + e;
    float v[8];
    float m = -1e30f;
#pragma unroll
    for (int i = 0; i < 8; i++) {
        v[i] = lp[(size_t)(threadIdx.x + i*256)*E];
        m = fmaxf(m, v[i]);
    }
    __shared__ float red[256];
    red[threadIdx.x] = m; __syncthreads();
    for (int s = 128; s > 0; s >>= 1) {
        if (threadIdx.x < s) red[threadIdx.x] = fmaxf(red[threadIdx.x], red[threadIdx.x + s]);
        __syncthreads();
    }
    m = red[0]; __syncthreads();
    float ssum = 0.f;
#pragma unroll
    for (int i = 0; i < 8; i++) { v[i] = __expf(v[i] - m); ssum += v[i]; }
    red[threadIdx.x] = ssum; __syncthreads();
    for (int s = 128; s > 0; s >>= 1) {
        if (threadIdx.x < s) red[threadIdx.x] += red[threadIdx.x + s];
        __syncthreads();
    }
    float inv = 1.f / red[0];
    float* op = out + (size_t)b*T*E + e;
#pragma unroll
    for (int i = 0; i < 8; i++) op[(size_t)(threadIdx.x + i*256)*E] = v[i]*inv;
}

// ---------------- combine softmax (over E, per (b,t)) ----------------
__global__ void combine_softmax_kernel(const float* __restrict__ lg, float* __restrict__ out) {
    int row = blockIdx.x*256 + threadIdx.x;
    const float* lp = lg + (size_t)row * E;
    float m = -1e30f;
#pragma unroll
    for (int e = 0; e < E; e++) m = fmaxf(m, lp[e]);
    float ve[E]; float s = 0.f;
#pragma unroll
    for (int e = 0; e < E; e++) { ve[e] = __expf(lp[e] - m); s += ve[e]; }
    float inv = 1.f / s;
    float* op = out + (size_t)row * E;
#pragma unroll
    for (int e = 0; e < E; e++) op[e] = ve[e]*inv;
}

// ---------------- slots (all experts in one pass) = dispatch^T @ hn ----------------
__global__ void slots_all_kernel(const float* __restrict__ disp, const float* __restrict__ hn,
                                 float* __restrict__ slots) {
    int d = blockIdx.x*256 + threadIdx.x;
    int b = blockIdx.y;
    __shared__ float sd[256][E];
    float acc[E];
#pragma unroll
    for (int e = 0; e < E; e++) acc[e] = 0.f;
    for (int t0 = 0; t0 < T; t0 += 256) {
        __syncthreads();
        const float4* dp = (const float4*)(disp + ((size_t)b*T + t0 + threadIdx.x)*E);
        float4 d0 = dp[0], d1 = dp[1];
        sd[threadIdx.x][0] = d0.x; sd[threadIdx.x][1] = d0.y;
        sd[threadIdx.x][2] = d0.z; sd[threadIdx.x][3] = d0.w;
        sd[threadIdx.x][4] = d1.x; sd[threadIdx.x][5] = d1.y;
        sd[threadIdx.x][6] = d1.z; sd[threadIdx.x][7] = d1.w;
        __syncthreads();
        const float* hp = hn + ((size_t)b*T + t0)*D + d;
#pragma unroll 4
        for (int tt = 0; tt < 256; tt++) {
            float hv = hp[(size_t)tt*D];
#pragma unroll
            for (int e = 0; e < E; e++) acc[e] += sd[tt][e] * hv;
        }
    }
#pragma unroll
    for (int e = 0; e < E; e++) slots[((size_t)b*E + e)*D + d] = acc[e];
}

// ---------------- expert up-proj: silu(slots@w1) * (slots@w3) ----------------
__global__ void gact_kernel(const float* __restrict__ slots, const float* __restrict__ w1,
                            const float* __restrict__ w3, float* __restrict__ gact) {
    int hcol = blockIdx.x*256 + threadIdx.x;
    int e = blockIdx.y;
    __shared__ float s0[D], s1[D];
    for (int i = threadIdx.x; i < D; i += 256) {
        s0[i] = slots[((size_t)0*E + e)*D + i];
        s1[i] = slots[((size_t)1*E + e)*D + i];
    }
    __syncthreads();
    float a10 = 0.f, a11 = 0.f, a30 = 0.f, a31 = 0.f;
    const float* w1p = w1 + (size_t)e*D*FH + hcol;
    const float* w3p = w3 + (size_t)e*D*FH + hcol;
#pragma unroll 8
    for (int dd = 0; dd < D; dd++) {
        float w1v = w1p[(size_t)dd*FH];
        float w3v = w3p[(size_t)dd*FH];
        a10 += s0[dd]*w1v; a11 += s1[dd]*w1v;
        a30 += s0[dd]*w3v; a31 += s1[dd]*w3v;
    }
    float g0 = a10 / (1.f + __expf(-a10)) * a30;
    float g1 = a11 / (1.f + __expf(-a11)) * a31;
    gact[((size_t)0*E + e)*FH + hcol] = g0;
    gact[((size_t)1*E + e)*FH + hcol] = g1;
}

// ---------------- expert down-proj, split-K partials ----------------
__global__ void w2_kernel(const float* __restrict__ gact, const float* __restrict__ w2,
                          float* __restrict__ ypart) {
    const int CH = FH / KS;
    int d = blockIdx.x*256 + threadIdx.x;
    int e = blockIdx.y;
    int kc = blockIdx.z;
    __shared__ float gg0[FH / KS], gg1[FH / KS];
    for (int i = threadIdx.x; i < CH; i += 256) {
        gg0[i] = gact[((size_t)0*E + e)*FH + kc*CH + i];
        gg1[i] = gact[((size_t)1*E + e)*FH + kc*CH + i];
    }
    __syncthreads();
    float a0 = 0.f, a1 = 0.f;
    const float* w2p = w2 + ((size_t)e*FH + (size_t)kc*CH)*D + d;
#pragma unroll 8
    for (int hh = 0; hh < CH; hh++) {
        float wv = w2p[(size_t)hh*D];
        a0 += gg0[hh]*wv; a1 += gg1[hh]*wv;
    }
    ypart[((size_t)kc*B*E + 0*E + e)*D + d] = a0;
    ypart[((size_t)kc*B*E + 1*E + e)*D + d] = a1;
}

__global__ void yreduce_kernel(const float* __restrict__ ypart, float* __restrict__ y) {
    int i = blockIdx.x*256 + threadIdx.x;
    float s = 0.f;
#pragma unroll
    for (int kc = 0; kc < KS; kc++) s += ypart[(size_t)kc*B*E*D + i];
    y[i] = s;
}

// ---------------- final: out = h + combine @ y ----------------
__global__ void final_kernel(const float* __restrict__ h, const float* __restrict__ comb,
                             const float* __restrict__ y, float* __restrict__ out) {
    int row = blockIdx.x;
    int b = row / T;
    float c[E];
    const float* cp = comb + (size_t)row*E;
#pragma unroll
    for (int e = 0; e < E; e++) c[e] = cp[e];
#pragma unroll
    for (int i = 0; i < 8; i++) {
        int d = threadIdx.x + i*256;
        float acc = h[(size_t)row*D + d];
#pragma unroll
        for (int e = 0; e < E; e++) acc += c[e] * y[((size_t)b*E + e)*D + d];
        out[(size_t)row*D + d] = acc;
    }
}

// ---------------- launch ----------------
extern "C" void kernel_launch(void* const* d_in, const int* in_sizes, int n_in,
                              void* d_out, int out_size) {
    const float* x   = (const float*)d_in[0];
    const float* fc  = (const float*)d_in[3];
    const float* wq  = (const float*)d_in[4];
    const float* wk  = (const float*)d_in[5];
    const float* wv  = (const float*)d_in[6];
    const float* wo  = (const float*)d_in[7];
    const float* sw  = (const float*)d_in[8];
    const float* w1  = (const float*)d_in[9];
    const float* w3  = (const float*)d_in[10];
    const float* w2  = (const float*)d_in[11];
    const float* anw = (const float*)d_in[12];
    const float* fnw = (const float*)d_in[13];
    const int* causal = (const int*)d_in[14];
    float* out = (float*)d_out;

    float *xn, *h, *hn, *logits, *disp, *comb, *slots, *gact, *ypart, *y;
    __nv_bfloat16 *ah, *al, *qh, *ql, *kh, *kl, *vh, *vl, *oh, *ol, *wth, *wtl;
    cudaGetSymbolAddress((void**)&xn,    g_xn);
    cudaGetSymbolAddress((void**)&h,     g_h);
    cudaGetSymbolAddress((void**)&hn,    g_hn);
    cudaGetSymbolAddress((void**)&logits,g_logits);
    cudaGetSymbolAddress((void**)&disp,  g_disp);
    cudaGetSymbolAddress((void**)&comb,  g_comb);
    cudaGetSymbolAddress((void**)&slots, g_slots);
    cudaGetSymbolAddress((void**)&gact,  g_gact);
    cudaGetSymbolAddress((void**)&ypart, g_ypart);
    cudaGetSymbolAddress((void**)&y,     g_y);
    cudaGetSymbolAddress((void**)&ah,    g_ah);
    cudaGetSymbolAddress((void**)&al,    g_al);
    cudaGetSymbolAddress((void**)&qh,    g_qh);
    cudaGetSymbolAddress((void**)&ql,    g_ql);
    cudaGetSymbolAddress((void**)&kh,    g_kh);
    cudaGetSymbolAddress((void**)&kl,    g_kl);
    cudaGetSymbolAddress((void**)&vh,    g_vh);
    cudaGetSymbolAddress((void**)&vl,    g_vl);
    cudaGetSymbolAddress((void**)&oh,    g_oh);
    cudaGetSymbolAddress((void**)&ol,    g_ol);
    cudaGetSymbolAddress((void**)&wth,   g_wth);
    cudaGetSymbolAddress((void**)&wtl,   g_wtl);

    cudaFuncSetAttribute(mma_gemm_kernel, cudaFuncAttributeMaxDynamicSharedMemorySize, MMA_SMEM);
    cudaFuncSetAttribute(fattn_kernel, cudaFuncAttributeMaxDynamicSharedMemorySize, FATTN_SMEM);

    const size_t NK = (size_t)D * D;

    rmsnorm_kernel<<<MT, 256>>>(x, anw, xn, ah, al);

    dim3 wgrid(D/32, D/32);
    wsplit_kernel<<<wgrid, dim3(32,8)>>>(wq, wth + 0*NK, wtl + 0*NK);
    wsplit_kernel<<<wgrid, dim3(32,8)>>>(wk, wth + 1*NK, wtl + 1*NK);
    wsplit_kernel<<<wgrid, dim3(32,8)>>>(wv, wth + 2*NK, wtl + 2*NK);
    wsplit_kernel<<<wgrid, dim3(32,8)>>>(wo, wth + 3*NK, wtl + 3*NK);

    dim3 gg(D/GN, MT/GM);
    mma_gemm_kernel<<<gg, 256, MMA_SMEM>>>(ah, al, wth + 0*NK, wtl + 0*NK, nullptr, nullptr,
                                           1, fc, qh, ql, MT, D, D);
    mma_gemm_kernel<<<gg, 256, MMA_SMEM>>>(ah, al, wth + 1*NK, wtl + 1*NK, nullptr, nullptr,
                                           1, fc, kh, kl, MT, D, D);
    mma_gemm_kernel<<<gg, 256, MMA_SMEM>>>(ah, al, wth + 2*NK, wtl + 2*NK, nullptr, nullptr,
                                           2, nullptr, vh, vl, MT, D, D);

    fattn_kernel<<<dim3(T/AQ, H, B), 256, FATTN_SMEM>>>(qh, ql, kh, kl, vh, vl, oh, ol, causal);

    mma_gemm_kernel<<<gg, 256, MMA_SMEM>>>(oh, ol, wth + 3*NK, wtl + 3*NK, xn, h,
                                           0, nullptr, nullptr, nullptr, MT, D, D);

    rmsnorm_kernel<<<MT, 256>>>(h, fnw, hn, nullptr, nullptr);

    logits_kernel<<<MT, 256>>>(hn, sw, logits);
    dispatch_softmax_kernel<<<B*E, 256>>>(logits, disp);
    combine_softmax_kernel<<<MT/256, 256>>>(logits, comb);

    slots_all_kernel<<<dim3(D/256, B), 256>>>(disp, hn, slots);
    gact_kernel<<<dim3(FH/256, E), 256>>>(slots, w1, w3, gact);
    w2_kernel<<<dim3(D/256, E, KS), 256>>>(gact, w2, ypart);
    yreduce_kernel<<<(B*E*D)/256, 256>>>(ypart, y);

    final_kernel<<<MT, 256>>>(h, comb, y, out);
}

// round 11
// speedup vs baseline: 1.0711x; 1.0390x over previous
#include <cuda_runtime.h>
#include <cuda_bf16.h>
#include <cuda_fp16.h>
#include <cstdint>
#include <cstddef>

#define B 2
#define T 2048
#define D 2048
#define H 16
#define HD 128
#define E 8
#define FH 8192
#define EPSV 1e-6f
#define MT (B*T)

// ---------------- scratch (device globals; no allocation) ----------------
__device__ float g_xn  [(size_t)B*T*D];
__device__ float g_h   [(size_t)B*T*D];
__device__ float g_hn  [(size_t)B*T*D];
__device__ float g_logits[(size_t)B*T*E];
__device__ float g_disp  [(size_t)B*T*E];
__device__ float g_comb  [(size_t)B*T*E];
__device__ float g_slots [(size_t)B*E*D];
__device__ float g_gact  [(size_t)B*E*FH];
#define KS 8
__device__ float g_ypart[(size_t)KS*B*E*D];
__device__ float g_y    [(size_t)B*E*D];
// split operands (fp16 for attention q/k/v; bf16 for GEMM A/B and attention output)
__device__ __nv_bfloat16 g_ah[(size_t)MT*D];
__device__ __nv_bfloat16 g_al[(size_t)MT*D];
__device__ __nv_bfloat16 g_qh[(size_t)MT*D];    // fp16 bits
__device__ __nv_bfloat16 g_kh[(size_t)MT*D];    // fp16 bits
__device__ __nv_bfloat16 g_kl[(size_t)MT*D];    // fp16 bits
__device__ __nv_bfloat16 g_vh[(size_t)MT*D];    // fp16 bits
__device__ __nv_bfloat16 g_vl[(size_t)MT*D];    // fp16 bits
__device__ __nv_bfloat16 g_oh[(size_t)MT*D];
__device__ __nv_bfloat16 g_ol[(size_t)MT*D];
__device__ __nv_bfloat16 g_wth[(size_t)4*D*D];
__device__ __nv_bfloat16 g_wtl[(size_t)4*D*D];

// ---------------- helpers ----------------
__device__ __forceinline__ uint32_t smem_u32(const void* p) {
    uint32_t a;
    asm("{ .reg .u64 t; cvta.to.shared.u64 t, %1; cvt.u32.u64 %0, t; }" : "=r"(a) : "l"(p));
    return a;
}
__device__ __forceinline__ void cp_async16(uint32_t saddr, const void* gaddr) {
    asm volatile("cp.async.ca.shared.global [%0], [%1], 16;" :: "r"(saddr), "l"(gaddr));
}
__device__ __forceinline__ void cp_commit() {
    asm volatile("cp.async.commit_group;");
}
template<int N>
__device__ __forceinline__ void cp_wait() {
    asm volatile("cp.async.wait_group %0;" :: "n"(N));
}
__device__ __forceinline__ void ldmx4(uint32_t* r, uint32_t addr) {
    asm volatile("ldmatrix.sync.aligned.m8n8.x4.shared.b16 {%0,%1,%2,%3}, [%4];"
                 : "=r"(r[0]), "=r"(r[1]), "=r"(r[2]), "=r"(r[3]) : "r"(addr));
}
__device__ __forceinline__ void ldmx4t(uint32_t* r, uint32_t addr) {
    asm volatile("ldmatrix.sync.aligned.m8n8.x4.trans.shared.b16 {%0,%1,%2,%3}, [%4];"
                 : "=r"(r[0]), "=r"(r[1]), "=r"(r[2]), "=r"(r[3]) : "r"(addr));
}
__device__ __forceinline__ void mma16816(float* c, const uint32_t* a, uint32_t b0, uint32_t b1) {
    asm volatile(
        "mma.sync.aligned.m16n8k16.row.col.f32.bf16.bf16.f32 "
        "{%0,%1,%2,%3}, {%4,%5,%6,%7}, {%8,%9}, {%0,%1,%2,%3};"
        : "+f"(c[0]), "+f"(c[1]), "+f"(c[2]), "+f"(c[3])
        : "r"(a[0]), "r"(a[1]), "r"(a[2]), "r"(a[3]), "r"(b0), "r"(b1));
}
__device__ __forceinline__ void mma16816h(float* c, const uint32_t* a, uint32_t b0, uint32_t b1) {
    asm volatile(
        "mma.sync.aligned.m16n8k16.row.col.f32.f16.f16.f32 "
        "{%0,%1,%2,%3}, {%4,%5,%6,%7}, {%8,%9}, {%0,%1,%2,%3};"
        : "+f"(c[0]), "+f"(c[1]), "+f"(c[2]), "+f"(c[3])
        : "r"(a[0]), "r"(a[1]), "r"(a[2]), "r"(a[3]), "r"(b0), "r"(b1));
}
// hardware exp2 (MUFU pipe)
__device__ __forceinline__ float hex2(float x) {
    float r; asm("ex2.approx.f32 %0, %1;" : "=f"(r) : "f"(x)); return r;
}
// bf16 hi/lo split pack (for GEMM operands)
__device__ __forceinline__ void packsplit(float p0, float p1, uint32_t& hi, uint32_t& lo) {
    __nv_bfloat16 h0 = __float2bfloat16_rn(p0), h1 = __float2bfloat16_rn(p1);
    __nv_bfloat162 hv(h0, h1);
    hi = *reinterpret_cast<uint32_t*>(&hv);
    __nv_bfloat162 lv(__float2bfloat16_rn(p0 - __bfloat162float(h0)),
                      __float2bfloat16_rn(p1 - __bfloat162float(h1)));
    lo = *reinterpret_cast<uint32_t*>(&lv);
}
// fp16 hi/lo split pack (for attention operands)
__device__ __forceinline__ void packsplit_h(float p0, float p1, uint32_t& hi, uint32_t& lo) {
    __half h0 = __float2half_rn(p0), h1 = __float2half_rn(p1);
    __half2 hv(h0, h1);
    hi = *reinterpret_cast<uint32_t*>(&hv);
    __half2 lv(__float2half_rn(p0 - __half2float(h0)),
               __float2half_rn(p1 - __half2float(h1)));
    lo = *reinterpret_cast<uint32_t*>(&lv);
}

// ---------------- rmsnorm (optional fused bf16 hi/lo split) ----------------
__global__ void rmsnorm_kernel(const float* __restrict__ x, const float* __restrict__ w,
                               float* __restrict__ out,
                               __nv_bfloat16* __restrict__ hi, __nv_bfloat16* __restrict__ lo) {
    int row = blockIdx.x;
    const float* xp = x + (size_t)row * D;
    float v[8];
    float ss = 0.f;
#pragma unroll
    for (int i = 0; i < 8; i++) { v[i] = xp[threadIdx.x + i*256]; ss += v[i]*v[i]; }
    __shared__ float red[256];
    red[threadIdx.x] = ss; __syncthreads();
    for (int s = 128; s > 0; s >>= 1) {
        if (threadIdx.x < s) red[threadIdx.x] += red[threadIdx.x + s];
        __syncthreads();
    }
    float rms = rsqrtf(red[0] / (float)D + EPSV);
    float* op = out + (size_t)row * D;
#pragma unroll
    for (int i = 0; i < 8; i++) {
        int d = threadIdx.x + i*256;
        float o = v[i]*rms*w[d];
        op[d] = o;
        if (hi) {
            __nv_bfloat16 hb = __float2bfloat16_rn(o);
            hi[(size_t)row*D + d] = hb;
            lo[(size_t)row*D + d] = __float2bfloat16_rn(o - __bfloat162float(hb));
        }
    }
}

// ---------------- transpose + split weights: W[K,N] -> WT[N,K] hi/lo bf16 ----------------
__global__ void wsplit_kernel(const float* __restrict__ W,
                              __nv_bfloat16* __restrict__ th, __nv_bfloat16* __restrict__ tl) {
    __shared__ float t[32][33];
    int n0 = blockIdx.x * 32, k0 = blockIdx.y * 32;
    int tx = threadIdx.x, ty = threadIdx.y;   // 32 x 8
#pragma unroll
    for (int i = 0; i < 4; i++)
        t[ty + 8*i][tx] = W[(size_t)(k0 + ty + 8*i) * D + n0 + tx];
    __syncthreads();
#pragma unroll
    for (int i = 0; i < 4; i++) {
        float v = t[tx][ty + 8*i];
        size_t o = (size_t)(n0 + ty + 8*i) * D + k0 + tx;
        __nv_bfloat16 hv = __float2bfloat16_rn(v);
        th[o] = hv;
        tl[o] = __float2bfloat16_rn(v - __bfloat162float(hv));
    }
}

// ---------------- mma.sync GEMM: C[M,N] = A[M,K] @ B^T (B given [N,K]) ----------------
// mode 0: fp32 C (+Res). mode 1: rope + fp16 hi/lo split. mode 2: fp16 hi/lo split.
// (modes 1/2 feed the fp16 attention kernel; Clo may be nullptr to skip lo)
#define GM 128
#define GN 128
#define GK 32
#define TSTR 40
#define TILE_B2 (128*TSTR*2)
#define STG_B2 (4*TILE_B2)
#define MMA_SMEM (2*STG_B2)

__global__ __launch_bounds__(256, 2)
void mma_gemm_kernel(const __nv_bfloat16* __restrict__ Ah, const __nv_bfloat16* __restrict__ Al,
                     const __nv_bfloat16* __restrict__ Bh, const __nv_bfloat16* __restrict__ Bl,
                     const float* __restrict__ Res, float* __restrict__ C,
                     int mode, const float* __restrict__ fc,
                     __nv_bfloat16* __restrict__ Chi, __nv_bfloat16* __restrict__ Clo,
                     int Mdim, int Ndim, int Kdim) {
    extern __shared__ char smem[];
    uint32_t sb = smem_u32(smem);
    int tid = threadIdx.x, lane = tid & 31, warp = tid >> 5;
    int wm = warp & 3, wn = warp >> 2;
    int m0 = blockIdx.y * GM, n0 = blockIdx.x * GN;

    int lrow[2], lcol[2];
    uint32_t sdst[2];
#pragma unroll
    for (int p = 0; p < 2; p++) {
        int idx = tid + p*256;
        lrow[p] = idx >> 2;
        lcol[p] = (idx & 3) * 8;
        sdst[p] = (uint32_t)(lrow[p]*TSTR + lcol[p]) * 2;
    }

    const int nkt = Kdim / GK;

    auto issue = [&](int kt, int stage) {
        uint32_t s0 = sb + stage * STG_B2;
        const __nv_bfloat16* srcs[4] = {
            Ah + (size_t)m0 * Kdim, Al + (size_t)m0 * Kdim,
            Bh + (size_t)n0 * Kdim, Bl + (size_t)n0 * Kdim };
#pragma unroll
        for (int tl = 0; tl < 4; tl++) {
#pragma unroll
            for (int p = 0; p < 2; p++) {
                const __nv_bfloat16* g = srcs[tl] + (size_t)lrow[p] * Kdim + kt*GK + lcol[p];
                cp_async16(s0 + tl*TILE_B2 + sdst[p], g);
            }
        }
        cp_commit();
    };

    float acc[2][8][4];
#pragma unroll
    for (int mi = 0; mi < 2; mi++)
#pragma unroll
        for (int nj = 0; nj < 8; nj++)
#pragma unroll
            for (int c = 0; c < 4; c++) acc[mi][nj][c] = 0.f;

    int lr = lane & 15, lc8 = (lane >> 4) << 3;

    issue(0, 0);

    for (int kt = 0; kt < nkt; kt++) {
        int stage = kt & 1;
        if (kt + 1 < nkt) { issue(kt + 1, stage ^ 1); cp_wait<1>(); }
        else              { cp_wait<0>(); }
        __syncthreads();

        uint32_t s0 = sb + stage * STG_B2;
        uint32_t sAh = s0, sAl = s0 + TILE_B2, sBh = s0 + 2*TILE_B2, sBl = s0 + 3*TILE_B2;

#pragma unroll
        for (int ks = 0; ks < 2; ks++) {
            int kc = ks*16 + lc8;
            uint32_t ah[2][4], al[2][4], bh[4][4], bl[4][4];
#pragma unroll
            for (int mi = 0; mi < 2; mi++)
                ldmx4(ah[mi], sAh + (uint32_t)((wm*32 + mi*16 + lr)*TSTR + kc) * 2);
#pragma unroll
            for (int njp = 0; njp < 4; njp++)
                ldmx4(bh[njp], sBh + (uint32_t)((wn*64 + njp*16 + lr)*TSTR + kc) * 2);
#pragma unroll
            for (int mi = 0; mi < 2; mi++)
#pragma unroll
                for (int njp = 0; njp < 4; njp++) {
                    mma16816(acc[mi][2*njp+0], ah[mi], bh[njp][0], bh[njp][2]);
                    mma16816(acc[mi][2*njp+1], ah[mi], bh[njp][1], bh[njp][3]);
                }
#pragma unroll
            for (int mi = 0; mi < 2; mi++)
                ldmx4(al[mi], sAl + (uint32_t)((wm*32 + mi*16 + lr)*TSTR + kc) * 2);
#pragma unroll
            for (int mi = 0; mi < 2; mi++)
#pragma unroll
                for (int njp = 0; njp < 4; njp++) {
                    mma16816(acc[mi][2*njp+0], al[mi], bh[njp][0], bh[njp][2]);
                    mma16816(acc[mi][2*njp+1], al[mi], bh[njp][1], bh[njp][3]);
                }
#pragma unroll
            for (int njp = 0; njp < 4; njp++)
                ldmx4(bl[njp], sBl + (uint32_t)((wn*64 + njp*16 + lr)*TSTR + kc) * 2);
#pragma unroll
            for (int mi = 0; mi < 2; mi++)
#pragma unroll
                for (int njp = 0; njp < 4; njp++) {
                    mma16816(acc[mi][2*njp+0], ah[mi], bl[njp][0], bl[njp][2]);
                    mma16816(acc[mi][2*njp+1], ah[mi], bl[njp][1], bl[njp][3]);
                }
        }
        __syncthreads();
    }

    int g = lane >> 2, tg = lane & 3;
    if (mode == 0) {
#pragma unroll
        for (int mi = 0; mi < 2; mi++) {
            size_t row0 = (size_t)(m0 + wm*32 + mi*16 + g);
#pragma unroll
            for (int nj = 0; nj < 8; nj++) {
                size_t col = (size_t)(n0 + wn*64 + nj*8 + tg*2);
                float2 v0 = make_float2(acc[mi][nj][0], acc[mi][nj][1]);
                float2 v1 = make_float2(acc[mi][nj][2], acc[mi][nj][3]);
                if (Res) {
                    float2 r0 = *(const float2*)(Res + row0*Ndim + col);
                    float2 r1 = *(const float2*)(Res + (row0+8)*Ndim + col);
                    v0.x += r0.x; v0.y += r0.y; v1.x += r1.x; v1.y += r1.y;
                }
                *(float2*)(C + row0*Ndim + col) = v0;
                *(float2*)(C + (row0+8)*Ndim + col) = v1;
            }
        }
    } else {
#pragma unroll
        for (int mi = 0; mi < 2; mi++) {
            size_t row0 = (size_t)(m0 + wm*32 + mi*16 + g);
            size_t row1 = row0 + 8;
#pragma unroll
            for (int nj = 0; nj < 8; nj++) {
                int col = n0 + wn*64 + nj*8 + tg*2;
                float2 v0 = make_float2(acc[mi][nj][0], acc[mi][nj][1]);
                float2 v1 = make_float2(acc[mi][nj][2], acc[mi][nj][3]);
                if (mode == 1) {
                    int cb = col & (HD - 1);
                    float2 c0 = *(const float2*)(fc + (size_t)(row0 & (T-1))*HD + cb);
                    float2 c1 = *(const float2*)(fc + (size_t)(row1 & (T-1))*HD + cb);
                    v0 = make_float2(v0.x*c0.x - v0.y*c0.y, v0.x*c0.y + v0.y*c0.x);
                    v1 = make_float2(v1.x*c1.x - v1.y*c1.y, v1.x*c1.y + v1.y*c1.x);
                }
                uint32_t h0, l0w, h1, l1w;
                packsplit_h(v0.x, v0.y, h0, l0w);
                packsplit_h(v1.x, v1.y, h1, l1w);
                *(uint32_t*)(Chi + row0*Ndim + col) = h0;
                *(uint32_t*)(Chi + row1*Ndim + col) = h1;
                if (Clo) {
                    *(uint32_t*)(Clo + row0*Ndim + col) = l0w;
                    *(uint32_t*)(Clo + row1*Ndim + col) = l1w;
                }
            }
        }
    }
}

// ---------------- flash attention (mma.sync fp16, 2-term split, MUFU exp) ----------------
// S = Qh*Kh + Qh*Kl ; O = Ph*Vh + Ph*Vl  (fp16 hi/lo; dropped cross terms ~2^-12)
#define AQ 128
#define AKV 64
#define ASTRB 272
#define ATILE_B (AKV*ASTRB)
#define ASTG_B (4*ATILE_B)
#define FATTN_SMEM (2*ASTG_B)
#define SCL2 0.12751743867f             // (1/sqrt(128)) * log2(e)

__global__ __launch_bounds__(256)
void fattn_kernel(const __nv_bfloat16* __restrict__ Qh,
                  const __nv_bfloat16* __restrict__ Kh, const __nv_bfloat16* __restrict__ Kl,
                  const __nv_bfloat16* __restrict__ Vh, const __nv_bfloat16* __restrict__ Vl,
                  __nv_bfloat16* __restrict__ Oh, __nv_bfloat16* __restrict__ Ol,
                  const int* __restrict__ causal_flag) {
    extern __shared__ char smem[];
    uint32_t sb = smem_u32(smem);
    int tid = threadIdx.x, lane = tid & 31, warp = tid >> 5;
    int g = lane >> 2, tg = lane & 3;
    // heavy causal tiles first for better tail packing
    int q0 = (gridDim.x - 1 - blockIdx.x) * AQ;
    int h = blockIdx.y, b = blockIdx.z;
    bool causal = (*causal_flag) != 0;
    int wrow = q0 + warp * 16;

    uint32_t s0 = sb, s1 = sb + ASTG_B;

    const size_t bbase = ((size_t)b * T) << 11;
    const size_t hbase = (size_t)h * HD;

    // async-load Q-hi into s0 (fp16, 128 rows x 128 cols)
#pragma unroll
    for (int j = 0; j < 8; j++) {
        int c = tid + j*256;
        int r = c >> 4, col = c & 15;
        cp_async16(s0 + r*ASTRB + col*16,
                   Qh + bbase + ((size_t)(q0 + r) << 11) + hbase + col*8);
    }
    cp_commit();

    auto issue_kv = [&](int kvt, uint32_t stg) {
        int k0 = kvt * AKV;
        const __nv_bfloat16* ptrs[4] = {Kh, Kl, Vh, Vl};
#pragma unroll
        for (int tl = 0; tl < 4; tl++) {
#pragma unroll
            for (int j = 0; j < 4; j++) {
                int c = tid + j*256;
                int r = c >> 4, col = c & 15;
                cp_async16(stg + tl*ATILE_B + r*ASTRB + col*16,
                           ptrs[tl] + bbase + ((size_t)(k0 + r) << 11) + hbase + col*8);
            }
        }
        cp_commit();
    };

    int ntile = causal ? (q0 + AQ)/AKV : T/AKV;
    issue_kv(0, s1);

    cp_wait<1>();
    __syncthreads();

    int lr = lane & 15, c8 = (lane >> 4) << 3;
    uint32_t qf[8][4];
#pragma unroll
    for (int ks = 0; ks < 8; ks++)
        ldmx4(qf[ks], s0 + (warp*16 + lr)*ASTRB + (ks*16 + c8)*2);
    __syncthreads();

    float oa[16][4];
#pragma unroll
    for (int i = 0; i < 16; i++) { oa[i][0]=0.f; oa[i][1]=0.f; oa[i][2]=0.f; oa[i][3]=0.f; }
    float m0 = -1e30f, m1 = -1e30f, l0 = 0.f, l1 = 0.f;

    for (int kvt = 0; kvt < ntile; kvt++) {
        uint32_t cur = (kvt & 1) ? s0 : s1;
        uint32_t nxt = (kvt & 1) ? s1 : s0;
        if (kvt + 1 < ntile) { issue_kv(kvt + 1, nxt); cp_wait<1>(); }
        else                 { cp_wait<0>(); }
        __syncthreads();
        int k0 = kvt * AKV;

        if (!causal || k0 <= wrow + 15) {
            uint32_t KHs = cur, KLs = cur + ATILE_B, VHs = cur + 2*ATILE_B, VLs = cur + 3*ATILE_B;
            float sa[8][4];
#pragma unroll
            for (int nj = 0; nj < 8; nj++) { sa[nj][0]=0.f; sa[nj][1]=0.f; sa[nj][2]=0.f; sa[nj][3]=0.f; }
#pragma unroll
            for (int ks = 0; ks < 8; ks++) {
                uint32_t bh[4][4], bl[4][4];
#pragma unroll
                for (int n4 = 0; n4 < 4; n4++)
                    ldmx4(bh[n4], KHs + (n4*16 + lr)*ASTRB + (ks*16 + c8)*2);
#pragma unroll
                for (int n4 = 0; n4 < 4; n4++) {
                    mma16816h(sa[2*n4+0], qf[ks], bh[n4][0], bh[n4][2]);
                    mma16816h(sa[2*n4+1], qf[ks], bh[n4][1], bh[n4][3]);
                }
#pragma unroll
                for (int n4 = 0; n4 < 4; n4++)
                    ldmx4(bl[n4], KLs + (n4*16 + lr)*ASTRB + (ks*16 + c8)*2);
#pragma unroll
                for (int n4 = 0; n4 < 4; n4++) {
                    mma16816h(sa[2*n4+0], qf[ks], bl[n4][0], bl[n4][2]);
                    mma16816h(sa[2*n4+1], qf[ks], bl[n4][1], bl[n4][3]);
                }
            }
            if (causal && k0 + 63 > wrow) {
#pragma unroll
                for (int nj = 0; nj < 8; nj++) {
                    int col = k0 + nj*8 + 2*tg;
                    if (col     > wrow + g)     sa[nj][0] = -1e30f;
                    if (col + 1 > wrow + g)     sa[nj][1] = -1e30f;
                    if (col     > wrow + g + 8) sa[nj][2] = -1e30f;
                    if (col + 1 > wrow + g + 8) sa[nj][3] = -1e30f;
                }
            }
            float mt0 = -1e30f, mt1 = -1e30f;
#pragma unroll
            for (int nj = 0; nj < 8; nj++) {
                mt0 = fmaxf(mt0, fmaxf(sa[nj][0], sa[nj][1]));
                mt1 = fmaxf(mt1, fmaxf(sa[nj][2], sa[nj][3]));
            }
            mt0 = fmaxf(mt0, __shfl_xor_sync(0xffffffffu, mt0, 1));
            mt0 = fmaxf(mt0, __shfl_xor_sync(0xffffffffu, mt0, 2));
            mt1 = fmaxf(mt1, __shfl_xor_sync(0xffffffffu, mt1, 1));
            mt1 = fmaxf(mt1, __shfl_xor_sync(0xffffffffu, mt1, 2));
            float mn0 = fmaxf(m0, mt0), mn1 = fmaxf(m1, mt1);
            float al0 = hex2((m0 - mn0)*SCL2), al1 = hex2((m1 - mn1)*SCL2);
            float nb0 = mn0 * SCL2, nb1 = mn1 * SCL2;
            float ls0 = 0.f, ls1 = 0.f;
#pragma unroll
            for (int nj = 0; nj < 8; nj++) {
                float p0 = hex2(fmaf(sa[nj][0], SCL2, -nb0));
                float p1 = hex2(fmaf(sa[nj][1], SCL2, -nb0));
                float p2 = hex2(fmaf(sa[nj][2], SCL2, -nb1));
                float p3 = hex2(fmaf(sa[nj][3], SCL2, -nb1));
                sa[nj][0]=p0; sa[nj][1]=p1; sa[nj][2]=p2; sa[nj][3]=p3;
                ls0 += p0 + p1; ls1 += p2 + p3;
            }
            ls0 += __shfl_xor_sync(0xffffffffu, ls0, 1);
            ls0 += __shfl_xor_sync(0xffffffffu, ls0, 2);
            ls1 += __shfl_xor_sync(0xffffffffu, ls1, 1);
            ls1 += __shfl_xor_sync(0xffffffffu, ls1, 2);
            l0 = l0*al0 + ls0; l1 = l1*al1 + ls1;
            m0 = mn0; m1 = mn1;
#pragma unroll
            for (int i2 = 0; i2 < 16; i2++) {
                oa[i2][0]*=al0; oa[i2][1]*=al0; oa[i2][2]*=al1; oa[i2][3]*=al1;
            }
            // P fragments (S-acc layout -> A-frag layout), fp16 hi only
            uint32_t pf[4][4];
#pragma unroll
            for (int kt = 0; kt < 4; kt++) {
                __half2 t0 = __floats2half2_rn(sa[2*kt][0],   sa[2*kt][1]);
                __half2 t1 = __floats2half2_rn(sa[2*kt][2],   sa[2*kt][3]);
                __half2 t2 = __floats2half2_rn(sa[2*kt+1][0], sa[2*kt+1][1]);
                __half2 t3 = __floats2half2_rn(sa[2*kt+1][2], sa[2*kt+1][3]);
                pf[kt][0] = *reinterpret_cast<uint32_t*>(&t0);
                pf[kt][1] = *reinterpret_cast<uint32_t*>(&t1);
                pf[kt][2] = *reinterpret_cast<uint32_t*>(&t2);
                pf[kt][3] = *reinterpret_cast<uint32_t*>(&t3);
            }
            int mlane = lane >> 3;
            int kvr = (mlane & 1)*8 + (lane & 7);
            int hdc = (mlane >> 1)*8;
#pragma unroll
            for (int kt = 0; kt < 4; kt++) {
                uint32_t rbase = (uint32_t)((kt*16 + kvr)*ASTRB + hdc*2);
#pragma unroll
                for (int hp = 0; hp < 8; hp++) {
                    uint32_t vfh[4], vfl[4];
                    ldmx4t(vfh, VHs + rbase + hp*32);
                    ldmx4t(vfl, VLs + rbase + hp*32);
                    mma16816h(oa[2*hp+0], pf[kt], vfh[0], vfh[1]);
                    mma16816h(oa[2*hp+1], pf[kt], vfh[2], vfh[3]);
                    mma16816h(oa[2*hp+0], pf[kt], vfl[0], vfl[1]);
                    mma16816h(oa[2*hp+1], pf[kt], vfl[2], vfl[3]);
                }
            }
        }
        __syncthreads();
    }

    float inv0 = 1.f / l0, inv1 = 1.f / l1;
    size_t off0 = bbase + ((size_t)(wrow + g) << 11) + hbase;
    size_t off1 = bbase + ((size_t)(wrow + g + 8) << 11) + hbase;
#pragma unroll
    for (int hp = 0; hp < 16; hp++) {
        int hd = hp*8 + 2*tg;
        uint32_t h0, l0w, h1, l1w;
        packsplit(oa[hp][0]*inv0, oa[hp][1]*inv0, h0, l0w);      // bf16 for Wo GEMM
        packsplit(oa[hp][2]*inv1, oa[hp][3]*inv1, h1, l1w);
        *(uint32_t*)(Oh + off0 + hd) = h0;
        *(uint32_t*)(Ol + off0 + hd) = l0w;
        *(uint32_t*)(Oh + off1 + hd) = h1;
        *(uint32_t*)(Ol + off1 + hd) = l1w;
    }
}

// ---------------- router logits: hn @ slots_w (D x E) ----------------
__global__ void logits_kernel(const float* __restrict__ hn, const float* __restrict__ sw,
                              float* __restrict__ out) {
    int row = blockIdx.x;
    const float* hp = hn + (size_t)row * D;
    float acc[E];
#pragma unroll
    for (int e = 0; e < E; e++) acc[e] = 0.f;
#pragma unroll
    for (int i = 0; i < 8; i++) {
        int d = threadIdx.x + i*256;
        float hv = hp[d];
        const float* swp = sw + (size_t)d * E;
#pragma unroll
        for (int e = 0; e < E; e++) acc[e] += hv * swp[e];
    }
#pragma unroll
    for (int e = 0; e < E; e++)
        for (int o = 16; o > 0; o >>= 1) acc[e] += __shfl_xor_sync(0xffffffffu, acc[e], o);
    __shared__ float red[8][E];
    int warp = threadIdx.x >> 5, lane = threadIdx.x & 31;
    if (lane == 0)
#pragma unroll
        for (int e = 0; e < E; e++) red[warp][e] = acc[e];
    __syncthreads();
    if (threadIdx.x < E) {
        float s = 0.f;
#pragma unroll
        for (int w = 0; w < 8; w++) s += red[w][threadIdx.x];
        out[(size_t)row*E + threadIdx.x] = s;
    }
}

// ---------------- dispatch softmax (over T, per (b,e)) ----------------
__global__ void dispatch_softmax_kernel(const float* __restrict__ lg, float* __restrict__ out) {
    int b = blockIdx.x >> 3, e = blockIdx.x & 7;
    const float* lp = lg + (size_t)b*T*E + e;
    float v[8];
    float m = -1e30f;
#pragma unroll
    for (int i = 0; i < 8; i++) {
        v[i] = lp[(size_t)(threadIdx.x + i*256)*E];
        m = fmaxf(m, v[i]);
    }
    __shared__ float red[256];
    red[threadIdx.x] = m; __syncthreads();
    for (int s = 128; s > 0; s >>= 1) {
        if (threadIdx.x < s) red[threadIdx.x] = fmaxf(red[threadIdx.x], red[threadIdx.x + s]);
        __syncthreads();
    }
    m = red[0]; __syncthreads();
    float ssum = 0.f;
#pragma unroll
    for (int i = 0; i < 8; i++) { v[i] = __expf(v[i] - m); ssum += v[i]; }
    red[threadIdx.x] = ssum; __syncthreads();
    for (int s = 128; s > 0; s >>= 1) {
        if (threadIdx.x < s) red[threadIdx.x] += red[threadIdx.x + s];
        __syncthreads();
    }
    float inv = 1.f / red[0];
    float* op = out + (size_t)b*T*E + e;
#pragma unroll
    for (int i = 0; i < 8; i++) op[(size_t)(threadIdx.x + i*256)*E] = v[i]*inv;
}

// ---------------- combine softmax (over E, per (b,t)) ----------------
__global__ void combine_softmax_kernel(const float* __restrict__ lg, float* __restrict__ out) {
    int row = blockIdx.x*256 + threadIdx.x;
    const float* lp = lg + (size_t)row * E;
    float m = -1e30f;
#pragma unroll
    for (int e = 0; e < E; e++) m = fmaxf(m, lp[e]);
    float ve[E]; float s = 0.f;
#pragma unroll
    for (int e = 0; e < E; e++) { ve[e] = __expf(lp[e] - m); s += ve[e]; }
    float inv = 1.f / s;
    float* op = out + (size_t)row * E;
#pragma unroll
    for (int e = 0; e < E; e++) op[e] = ve[e]*inv;
}

// ---------------- slots (all experts in one pass) = dispatch^T @ hn ----------------
__global__ void slots_all_kernel(const float* __restrict__ disp, const float* __restrict__ hn,
                                 float* __restrict__ slots) {
    int d = blockIdx.x*256 + threadIdx.x;
    int b = blockIdx.y;
    __shared__ float sd[256][E];
    float acc[E];
#pragma unroll
    for (int e = 0; e < E; e++) acc[e] = 0.f;
    for (int t0 = 0; t0 < T; t0 += 256) {
        __syncthreads();
        const float4* dp = (const float4*)(disp + ((size_t)b*T + t0 + threadIdx.x)*E);
        float4 d0 = dp[0], d1 = dp[1];
        sd[threadIdx.x][0] = d0.x; sd[threadIdx.x][1] = d0.y;
        sd[threadIdx.x][2] = d0.z; sd[threadIdx.x][3] = d0.w;
        sd[threadIdx.x][4] = d1.x; sd[threadIdx.x][5] = d1.y;
        sd[threadIdx.x][6] = d1.z; sd[threadIdx.x][7] = d1.w;
        __syncthreads();
        const float* hp = hn + ((size_t)b*T + t0)*D + d;
#pragma unroll 4
        for (int tt = 0; tt < 256; tt++) {
            float hv = hp[(size_t)tt*D];
#pragma unroll
            for (int e = 0; e < E; e++) acc[e] += sd[tt][e] * hv;
        }
    }
#pragma unroll
    for (int e = 0; e < E; e++) slots[((size_t)b*E + e)*D + d] = acc[e];
}

// ---------------- expert up-proj: silu(slots@w1) * (slots@w3) ----------------
__global__ void gact_kernel(const float* __restrict__ slots, const float* __restrict__ w1,
                            const float* __restrict__ w3, float* __restrict__ gact) {
    int hcol = blockIdx.x*256 + threadIdx.x;
    int e = blockIdx.y;
    __shared__ float s0[D], s1[D];
    for (int i = threadIdx.x; i < D; i += 256) {
        s0[i] = slots[((size_t)0*E + e)*D + i];
        s1[i] = slots[((size_t)1*E + e)*D + i];
    }
    __syncthreads();
    float a10 = 0.f, a11 = 0.f, a30 = 0.f, a31 = 0.f;
    const float* w1p = w1 + (size_t)e*D*FH + hcol;
    const float* w3p = w3 + (size_t)e*D*FH + hcol;
#pragma unroll 8
    for (int dd = 0; dd < D; dd++) {
        float w1v = w1p[(size_t)dd*FH];
        float w3v = w3p[(size_t)dd*FH];
        a10 += s0[dd]*w1v; a11 += s1[dd]*w1v;
        a30 += s0[dd]*w3v; a31 += s1[dd]*w3v;
    }
    float g0 = a10 / (1.f + __expf(-a10)) * a30;
    float g1 = a11 / (1.f + __expf(-a11)) * a31;
    gact[((size_t)0*E + e)*FH + hcol] = g0;
    gact[((size_t)1*E + e)*FH + hcol] = g1;
}

// ---------------- expert down-proj, split-K partials ----------------
__global__ void w2_kernel(const float* __restrict__ gact, const float* __restrict__ w2,
                          float* __restrict__ ypart) {
    const int CH = FH / KS;
    int d = blockIdx.x*256 + threadIdx.x;
    int e = blockIdx.y;
    int kc = blockIdx.z;
    __shared__ float gg0[FH / KS], gg1[FH / KS];
    for (int i = threadIdx.x; i < CH; i += 256) {
        gg0[i] = gact[((size_t)0*E + e)*FH + kc*CH + i];
        gg1[i] = gact[((size_t)1*E + e)*FH + kc*CH + i];
    }
    __syncthreads();
    float a0 = 0.f, a1 = 0.f;
    const float* w2p = w2 + ((size_t)e*FH + (size_t)kc*CH)*D + d;
#pragma unroll 8
    for (int hh = 0; hh < CH; hh++) {
        float wv = w2p[(size_t)hh*D];
        a0 += gg0[hh]*wv; a1 += gg1[hh]*wv;
    }
    ypart[((size_t)kc*B*E + 0*E + e)*D + d] = a0;
    ypart[((size_t)kc*B*E + 1*E + e)*D + d] = a1;
}

__global__ void yreduce_kernel(const float* __restrict__ ypart, float* __restrict__ y) {
    int i = blockIdx.x*256 + threadIdx.x;
    float s = 0.f;
#pragma unroll
    for (int kc = 0; kc < KS; kc++) s += ypart[(size_t)kc*B*E*D + i];
    y[i] = s;
}

// ---------------- final: out = h + combine @ y ----------------
__global__ void final_kernel(const float* __restrict__ h, const float* __restrict__ comb,
                             const float* __restrict__ y, float* __restrict__ out) {
    int row = blockIdx.x;
    int b = row / T;
    float c[E];
    const float* cp = comb + (size_t)row*E;
#pragma unroll
    for (int e = 0; e < E; e++) c[e] = cp[e];
#pragma unroll
    for (int i = 0; i < 8; i++) {
        int d = threadIdx.x + i*256;
        float acc = h[(size_t)row*D + d];
#pragma unroll
        for (int e = 0; e < E; e++) acc += c[e] * y[((size_t)b*E + e)*D + d];
        out[(size_t)row*D + d] = acc;
    }
}

// ---------------- launch ----------------
extern "C" void kernel_launch(void* const* d_in, const int* in_sizes, int n_in,
                              void* d_out, int out_size) {
    const float* x   = (const float*)d_in[0];
    const float* fc  = (const float*)d_in[3];
    const float* wq  = (const float*)d_in[4];
    const float* wk  = (const float*)d_in[5];
    const float* wv  = (const float*)d_in[6];
    const float* wo  = (const float*)d_in[7];
    const float* sw  = (const float*)d_in[8];
    const float* w1  = (const float*)d_in[9];
    const float* w3  = (const float*)d_in[10];
    const float* w2  = (const float*)d_in[11];
    const float* anw = (const float*)d_in[12];
    const float* fnw = (const float*)d_in[13];
    const int* causal = (const int*)d_in[14];
    float* out = (float*)d_out;

    float *xn, *h, *hn, *logits, *disp, *comb, *slots, *gact, *ypart, *y;
    __nv_bfloat16 *ah, *al, *qh, *kh, *kl, *vh, *vl, *oh, *ol, *wth, *wtl;
    cudaGetSymbolAddress((void**)&xn,    g_xn);
    cudaGetSymbolAddress((void**)&h,     g_h);
    cudaGetSymbolAddress((void**)&hn,    g_hn);
    cudaGetSymbolAddress((void**)&logits,g_logits);
    cudaGetSymbolAddress((void**)&disp,  g_disp);
    cudaGetSymbolAddress((void**)&comb,  g_comb);
    cudaGetSymbolAddress((void**)&slots, g_slots);
    cudaGetSymbolAddress((void**)&gact,  g_gact);
    cudaGetSymbolAddress((void**)&ypart, g_ypart);
    cudaGetSymbolAddress((void**)&y,     g_y);
    cudaGetSymbolAddress((void**)&ah,    g_ah);
    cudaGetSymbolAddress((void**)&al,    g_al);
    cudaGetSymbolAddress((void**)&qh,    g_qh);
    cudaGetSymbolAddress((void**)&kh,    g_kh);
    cudaGetSymbolAddress((void**)&kl,    g_kl);
    cudaGetSymbolAddress((void**)&vh,    g_vh);
    cudaGetSymbolAddress((void**)&vl,    g_vl);
    cudaGetSymbolAddress((void**)&oh,    g_oh);
    cudaGetSymbolAddress((void**)&ol,    g_ol);
    cudaGetSymbolAddress((void**)&wth,   g_wth);
    cudaGetSymbolAddress((void**)&wtl,   g_wtl);

    cudaFuncSetAttribute(mma_gemm_kernel, cudaFuncAttributeMaxDynamicSharedMemorySize, MMA_SMEM);
    cudaFuncSetAttribute(fattn_kernel, cudaFuncAttributeMaxDynamicSharedMemorySize, FATTN_SMEM);

    const size_t NK = (size_t)D * D;

    rmsnorm_kernel<<<MT, 256>>>(x, anw, xn, ah, al);

    dim3 wgrid(D/32, D/32);
    wsplit_kernel<<<wgrid, dim3(32,8)>>>(wq, wth + 0*NK, wtl + 0*NK);
    wsplit_kernel<<<wgrid, dim3(32,8)>>>(wk, wth + 1*NK, wtl + 1*NK);
    wsplit_kernel<<<wgrid, dim3(32,8)>>>(wv, wth + 2*NK, wtl + 2*NK);
    wsplit_kernel<<<wgrid, dim3(32,8)>>>(wo, wth + 3*NK, wtl + 3*NK);

    dim3 gg(D/GN, MT/GM);
    // QKV GEMMs: rope+fp16 split epilogues (q: hi only; k,v: hi+lo)
    mma_gemm_kernel<<<gg, 256, MMA_SMEM>>>(ah, al, wth + 0*NK, wtl + 0*NK, nullptr, nullptr,
                                           1, fc, qh, nullptr, MT, D, D);
    mma_gemm_kernel<<<gg, 256, MMA_SMEM>>>(ah, al, wth + 1*NK, wtl + 1*NK, nullptr, nullptr,
                                           1, fc, kh, kl, MT, D, D);
    mma_gemm_kernel<<<gg, 256, MMA_SMEM>>>(ah, al, wth + 2*NK, wtl + 2*NK, nullptr, nullptr,
                                           2, nullptr, vh, vl, MT, D, D);

    fattn_kernel<<<dim3(T/AQ, H, B), 256, FATTN_SMEM>>>(qh, kh, kl, vh, vl, oh, ol, causal);

    mma_gemm_kernel<<<gg, 256, MMA_SMEM>>>(oh, ol, wth + 3*NK, wtl + 3*NK, xn, h,
                                           0, nullptr, nullptr, nullptr, MT, D, D);

    rmsnorm_kernel<<<MT, 256>>>(h, fnw, hn, nullptr, nullptr);

    logits_kernel<<<MT, 256>>>(hn, sw, logits);
    dispatch_softmax_kernel<<<B*E, 256>>>(logits, disp);
    combine_softmax_kernel<<<MT/256, 256>>>(logits, comb);

    slots_all_kernel<<<dim3(D/256, B), 256>>>(disp, hn, slots);
    gact_kernel<<<dim3(FH/256, E), 256>>>(slots, w1, w3, gact);
    w2_kernel<<<dim3(D/256, E, KS), 256>>>(gact, w2, ypart);
    yreduce_kernel<<<(B*E*D)/256, 256>>>(ypart, y);

    final_kernel<<<MT, 256>>>(h, comb, y, out);
}

// round 12
// speedup vs baseline: 1.3025x; 1.2160x over previous
#include <cuda_runtime.h>
#include <cuda_bf16.h>
#include <cuda_fp16.h>
#include <cstdint>
#include <cstddef>

#define B 2
#define T 2048
#define D 2048
#define H 16
#define HD 128
#define E 8
#define FH 8192
#define EPSV 1e-6f
#define MT (B*T)

// ---------------- scratch (device globals; no allocation) ----------------
__device__ float g_xn  [(size_t)B*T*D];
__device__ float g_h   [(size_t)B*T*D];
__device__ float g_hn  [(size_t)B*T*D];
__device__ float g_logits[(size_t)B*T*E];
__device__ float g_disp  [(size_t)B*T*E];
__device__ float g_comb  [(size_t)B*T*E];
__device__ float g_slots [(size_t)B*E*D];
__device__ float g_gact  [(size_t)B*E*FH];
#define KS 8
__device__ float g_ypart[(size_t)KS*B*E*D];
__device__ float g_y    [(size_t)B*E*D];
// fp16 split operands
__device__ __half g_ah[(size_t)MT*D];
__device__ __half g_al[(size_t)MT*D];
__device__ __half g_qh[(size_t)MT*D];
__device__ __half g_kh[(size_t)MT*D];
__device__ __half g_kl[(size_t)MT*D];
__device__ __half g_vh[(size_t)MT*D];
__device__ __half g_vl[(size_t)MT*D];
__device__ __half g_oh[(size_t)MT*D];
__device__ __half g_ol[(size_t)MT*D];
__device__ __half g_wth[(size_t)4*D*D];   // W^T fp16 (hi only)

// ---------------- helpers ----------------
__device__ __forceinline__ uint32_t smem_u32(const void* p) {
    uint32_t a;
    asm("{ .reg .u64 t; cvta.to.shared.u64 t, %1; cvt.u32.u64 %0, t; }" : "=r"(a) : "l"(p));
    return a;
}
__device__ __forceinline__ void cp_async16(uint32_t saddr, const void* gaddr) {
    asm volatile("cp.async.ca.shared.global [%0], [%1], 16;" :: "r"(saddr), "l"(gaddr));
}
__device__ __forceinline__ void cp_commit() {
    asm volatile("cp.async.commit_group;");
}
template<int N>
__device__ __forceinline__ void cp_wait() {
    asm volatile("cp.async.wait_group %0;" :: "n"(N));
}
__device__ __forceinline__ void ldmx4(uint32_t* r, uint32_t addr) {
    asm volatile("ldmatrix.sync.aligned.m8n8.x4.shared.b16 {%0,%1,%2,%3}, [%4];"
                 : "=r"(r[0]), "=r"(r[1]), "=r"(r[2]), "=r"(r[3]) : "r"(addr));
}
__device__ __forceinline__ void ldmx4t(uint32_t* r, uint32_t addr) {
    asm volatile("ldmatrix.sync.aligned.m8n8.x4.trans.shared.b16 {%0,%1,%2,%3}, [%4];"
                 : "=r"(r[0]), "=r"(r[1]), "=r"(r[2]), "=r"(r[3]) : "r"(addr));
}
__device__ __forceinline__ void mma16816h(float* c, const uint32_t* a, uint32_t b0, uint32_t b1) {
    asm volatile(
        "mma.sync.aligned.m16n8k16.row.col.f32.f16.f16.f32 "
        "{%0,%1,%2,%3}, {%4,%5,%6,%7}, {%8,%9}, {%0,%1,%2,%3};"
        : "+f"(c[0]), "+f"(c[1]), "+f"(c[2]), "+f"(c[3])
        : "r"(a[0]), "r"(a[1]), "r"(a[2]), "r"(a[3]), "r"(b0), "r"(b1));
}
// hardware exp2 (MUFU pipe)
__device__ __forceinline__ float hex2(float x) {
    float r; asm("ex2.approx.f32 %0, %1;" : "=f"(r) : "f"(x)); return r;
}
// fp16 hi/lo split pack
__device__ __forceinline__ void packsplit_h(float p0, float p1, uint32_t& hi, uint32_t& lo) {
    __half h0 = __float2half_rn(p0), h1 = __float2half_rn(p1);
    __half2 hv(h0, h1);
    hi = *reinterpret_cast<uint32_t*>(&hv);
    __half2 lv(__float2half_rn(p0 - __half2float(h0)),
               __float2half_rn(p1 - __half2float(h1)));
    lo = *reinterpret_cast<uint32_t*>(&lv);
}

// ---------------- rmsnorm (optional fused fp16 hi/lo split) ----------------
__global__ void rmsnorm_kernel(const float* __restrict__ x, const float* __restrict__ w,
                               float* __restrict__ out,
                               __half* __restrict__ hi, __half* __restrict__ lo) {
    int row = blockIdx.x;
    const float* xp = x + (size_t)row * D;
    float v[8];
    float ss = 0.f;
#pragma unroll
    for (int i = 0; i < 8; i++) { v[i] = xp[threadIdx.x + i*256]; ss += v[i]*v[i]; }
    __shared__ float red[256];
    red[threadIdx.x] = ss; __syncthreads();
    for (int s = 128; s > 0; s >>= 1) {
        if (threadIdx.x < s) red[threadIdx.x] += red[threadIdx.x + s];
        __syncthreads();
    }
    float rms = rsqrtf(red[0] / (float)D + EPSV);
    float* op = out + (size_t)row * D;
#pragma unroll
    for (int i = 0; i < 8; i++) {
        int d = threadIdx.x + i*256;
        float o = v[i]*rms*w[d];
        op[d] = o;
        if (hi) {
            __half hb = __float2half_rn(o);
            hi[(size_t)row*D + d] = hb;
            lo[(size_t)row*D + d] = __float2half_rn(o - __half2float(hb));
        }
    }
}

// ---------------- transpose weights: W[K,N] -> WT[N,K] fp16 ----------------
__global__ void wsplit_kernel(const float* __restrict__ W, __half* __restrict__ th) {
    __shared__ float t[32][33];
    int n0 = blockIdx.x * 32, k0 = blockIdx.y * 32;
    int tx = threadIdx.x, ty = threadIdx.y;   // 32 x 8
#pragma unroll
    for (int i = 0; i < 4; i++)
        t[ty + 8*i][tx] = W[(size_t)(k0 + ty + 8*i) * D + n0 + tx];
    __syncthreads();
#pragma unroll
    for (int i = 0; i < 4; i++) {
        float v = t[tx][ty + 8*i];
        th[(size_t)(n0 + ty + 8*i) * D + k0 + tx] = __float2half_rn(v);
    }
}

// ---------------- mma.sync GEMM (fp16 2-term): C = (Ah+Al) @ Bh^T ----------------
// mode 0: fp32 C (+Res). mode 1: rope + fp16 hi/lo split. mode 2: fp16 hi/lo split.
#define GM 128
#define GN 128
#define GK 32
#define TSTR 40
#define TILE_B2 (128*TSTR*2)
#define STG_B2 (3*TILE_B2)
#define MMA_SMEM (2*STG_B2)

__global__ __launch_bounds__(256, 2)
void mma_gemm_kernel(const __half* __restrict__ Ah, const __half* __restrict__ Al,
                     const __half* __restrict__ Bh,
                     const float* __restrict__ Res, float* __restrict__ C,
                     int mode, const float* __restrict__ fc,
                     __half* __restrict__ Chi, __half* __restrict__ Clo,
                     int Mdim, int Ndim, int Kdim) {
    extern __shared__ char smem[];
    uint32_t sb = smem_u32(smem);
    int tid = threadIdx.x, lane = tid & 31, warp = tid >> 5;
    int wm = warp & 3, wn = warp >> 2;
    int m0 = blockIdx.y * GM, n0 = blockIdx.x * GN;

    int lrow[2], lcol[2];
    uint32_t sdst[2];
#pragma unroll
    for (int p = 0; p < 2; p++) {
        int idx = tid + p*256;
        lrow[p] = idx >> 2;
        lcol[p] = (idx & 3) * 8;
        sdst[p] = (uint32_t)(lrow[p]*TSTR + lcol[p]) * 2;
    }

    const int nkt = Kdim / GK;

    auto issue = [&](int kt, int stage) {
        uint32_t s0 = sb + stage * STG_B2;
        const __half* srcs[3] = {
            Ah + (size_t)m0 * Kdim, Al + (size_t)m0 * Kdim, Bh + (size_t)n0 * Kdim };
#pragma unroll
        for (int tl = 0; tl < 3; tl++) {
#pragma unroll
            for (int p = 0; p < 2; p++) {
                const __half* g = srcs[tl] + (size_t)lrow[p] * Kdim + kt*GK + lcol[p];
                cp_async16(s0 + tl*TILE_B2 + sdst[p], g);
            }
        }
        cp_commit();
    };

    float acc[2][8][4];
#pragma unroll
    for (int mi = 0; mi < 2; mi++)
#pragma unroll
        for (int nj = 0; nj < 8; nj++)
#pragma unroll
            for (int c = 0; c < 4; c++) acc[mi][nj][c] = 0.f;

    int lr = lane & 15, lc8 = (lane >> 4) << 3;

    issue(0, 0);

    for (int kt = 0; kt < nkt; kt++) {
        int stage = kt & 1;
        if (kt + 1 < nkt) { issue(kt + 1, stage ^ 1); cp_wait<1>(); }
        else              { cp_wait<0>(); }
        __syncthreads();

        uint32_t s0 = sb + stage * STG_B2;
        uint32_t sAh = s0, sAl = s0 + TILE_B2, sBh = s0 + 2*TILE_B2;

#pragma unroll
        for (int ks = 0; ks < 2; ks++) {
            int kc = ks*16 + lc8;
            uint32_t ah[2][4], al[2][4], bh[4][4];
#pragma unroll
            for (int mi = 0; mi < 2; mi++)
                ldmx4(ah[mi], sAh + (uint32_t)((wm*32 + mi*16 + lr)*TSTR + kc) * 2);
#pragma unroll
            for (int njp = 0; njp < 4; njp++)
                ldmx4(bh[njp], sBh + (uint32_t)((wn*64 + njp*16 + lr)*TSTR + kc) * 2);
#pragma unroll
            for (int mi = 0; mi < 2; mi++)
#pragma unroll
                for (int njp = 0; njp < 4; njp++) {
                    mma16816h(acc[mi][2*njp+0], ah[mi], bh[njp][0], bh[njp][2]);
                    mma16816h(acc[mi][2*njp+1], ah[mi], bh[njp][1], bh[njp][3]);
                }
#pragma unroll
            for (int mi = 0; mi < 2; mi++)
                ldmx4(al[mi], sAl + (uint32_t)((wm*32 + mi*16 + lr)*TSTR + kc) * 2);
#pragma unroll
            for (int mi = 0; mi < 2; mi++)
#pragma unroll
                for (int njp = 0; njp < 4; njp++) {
                    mma16816h(acc[mi][2*njp+0], al[mi], bh[njp][0], bh[njp][2]);
                    mma16816h(acc[mi][2*njp+1], al[mi], bh[njp][1], bh[njp][3]);
                }
        }
        __syncthreads();
    }

    int g = lane >> 2, tg = lane & 3;
    if (mode == 0) {
#pragma unroll
        for (int mi = 0; mi < 2; mi++) {
            size_t row0 = (size_t)(m0 + wm*32 + mi*16 + g);
#pragma unroll
            for (int nj = 0; nj < 8; nj++) {
                size_t col = (size_t)(n0 + wn*64 + nj*8 + tg*2);
                float2 v0 = make_float2(acc[mi][nj][0], acc[mi][nj][1]);
                float2 v1 = make_float2(acc[mi][nj][2], acc[mi][nj][3]);
                if (Res) {
                    float2 r0 = *(const float2*)(Res + row0*Ndim + col);
                    float2 r1 = *(const float2*)(Res + (row0+8)*Ndim + col);
                    v0.x += r0.x; v0.y += r0.y; v1.x += r1.x; v1.y += r1.y;
                }
                *(float2*)(C + row0*Ndim + col) = v0;
                *(float2*)(C + (row0+8)*Ndim + col) = v1;
            }
        }
    } else {
#pragma unroll
        for (int mi = 0; mi < 2; mi++) {
            size_t row0 = (size_t)(m0 + wm*32 + mi*16 + g);
            size_t row1 = row0 + 8;
#pragma unroll
            for (int nj = 0; nj < 8; nj++) {
                int col = n0 + wn*64 + nj*8 + tg*2;
                float2 v0 = make_float2(acc[mi][nj][0], acc[mi][nj][1]);
                float2 v1 = make_float2(acc[mi][nj][2], acc[mi][nj][3]);
                if (mode == 1) {
                    int cb = col & (HD - 1);
                    float2 c0 = *(const float2*)(fc + (size_t)(row0 & (T-1))*HD + cb);
                    float2 c1 = *(const float2*)(fc + (size_t)(row1 & (T-1))*HD + cb);
                    v0 = make_float2(v0.x*c0.x - v0.y*c0.y, v0.x*c0.y + v0.y*c0.x);
                    v1 = make_float2(v1.x*c1.x - v1.y*c1.y, v1.x*c1.y + v1.y*c1.x);
                }
                uint32_t h0, l0w, h1, l1w;
                packsplit_h(v0.x, v0.y, h0, l0w);
                packsplit_h(v1.x, v1.y, h1, l1w);
                *(uint32_t*)(Chi + row0*Ndim + col) = h0;
                *(uint32_t*)(Chi + row1*Ndim + col) = h1;
                if (Clo) {
                    *(uint32_t*)(Clo + row0*Ndim + col) = l0w;
                    *(uint32_t*)(Clo + row1*Ndim + col) = l1w;
                }
            }
        }
    }
}

// ---------------- flash attention (mma.sync fp16, 2-term split, MUFU exp) ----------------
#define AQ 128
#define AKV 64
#define ASTRB 272
#define ATILE_B (AKV*ASTRB)
#define ASTG_B (4*ATILE_B)
#define FATTN_SMEM (2*ASTG_B)
#define SCL2 0.12751743867f             // (1/sqrt(128)) * log2(e)

__global__ __launch_bounds__(256)
void fattn_kernel(const __half* __restrict__ Qh,
                  const __half* __restrict__ Kh, const __half* __restrict__ Kl,
                  const __half* __restrict__ Vh, const __half* __restrict__ Vl,
                  __half* __restrict__ Oh, __half* __restrict__ Ol,
                  const int* __restrict__ causal_flag) {
    extern __shared__ char smem[];
    uint32_t sb = smem_u32(smem);
    int tid = threadIdx.x, lane = tid & 31, warp = tid >> 5;
    int g = lane >> 2, tg = lane & 3;
    int q0 = (gridDim.x - 1 - blockIdx.x) * AQ;   // heavy tiles first
    int h = blockIdx.y, b = blockIdx.z;
    bool causal = (*causal_flag) != 0;
    int wrow = q0 + warp * 16;

    uint32_t s0 = sb, s1 = sb + ASTG_B;

    const size_t bbase = ((size_t)b * T) << 11;
    const size_t hbase = (size_t)h * HD;

#pragma unroll
    for (int j = 0; j < 8; j++) {
        int c = tid + j*256;
        int r = c >> 4, col = c & 15;
        cp_async16(s0 + r*ASTRB + col*16,
                   Qh + bbase + ((size_t)(q0 + r) << 11) + hbase + col*8);
    }
    cp_commit();

    auto issue_kv = [&](int kvt, uint32_t stg) {
        int k0 = kvt * AKV;
        const __half* ptrs[4] = {Kh, Kl, Vh, Vl};
#pragma unroll
        for (int tl = 0; tl < 4; tl++) {
#pragma unroll
            for (int j = 0; j < 4; j++) {
                int c = tid + j*256;
                int r = c >> 4, col = c & 15;
                cp_async16(stg + tl*ATILE_B + r*ASTRB + col*16,
                           ptrs[tl] + bbase + ((size_t)(k0 + r) << 11) + hbase + col*8);
            }
        }
        cp_commit();
    };

    int ntile = causal ? (q0 + AQ)/AKV : T/AKV;
    issue_kv(0, s1);

    cp_wait<1>();
    __syncthreads();

    int lr = lane & 15, c8 = (lane >> 4) << 3;
    uint32_t qf[8][4];
#pragma unroll
    for (int ks = 0; ks < 8; ks++)
        ldmx4(qf[ks], s0 + (warp*16 + lr)*ASTRB + (ks*16 + c8)*2);
    __syncthreads();

    float oa[16][4];
#pragma unroll
    for (int i = 0; i < 16; i++) { oa[i][0]=0.f; oa[i][1]=0.f; oa[i][2]=0.f; oa[i][3]=0.f; }
    float m0 = -1e30f, m1 = -1e30f, l0 = 0.f, l1 = 0.f;

    for (int kvt = 0; kvt < ntile; kvt++) {
        uint32_t cur = (kvt & 1) ? s0 : s1;
        uint32_t nxt = (kvt & 1) ? s1 : s0;
        if (kvt + 1 < ntile) { issue_kv(kvt + 1, nxt); cp_wait<1>(); }
        else                 { cp_wait<0>(); }
        __syncthreads();
        int k0 = kvt * AKV;

        if (!causal || k0 <= wrow + 15) {
            uint32_t KHs = cur, KLs = cur + ATILE_B, VHs = cur + 2*ATILE_B, VLs = cur + 3*ATILE_B;
            float sa[8][4];
#pragma unroll
            for (int nj = 0; nj < 8; nj++) { sa[nj][0]=0.f; sa[nj][1]=0.f; sa[nj][2]=0.f; sa[nj][3]=0.f; }
#pragma unroll
            for (int ks = 0; ks < 8; ks++) {
                uint32_t bh[4][4], bl[4][4];
#pragma unroll
                for (int n4 = 0; n4 < 4; n4++)
                    ldmx4(bh[n4], KHs + (n4*16 + lr)*ASTRB + (ks*16 + c8)*2);
#pragma unroll
                for (int n4 = 0; n4 < 4; n4++) {
                    mma16816h(sa[2*n4+0], qf[ks], bh[n4][0], bh[n4][2]);
                    mma16816h(sa[2*n4+1], qf[ks], bh[n4][1], bh[n4][3]);
                }
#pragma unroll
                for (int n4 = 0; n4 < 4; n4++)
                    ldmx4(bl[n4], KLs + (n4*16 + lr)*ASTRB + (ks*16 + c8)*2);
#pragma unroll
                for (int n4 = 0; n4 < 4; n4++) {
                    mma16816h(sa[2*n4+0], qf[ks], bl[n4][0], bl[n4][2]);
                    mma16816h(sa[2*n4+1], qf[ks], bl[n4][1], bl[n4][3]);
                }
            }
            if (causal && k0 + 63 > wrow) {
#pragma unroll
                for (int nj = 0; nj < 8; nj++) {
                    int col = k0 + nj*8 + 2*tg;
                    if (col     > wrow + g)     sa[nj][0] = -1e30f;
                    if (col + 1 > wrow + g)     sa[nj][1] = -1e30f;
                    if (col     > wrow + g + 8) sa[nj][2] = -1e30f;
                    if (col + 1 > wrow + g + 8) sa[nj][3] = -1e30f;
                }
            }
            float mt0 = -1e30f, mt1 = -1e30f;
#pragma unroll
            for (int nj = 0; nj < 8; nj++) {
                mt0 = fmaxf(mt0, fmaxf(sa[nj][0], sa[nj][1]));
                mt1 = fmaxf(mt1, fmaxf(sa[nj][2], sa[nj][3]));
            }
            mt0 = fmaxf(mt0, __shfl_xor_sync(0xffffffffu, mt0, 1));
            mt0 = fmaxf(mt0, __shfl_xor_sync(0xffffffffu, mt0, 2));
            mt1 = fmaxf(mt1, __shfl_xor_sync(0xffffffffu, mt1, 1));
            mt1 = fmaxf(mt1, __shfl_xor_sync(0xffffffffu, mt1, 2));
            float mn0 = fmaxf(m0, mt0), mn1 = fmaxf(m1, mt1);
            float al0 = hex2((m0 - mn0)*SCL2), al1 = hex2((m1 - mn1)*SCL2);
            float nb0 = mn0 * SCL2, nb1 = mn1 * SCL2;
            float ls0 = 0.f, ls1 = 0.f;
#pragma unroll
            for (int nj = 0; nj < 8; nj++) {
                float p0 = hex2(fmaf(sa[nj][0], SCL2, -nb0));
                float p1 = hex2(fmaf(sa[nj][1], SCL2, -nb0));
                float p2 = hex2(fmaf(sa[nj][2], SCL2, -nb1));
                float p3 = hex2(fmaf(sa[nj][3], SCL2, -nb1));
                sa[nj][0]=p0; sa[nj][1]=p1; sa[nj][2]=p2; sa[nj][3]=p3;
                ls0 += p0 + p1; ls1 += p2 + p3;
            }
            ls0 += __shfl_xor_sync(0xffffffffu, ls0, 1);
            ls0 += __shfl_xor_sync(0xffffffffu, ls0, 2);
            ls1 += __shfl_xor_sync(0xffffffffu, ls1, 1);
            ls1 += __shfl_xor_sync(0xffffffffu, ls1, 2);
            l0 = l0*al0 + ls0; l1 = l1*al1 + ls1;
            m0 = mn0; m1 = mn1;
#pragma unroll
            for (int i2 = 0; i2 < 16; i2++) {
                oa[i2][0]*=al0; oa[i2][1]*=al0; oa[i2][2]*=al1; oa[i2][3]*=al1;
            }
            uint32_t pf[4][4];
#pragma unroll
            for (int kt = 0; kt < 4; kt++) {
                __half2 t0 = __floats2half2_rn(sa[2*kt][0],   sa[2*kt][1]);
                __half2 t1 = __floats2half2_rn(sa[2*kt][2],   sa[2*kt][3]);
                __half2 t2 = __floats2half2_rn(sa[2*kt+1][0], sa[2*kt+1][1]);
                __half2 t3 = __floats2half2_rn(sa[2*kt+1][2], sa[2*kt+1][3]);
                pf[kt][0] = *reinterpret_cast<uint32_t*>(&t0);
                pf[kt][1] = *reinterpret_cast<uint32_t*>(&t1);
                pf[kt][2] = *reinterpret_cast<uint32_t*>(&t2);
                pf[kt][3] = *reinterpret_cast<uint32_t*>(&t3);
            }
            int mlane = lane >> 3;
            int kvr = (mlane & 1)*8 + (lane & 7);
            int hdc = (mlane >> 1)*8;
#pragma unroll
            for (int kt = 0; kt < 4; kt++) {
                uint32_t rbase = (uint32_t)((kt*16 + kvr)*ASTRB + hdc*2);
#pragma unroll
                for (int hp = 0; hp < 8; hp++) {
                    uint32_t vfh[4], vfl[4];
                    ldmx4t(vfh, VHs + rbase + hp*32);
                    ldmx4t(vfl, VLs + rbase + hp*32);
                    mma16816h(oa[2*hp+0], pf[kt], vfh[0], vfh[1]);
                    mma16816h(oa[2*hp+1], pf[kt], vfh[2], vfh[3]);
                    mma16816h(oa[2*hp+0], pf[kt], vfl[0], vfl[1]);
                    mma16816h(oa[2*hp+1], pf[kt], vfl[2], vfl[3]);
                }
            }
        }
        __syncthreads();
    }

    float inv0 = 1.f / l0, inv1 = 1.f / l1;
    size_t off0 = bbase + ((size_t)(wrow + g) << 11) + hbase;
    size_t off1 = bbase + ((size_t)(wrow + g + 8) << 11) + hbase;
#pragma unroll
    for (int hp = 0; hp < 16; hp++) {
        int hd = hp*8 + 2*tg;
        uint32_t h0, l0w, h1, l1w;
        packsplit_h(oa[hp][0]*inv0, oa[hp][1]*inv0, h0, l0w);    // fp16 for Wo GEMM
        packsplit_h(oa[hp][2]*inv1, oa[hp][3]*inv1, h1, l1w);
        *(uint32_t*)(Oh + off0 + hd) = h0;
        *(uint32_t*)(Ol + off0 + hd) = l0w;
        *(uint32_t*)(Oh + off1 + hd) = h1;
        *(uint32_t*)(Ol + off1 + hd) = l1w;
    }
}

// ---------------- router logits: hn @ slots_w (D x E) ----------------
__global__ void logits_kernel(const float* __restrict__ hn, const float* __restrict__ sw,
                              float* __restrict__ out) {
    int row = blockIdx.x;
    const float* hp = hn + (size_t)row * D;
    float acc[E];
#pragma unroll
    for (int e = 0; e < E; e++) acc[e] = 0.f;
#pragma unroll
    for (int i = 0; i < 8; i++) {
        int d = threadIdx.x + i*256;
        float hv = hp[d];
        const float* swp = sw + (size_t)d * E;
#pragma unroll
        for (int e = 0; e < E; e++) acc[e] += hv * swp[e];
    }
#pragma unroll
    for (int e = 0; e < E; e++)
        for (int o = 16; o > 0; o >>= 1) acc[e] += __shfl_xor_sync(0xffffffffu, acc[e], o);
    __shared__ float red[8][E];
    int warp = threadIdx.x >> 5, lane = threadIdx.x & 31;
    if (lane == 0)
#pragma unroll
        for (int e = 0; e < E; e++) red[warp][e] = acc[e];
    __syncthreads();
    if (threadIdx.x < E) {
        float s = 0.f;
#pragma unroll
        for (int w = 0; w < 8; w++) s += red[w][threadIdx.x];
        out[(size_t)row*E + threadIdx.x] = s;
    }
}

// ---------------- dispatch softmax (over T, per (b,e)) ----------------
__global__ void dispatch_softmax_kernel(const float* __restrict__ lg, float* __restrict__ out) {
    int b = blockIdx.x >> 3, e = blockIdx.x & 7;
    const float* lp = lg + (size_t)b*T*E + e;
    float v[8];
    float m = -1e30f;
#pragma unroll
    for (int i = 0; i < 8; i++) {
        v[i] = lp[(size_t)(threadIdx.x + i*256)*E];
        m = fmaxf(m, v[i]);
    }
    __shared__ float red[256];
    red[threadIdx.x] = m; __syncthreads();
    for (int s = 128; s > 0; s >>= 1) {
        if (threadIdx.x < s) red[threadIdx.x] = fmaxf(red[threadIdx.x], red[threadIdx.x + s]);
        __syncthreads();
    }
    m = red[0]; __syncthreads();
    float ssum = 0.f;
#pragma unroll
    for (int i = 0; i < 8; i++) { v[i] = __expf(v[i] - m); ssum += v[i]; }
    red[threadIdx.x] = ssum; __syncthreads();
    for (int s = 128; s > 0; s >>= 1) {
        if (threadIdx.x < s) red[threadIdx.x] += red[threadIdx.x + s];
        __syncthreads();
    }
    float inv = 1.f / red[0];
    float* op = out + (size_t)b*T*E + e;
#pragma unroll
    for (int i = 0; i < 8; i++) op[(size_t)(threadIdx.x + i*256)*E] = v[i]*inv;
}

// ---------------- combine softmax (over E, per (b,t)) ----------------
__global__ void combine_softmax_kernel(const float* __restrict__ lg, float* __restrict__ out) {
    int row = blockIdx.x*256 + threadIdx.x;
    const float* lp = lg + (size_t)row * E;
    float m = -1e30f;
#pragma unroll
    for (int e = 0; e < E; e++) m = fmaxf(m, lp[e]);
    float ve[E]; float s = 0.f;
#pragma unroll
    for (int e = 0; e < E; e++) { ve[e] = __expf(lp[e] - m); s += ve[e]; }
    float inv = 1.f / s;
    float* op = out + (size_t)row * E;
#pragma unroll
    for (int e = 0; e < E; e++) op[e] = ve[e]*inv;
}

// ---------------- slots (all experts in one pass) = dispatch^T @ hn ----------------
__global__ void slots_all_kernel(const float* __restrict__ disp, const float* __restrict__ hn,
                                 float* __restrict__ slots) {
    int d = blockIdx.x*256 + threadIdx.x;
    int b = blockIdx.y;
    __shared__ float sd[256][E];
    float acc[E];
#pragma unroll
    for (int e = 0; e < E; e++) acc[e] = 0.f;
    for (int t0 = 0; t0 < T; t0 += 256) {
        __syncthreads();
        const float4* dp = (const float4*)(disp + ((size_t)b*T + t0 + threadIdx.x)*E);
        float4 d0 = dp[0], d1 = dp[1];
        sd[threadIdx.x][0] = d0.x; sd[threadIdx.x][1] = d0.y;
        sd[threadIdx.x][2] = d0.z; sd[threadIdx.x][3] = d0.w;
        sd[threadIdx.x][4] = d1.x; sd[threadIdx.x][5] = d1.y;
        sd[threadIdx.x][6] = d1.z; sd[threadIdx.x][7] = d1.w;
        __syncthreads();
        const float* hp = hn + ((size_t)b*T + t0)*D + d;
#pragma unroll 4
        for (int tt = 0; tt < 256; tt++) {
            float hv = hp[(size_t)tt*D];
#pragma unroll
            for (int e = 0; e < E; e++) acc[e] += sd[tt][e] * hv;
        }
    }
#pragma unroll
    for (int e = 0; e < E; e++) slots[((size_t)b*E + e)*D + d] = acc[e];
}

// ---------------- expert up-proj: silu(slots@w1) * (slots@w3) ----------------
__global__ void gact_kernel(const float* __restrict__ slots, const float* __restrict__ w1,
                            const float* __restrict__ w3, float* __restrict__ gact) {
    int hcol = blockIdx.x*256 + threadIdx.x;
    int e = blockIdx.y;
    __shared__ float s0[D], s1[D];
    for (int i = threadIdx.x; i < D; i += 256) {
        s0[i] = slots[((size_t)0*E + e)*D + i];
        s1[i] = slots[((size_t)1*E + e)*D + i];
    }
    __syncthreads();
    float a10 = 0.f, a11 = 0.f, a30 = 0.f, a31 = 0.f;
    const float* w1p = w1 + (size_t)e*D*FH + hcol;
    const float* w3p = w3 + (size_t)e*D*FH + hcol;
#pragma unroll 8
    for (int dd = 0; dd < D; dd++) {
        float w1v = w1p[(size_t)dd*FH];
        float w3v = w3p[(size_t)dd*FH];
        a10 += s0[dd]*w1v; a11 += s1[dd]*w1v;
        a30 += s0[dd]*w3v; a31 += s1[dd]*w3v;
    }
    float g0 = a10 / (1.f + __expf(-a10)) * a30;
    float g1 = a11 / (1.f + __expf(-a11)) * a31;
    gact[((size_t)0*E + e)*FH + hcol] = g0;
    gact[((size_t)1*E + e)*FH + hcol] = g1;
}

// ---------------- expert down-proj, split-K partials ----------------
__global__ void w2_kernel(const float* __restrict__ gact, const float* __restrict__ w2,
                          float* __restrict__ ypart) {
    const int CH = FH / KS;
    int d = blockIdx.x*256 + threadIdx.x;
    int e = blockIdx.y;
    int kc = blockIdx.z;
    __shared__ float gg0[FH / KS], gg1[FH / KS];
    for (int i = threadIdx.x; i < CH; i += 256) {
        gg0[i] = gact[((size_t)0*E + e)*FH + kc*CH + i];
        gg1[i] = gact[((size_t)1*E + e)*FH + kc*CH + i];
    }
    __syncthreads();
    float a0 = 0.f, a1 = 0.f;
    const float* w2p = w2 + ((size_t)e*FH + (size_t)kc*CH)*D + d;
#pragma unroll 8
    for (int hh = 0; hh < CH; hh++) {
        float wv = w2p[(size_t)hh*D];
        a0 += gg0[hh]*wv; a1 += gg1[hh]*wv;
    }
    ypart[((size_t)kc*B*E + 0*E + e)*D + d] = a0;
    ypart[((size_t)kc*B*E + 1*E + e)*D + d] = a1;
}

__global__ void yreduce_kernel(const float* __restrict__ ypart, float* __restrict__ y) {
    int i = blockIdx.x*256 + threadIdx.x;
    float s = 0.f;
#pragma unroll
    for (int kc = 0; kc < KS; kc++) s += ypart[(size_t)kc*B*E*D + i];
    y[i] = s;
}

// ---------------- final: out = h + combine @ y ----------------
__global__ void final_kernel(const float* __restrict__ h, const float* __restrict__ comb,
                             const float* __restrict__ y, float* __restrict__ out) {
    int row = blockIdx.x;
    int b = row / T;
    float c[E];
    const float* cp = comb + (size_t)row*E;
#pragma unroll
    for (int e = 0; e < E; e++) c[e] = cp[e];
#pragma unroll
    for (int i = 0; i < 8; i++) {
        int d = threadIdx.x + i*256;
        float acc = h[(size_t)row*D + d];
#pragma unroll
        for (int e = 0; e < E; e++) acc += c[e] * y[((size_t)b*E + e)*D + d];
        out[(size_t)row*D + d] = acc;
    }
}

// ---------------- launch ----------------
extern "C" void kernel_launch(void* const* d_in, const int* in_sizes, int n_in,
                              void* d_out, int out_size) {
    const float* x   = (const float*)d_in[0];
    const float* fc  = (const float*)d_in[3];
    const float* wq  = (const float*)d_in[4];
    const float* wk  = (const float*)d_in[5];
    const float* wv  = (const float*)d_in[6];
    const float* wo  = (const float*)d_in[7];
    const float* sw  = (const float*)d_in[8];
    const float* w1  = (const float*)d_in[9];
    const float* w3  = (const float*)d_in[10];
    const float* w2  = (const float*)d_in[11];
    const float* anw = (const float*)d_in[12];
    const float* fnw = (const float*)d_in[13];
    const int* causal = (const int*)d_in[14];
    float* out = (float*)d_out;

    float *xn, *h, *hn, *logits, *disp, *comb, *slots, *gact, *ypart, *y;
    __half *ah, *al, *qh, *kh, *kl, *vh, *vl, *oh, *ol, *wth;
    cudaGetSymbolAddress((void**)&xn,    g_xn);
    cudaGetSymbolAddress((void**)&h,     g_h);
    cudaGetSymbolAddress((void**)&hn,    g_hn);
    cudaGetSymbolAddress((void**)&logits,g_logits);
    cudaGetSymbolAddress((void**)&disp,  g_disp);
    cudaGetSymbolAddress((void**)&comb,  g_comb);
    cudaGetSymbolAddress((void**)&slots, g_slots);
    cudaGetSymbolAddress((void**)&gact,  g_gact);
    cudaGetSymbolAddress((void**)&ypart, g_ypart);
    cudaGetSymbolAddress((void**)&y,     g_y);
    cudaGetSymbolAddress((void**)&ah,    g_ah);
    cudaGetSymbolAddress((void**)&al,    g_al);
    cudaGetSymbolAddress((void**)&qh,    g_qh);
    cudaGetSymbolAddress((void**)&kh,    g_kh);
    cudaGetSymbolAddress((void**)&kl,    g_kl);
    cudaGetSymbolAddress((void**)&vh,    g_vh);
    cudaGetSymbolAddress((void**)&vl,    g_vl);
    cudaGetSymbolAddress((void**)&oh,    g_oh);
    cudaGetSymbolAddress((void**)&ol,    g_ol);
    cudaGetSymbolAddress((void**)&wth,   g_wth);

    cudaFuncSetAttribute(mma_gemm_kernel, cudaFuncAttributeMaxDynamicSharedMemorySize, MMA_SMEM);
    cudaFuncSetAttribute(fattn_kernel, cudaFuncAttributeMaxDynamicSharedMemorySize, FATTN_SMEM);

    const size_t NK = (size_t)D * D;

    rmsnorm_kernel<<<MT, 256>>>(x, anw, xn, ah, al);

    dim3 wgrid(D/32, D/32);
    wsplit_kernel<<<wgrid, dim3(32,8)>>>(wq, wth + 0*NK);
    wsplit_kernel<<<wgrid, dim3(32,8)>>>(wk, wth + 1*NK);
    wsplit_kernel<<<wgrid, dim3(32,8)>>>(wv, wth + 2*NK);
    wsplit_kernel<<<wgrid, dim3(32,8)>>>(wo, wth + 3*NK);

    dim3 gg(D/GN, MT/GM);
    mma_gemm_kernel<<<gg, 256, MMA_SMEM>>>(ah, al, wth + 0*NK, nullptr, nullptr,
                                           1, fc, qh, nullptr, MT, D, D);
    mma_gemm_kernel<<<gg, 256, MMA_SMEM>>>(ah, al, wth + 1*NK, nullptr, nullptr,
                                           1, fc, kh, kl, MT, D, D);
    mma_gemm_kernel<<<gg, 256, MMA_SMEM>>>(ah, al, wth + 2*NK, nullptr, nullptr,
                                           2, nullptr, vh, vl, MT, D, D);

    fattn_kernel<<<dim3(T/AQ, H, B), 256, FATTN_SMEM>>>(qh, kh, kl, vh, vl, oh, ol, causal);

    mma_gemm_kernel<<<gg, 256, MMA_SMEM>>>(oh, ol, wth + 3*NK, xn, h,
                                           0, nullptr, nullptr, nullptr, MT, D, D);

    rmsnorm_kernel<<<MT, 256>>>(h, fnw, hn, nullptr, nullptr);

    logits_kernel<<<MT, 256>>>(hn, sw, logits);
    dispatch_softmax_kernel<<<B*E, 256>>>(logits, disp);
    combine_softmax_kernel<<<MT/256, 256>>>(logits, comb);

    slots_all_kernel<<<dim3(D/256, B), 256>>>(disp, hn, slots);
    gact_kernel<<<dim3(FH/256, E), 256>>>(slots, w1, w3, gact);
    w2_kernel<<<dim3(D/256, E, KS), 256>>>(gact, w2, ypart);
    yreduce_kernel<<<(B*E*D)/256, 256>>>(ypart, y);

    final_kernel<<<MT, 256>>>(h, comb, y, out);
}

// round 13
// speedup vs baseline: 1.7624x; 1.3531x over previous
#include <cuda_runtime.h>
#include <cuda_fp16.h>
#include <cstdint>
#include <cstddef>

#define B 2
#define T 2048
#define D 2048
#define H 16
#define HD 128
#define E 8
#define FH 8192
#define EPSV 1e-6f
#define MT (B*T)

// ---------------- scratch (device globals; no allocation) ----------------
__device__ float g_xn  [(size_t)B*T*D];
__device__ float g_h   [(size_t)B*T*D];
__device__ float g_hn  [(size_t)B*T*D];
__device__ float g_logits[(size_t)B*T*E];
__device__ float g_disp  [(size_t)B*T*E];
__device__ float g_comb  [(size_t)B*T*E];
__device__ float g_slots [(size_t)B*E*D];
__device__ float g_gact  [(size_t)B*E*FH];
#define KS 8
__device__ float g_ypart[(size_t)KS*B*E*D];
__device__ float g_y    [(size_t)B*E*D];
// fp16 operands (1-term)
__device__ __half g_ah[(size_t)MT*D];
__device__ __half g_qh[(size_t)MT*D];
__device__ __half g_kh[(size_t)MT*D];
__device__ __half g_vh[(size_t)MT*D];
__device__ __half g_oh[(size_t)MT*D];
__device__ __half g_wth[(size_t)4*D*D];   // W^T fp16

// ---------------- helpers ----------------
__device__ __forceinline__ uint32_t smem_u32(const void* p) {
    uint32_t a;
    asm("{ .reg .u64 t; cvta.to.shared.u64 t, %1; cvt.u32.u64 %0, t; }" : "=r"(a) : "l"(p));
    return a;
}
__device__ __forceinline__ void cp_async16(uint32_t saddr, const void* gaddr) {
    asm volatile("cp.async.ca.shared.global [%0], [%1], 16;" :: "r"(saddr), "l"(gaddr));
}
__device__ __forceinline__ void cp_commit() {
    asm volatile("cp.async.commit_group;");
}
template<int N>
__device__ __forceinline__ void cp_wait() {
    asm volatile("cp.async.wait_group %0;" :: "n"(N));
}
__device__ __forceinline__ void ldmx4(uint32_t* r, uint32_t addr) {
    asm volatile("ldmatrix.sync.aligned.m8n8.x4.shared.b16 {%0,%1,%2,%3}, [%4];"
                 : "=r"(r[0]), "=r"(r[1]), "=r"(r[2]), "=r"(r[3]) : "r"(addr));
}
__device__ __forceinline__ void ldmx4t(uint32_t* r, uint32_t addr) {
    asm volatile("ldmatrix.sync.aligned.m8n8.x4.trans.shared.b16 {%0,%1,%2,%3}, [%4];"
                 : "=r"(r[0]), "=r"(r[1]), "=r"(r[2]), "=r"(r[3]) : "r"(addr));
}
__device__ __forceinline__ void mma16816h(float* c, const uint32_t* a, uint32_t b0, uint32_t b1) {
    asm volatile(
        "mma.sync.aligned.m16n8k16.row.col.f32.f16.f16.f32 "
        "{%0,%1,%2,%3}, {%4,%5,%6,%7}, {%8,%9}, {%0,%1,%2,%3};"
        : "+f"(c[0]), "+f"(c[1]), "+f"(c[2]), "+f"(c[3])
        : "r"(a[0]), "r"(a[1]), "r"(a[2]), "r"(a[3]), "r"(b0), "r"(b1));
}
__device__ __forceinline__ float hex2(float x) {
    float r; asm("ex2.approx.f32 %0, %1;" : "=f"(r) : "f"(x)); return r;
}
__device__ __forceinline__ uint32_t packh2(float p0, float p1) {
    __half2 hv = __floats2half2_rn(p0, p1);
    return *reinterpret_cast<uint32_t*>(&hv);
}

// ---------------- rmsnorm (optional fused fp16 convert) ----------------
__global__ void rmsnorm_kernel(const float* __restrict__ x, const float* __restrict__ w,
                               float* __restrict__ out, __half* __restrict__ hi) {
    int row = blockIdx.x;
    const float* xp = x + (size_t)row * D;
    float v[8];
    float ss = 0.f;
#pragma unroll
    for (int i = 0; i < 8; i++) { v[i] = xp[threadIdx.x + i*256]; ss += v[i]*v[i]; }
    __shared__ float red[256];
    red[threadIdx.x] = ss; __syncthreads();
    for (int s = 128; s > 0; s >>= 1) {
        if (threadIdx.x < s) red[threadIdx.x] += red[threadIdx.x + s];
        __syncthreads();
    }
    float rms = rsqrtf(red[0] / (float)D + EPSV);
    float* op = out + (size_t)row * D;
#pragma unroll
    for (int i = 0; i < 8; i++) {
        int d = threadIdx.x + i*256;
        float o = v[i]*rms*w[d];
        op[d] = o;
        if (hi) hi[(size_t)row*D + d] = __float2half_rn(o);
    }
}

// ---------------- transpose weights: W[K,N] -> WT[N,K] fp16 ----------------
__global__ void wsplit_kernel(const float* __restrict__ W, __half* __restrict__ th) {
    __shared__ float t[32][33];
    int n0 = blockIdx.x * 32, k0 = blockIdx.y * 32;
    int tx = threadIdx.x, ty = threadIdx.y;   // 32 x 8
#pragma unroll
    for (int i = 0; i < 4; i++)
        t[ty + 8*i][tx] = W[(size_t)(k0 + ty + 8*i) * D + n0 + tx];
    __syncthreads();
#pragma unroll
    for (int i = 0; i < 4; i++) {
        float v = t[tx][ty + 8*i];
        th[(size_t)(n0 + ty + 8*i) * D + k0 + tx] = __float2half_rn(v);
    }
}

// ---------------- mma.sync GEMM (fp16 1-term): C = A16 @ B16^T ----------------
// mode 0: fp32 C (+Res). mode 1: rope + fp16 out. mode 2: fp16 out.
#define GM 128
#define GN 128
#define GK 32
#define TSTR 40
#define TILE_B2 (128*TSTR*2)
#define STG_B2 (2*TILE_B2)
#define MMA_SMEM (2*STG_B2)

__global__ __launch_bounds__(256, 2)
void mma_gemm_kernel(const __half* __restrict__ Ah, const __half* __restrict__ Bh,
                     const float* __restrict__ Res, float* __restrict__ C,
                     int mode, const float* __restrict__ fc,
                     __half* __restrict__ Chi,
                     int Mdim, int Ndim, int Kdim) {
    extern __shared__ char smem[];
    uint32_t sb = smem_u32(smem);
    int tid = threadIdx.x, lane = tid & 31, warp = tid >> 5;
    int wm = warp & 3, wn = warp >> 2;
    int m0 = blockIdx.y * GM, n0 = blockIdx.x * GN;

    int lrow[2], lcol[2];
    uint32_t sdst[2];
#pragma unroll
    for (int p = 0; p < 2; p++) {
        int idx = tid + p*256;
        lrow[p] = idx >> 2;
        lcol[p] = (idx & 3) * 8;
        sdst[p] = (uint32_t)(lrow[p]*TSTR + lcol[p]) * 2;
    }

    const int nkt = Kdim / GK;

    auto issue = [&](int kt, int stage) {
        uint32_t s0 = sb + stage * STG_B2;
        const __half* srcs[2] = { Ah + (size_t)m0 * Kdim, Bh + (size_t)n0 * Kdim };
#pragma unroll
        for (int tl = 0; tl < 2; tl++) {
#pragma unroll
            for (int p = 0; p < 2; p++) {
                const __half* g = srcs[tl] + (size_t)lrow[p] * Kdim + kt*GK + lcol[p];
                cp_async16(s0 + tl*TILE_B2 + sdst[p], g);
            }
        }
        cp_commit();
    };

    float acc[2][8][4];
#pragma unroll
    for (int mi = 0; mi < 2; mi++)
#pragma unroll
        for (int nj = 0; nj < 8; nj++)
#pragma unroll
            for (int c = 0; c < 4; c++) acc[mi][nj][c] = 0.f;

    int lr = lane & 15, lc8 = (lane >> 4) << 3;

    issue(0, 0);

    for (int kt = 0; kt < nkt; kt++) {
        int stage = kt & 1;
        if (kt + 1 < nkt) { issue(kt + 1, stage ^ 1); cp_wait<1>(); }
        else              { cp_wait<0>(); }
        __syncthreads();

        uint32_t s0 = sb + stage * STG_B2;
        uint32_t sAh = s0, sBh = s0 + TILE_B2;

#pragma unroll
        for (int ks = 0; ks < 2; ks++) {
            int kc = ks*16 + lc8;
            uint32_t ah[2][4], bh[4][4];
#pragma unroll
            for (int mi = 0; mi < 2; mi++)
                ldmx4(ah[mi], sAh + (uint32_t)((wm*32 + mi*16 + lr)*TSTR + kc) * 2);
#pragma unroll
            for (int njp = 0; njp < 4; njp++)
                ldmx4(bh[njp], sBh + (uint32_t)((wn*64 + njp*16 + lr)*TSTR + kc) * 2);
#pragma unroll
            for (int mi = 0; mi < 2; mi++)
#pragma unroll
                for (int njp = 0; njp < 4; njp++) {
                    mma16816h(acc[mi][2*njp+0], ah[mi], bh[njp][0], bh[njp][2]);
                    mma16816h(acc[mi][2*njp+1], ah[mi], bh[njp][1], bh[njp][3]);
                }
        }
        __syncthreads();
    }

    int g = lane >> 2, tg = lane & 3;
    if (mode == 0) {
#pragma unroll
        for (int mi = 0; mi < 2; mi++) {
            size_t row0 = (size_t)(m0 + wm*32 + mi*16 + g);
#pragma unroll
            for (int nj = 0; nj < 8; nj++) {
                size_t col = (size_t)(n0 + wn*64 + nj*8 + tg*2);
                float2 v0 = make_float2(acc[mi][nj][0], acc[mi][nj][1]);
                float2 v1 = make_float2(acc[mi][nj][2], acc[mi][nj][3]);
                if (Res) {
                    float2 r0 = *(const float2*)(Res + row0*Ndim + col);
                    float2 r1 = *(const float2*)(Res + (row0+8)*Ndim + col);
                    v0.x += r0.x; v0.y += r0.y; v1.x += r1.x; v1.y += r1.y;
                }
                *(float2*)(C + row0*Ndim + col) = v0;
                *(float2*)(C + (row0+8)*Ndim + col) = v1;
            }
        }
    } else {
#pragma unroll
        for (int mi = 0; mi < 2; mi++) {
            size_t row0 = (size_t)(m0 + wm*32 + mi*16 + g);
            size_t row1 = row0 + 8;
#pragma unroll
            for (int nj = 0; nj < 8; nj++) {
                int col = n0 + wn*64 + nj*8 + tg*2;
                float2 v0 = make_float2(acc[mi][nj][0], acc[mi][nj][1]);
                float2 v1 = make_float2(acc[mi][nj][2], acc[mi][nj][3]);
                if (mode == 1) {
                    int cb = col & (HD - 1);
                    float2 c0 = *(const float2*)(fc + (size_t)(row0 & (T-1))*HD + cb);
                    float2 c1 = *(const float2*)(fc + (size_t)(row1 & (T-1))*HD + cb);
                    v0 = make_float2(v0.x*c0.x - v0.y*c0.y, v0.x*c0.y + v0.y*c0.x);
                    v1 = make_float2(v1.x*c1.x - v1.y*c1.y, v1.x*c1.y + v1.y*c1.x);
                }
                *(uint32_t*)(Chi + row0*Ndim + col) = packh2(v0.x, v0.y);
                *(uint32_t*)(Chi + row1*Ndim + col) = packh2(v1.x, v1.y);
            }
        }
    }
}

// ---------------- flash attention (mma.sync fp16 1-term, MUFU exp) ----------------
#define AQ 128
#define AKV 64
#define ASTRB 272
#define ATILE_B (AKV*ASTRB)
#define ASTG_B (2*ATILE_B)
#define FATTN_SMEM (2*ASTG_B)
#define SCL2 0.12751743867f             // (1/sqrt(128)) * log2(e)

__global__ __launch_bounds__(256)
void fattn_kernel(const __half* __restrict__ Qh,
                  const __half* __restrict__ Kh, const __half* __restrict__ Vh,
                  __half* __restrict__ Oh,
                  const int* __restrict__ causal_flag) {
    extern __shared__ char smem[];
    uint32_t sb = smem_u32(smem);
    int tid = threadIdx.x, lane = tid & 31, warp = tid >> 5;
    int g = lane >> 2, tg = lane & 3;
    int q0 = (gridDim.x - 1 - blockIdx.x) * AQ;   // heavy tiles first
    int h = blockIdx.y, b = blockIdx.z;
    bool causal = (*causal_flag) != 0;
    int wrow = q0 + warp * 16;

    uint32_t s0 = sb, s1 = sb + ASTG_B;

    const size_t bbase = ((size_t)b * T) << 11;
    const size_t hbase = (size_t)h * HD;

    // Q (128 x 128 fp16) fills stage s0 exactly
#pragma unroll
    for (int j = 0; j < 8; j++) {
        int c = tid + j*256;
        int r = c >> 4, col = c & 15;
        cp_async16(s0 + r*ASTRB + col*16,
                   Qh + bbase + ((size_t)(q0 + r) << 11) + hbase + col*8);
    }
    cp_commit();

    auto issue_kv = [&](int kvt, uint32_t stg) {
        int k0 = kvt * AKV;
        const __half* ptrs[2] = {Kh, Vh};
#pragma unroll
        for (int tl = 0; tl < 2; tl++) {
#pragma unroll
            for (int j = 0; j < 4; j++) {
                int c = tid + j*256;
                int r = c >> 4, col = c & 15;
                cp_async16(stg + tl*ATILE_B + r*ASTRB + col*16,
                           ptrs[tl] + bbase + ((size_t)(k0 + r) << 11) + hbase + col*8);
            }
        }
        cp_commit();
    };

    int ntile = causal ? (q0 + AQ)/AKV : T/AKV;
    issue_kv(0, s1);

    cp_wait<1>();
    __syncthreads();

    int lr = lane & 15, c8 = (lane >> 4) << 3;
    uint32_t qf[8][4];
#pragma unroll
    for (int ks = 0; ks < 8; ks++)
        ldmx4(qf[ks], s0 + (warp*16 + lr)*ASTRB + (ks*16 + c8)*2);
    __syncthreads();

    float oa[16][4];
#pragma unroll
    for (int i = 0; i < 16; i++) { oa[i][0]=0.f; oa[i][1]=0.f; oa[i][2]=0.f; oa[i][3]=0.f; }
    float m0 = -1e30f, m1 = -1e30f, l0 = 0.f, l1 = 0.f;

    for (int kvt = 0; kvt < ntile; kvt++) {
        uint32_t cur = (kvt & 1) ? s0 : s1;
        uint32_t nxt = (kvt & 1) ? s1 : s0;
        if (kvt + 1 < ntile) { issue_kv(kvt + 1, nxt); cp_wait<1>(); }
        else                 { cp_wait<0>(); }
        __syncthreads();
        int k0 = kvt * AKV;

        if (!causal || k0 <= wrow + 15) {
            uint32_t KHs = cur, VHs = cur + ATILE_B;
            float sa[8][4];
#pragma unroll
            for (int nj = 0; nj < 8; nj++) { sa[nj][0]=0.f; sa[nj][1]=0.f; sa[nj][2]=0.f; sa[nj][3]=0.f; }
#pragma unroll
            for (int ks = 0; ks < 8; ks++) {
                uint32_t bh[4][4];
#pragma unroll
                for (int n4 = 0; n4 < 4; n4++)
                    ldmx4(bh[n4], KHs + (n4*16 + lr)*ASTRB + (ks*16 + c8)*2);
#pragma unroll
                for (int n4 = 0; n4 < 4; n4++) {
                    mma16816h(sa[2*n4+0], qf[ks], bh[n4][0], bh[n4][2]);
                    mma16816h(sa[2*n4+1], qf[ks], bh[n4][1], bh[n4][3]);
                }
            }
            if (causal && k0 + 63 > wrow) {
#pragma unroll
                for (int nj = 0; nj < 8; nj++) {
                    int col = k0 + nj*8 + 2*tg;
                    if (col     > wrow + g)     sa[nj][0] = -1e30f;
                    if (col + 1 > wrow + g)     sa[nj][1] = -1e30f;
                    if (col     > wrow + g + 8) sa[nj][2] = -1e30f;
                    if (col + 1 > wrow + g + 8) sa[nj][3] = -1e30f;
                }
            }
            float mt0 = -1e30f, mt1 = -1e30f;
#pragma unroll
            for (int nj = 0; nj < 8; nj++) {
                mt0 = fmaxf(mt0, fmaxf(sa[nj][0], sa[nj][1]));
                mt1 = fmaxf(mt1, fmaxf(sa[nj][2], sa[nj][3]));
            }
            mt0 = fmaxf(mt0, __shfl_xor_sync(0xffffffffu, mt0, 1));
            mt0 = fmaxf(mt0, __shfl_xor_sync(0xffffffffu, mt0, 2));
            mt1 = fmaxf(mt1, __shfl_xor_sync(0xffffffffu, mt1, 1));
            mt1 = fmaxf(mt1, __shfl_xor_sync(0xffffffffu, mt1, 2));
            float mn0 = fmaxf(m0, mt0), mn1 = fmaxf(m1, mt1);
            float al0 = hex2((m0 - mn0)*SCL2), al1 = hex2((m1 - mn1)*SCL2);
            float nb0 = mn0 * SCL2, nb1 = mn1 * SCL2;
            float ls0 = 0.f, ls1 = 0.f;
#pragma unroll
            for (int nj = 0; nj < 8; nj++) {
                float p0 = hex2(fmaf(sa[nj][0], SCL2, -nb0));
                float p1 = hex2(fmaf(sa[nj][1], SCL2, -nb0));
                float p2 = hex2(fmaf(sa[nj][2], SCL2, -nb1));
                float p3 = hex2(fmaf(sa[nj][3], SCL2, -nb1));
                sa[nj][0]=p0; sa[nj][1]=p1; sa[nj][2]=p2; sa[nj][3]=p3;
                ls0 += p0 + p1; ls1 += p2 + p3;
            }
            ls0 += __shfl_xor_sync(0xffffffffu, ls0, 1);
            ls0 += __shfl_xor_sync(0xffffffffu, ls0, 2);
            ls1 += __shfl_xor_sync(0xffffffffu, ls1, 1);
            ls1 += __shfl_xor_sync(0xffffffffu, ls1, 2);
            l0 = l0*al0 + ls0; l1 = l1*al1 + ls1;
            m0 = mn0; m1 = mn1;
#pragma unroll
            for (int i2 = 0; i2 < 16; i2++) {
                oa[i2][0]*=al0; oa[i2][1]*=al0; oa[i2][2]*=al1; oa[i2][3]*=al1;
            }
            uint32_t pf[4][4];
#pragma unroll
            for (int kt = 0; kt < 4; kt++) {
                pf[kt][0] = packh2(sa[2*kt][0],   sa[2*kt][1]);
                pf[kt][1] = packh2(sa[2*kt][2],   sa[2*kt][3]);
                pf[kt][2] = packh2(sa[2*kt+1][0], sa[2*kt+1][1]);
                pf[kt][3] = packh2(sa[2*kt+1][2], sa[2*kt+1][3]);
            }
            int mlane = lane >> 3;
            int kvr = (mlane & 1)*8 + (lane & 7);
            int hdc = (mlane >> 1)*8;
#pragma unroll
            for (int kt = 0; kt < 4; kt++) {
                uint32_t rbase = (uint32_t)((kt*16 + kvr)*ASTRB + hdc*2);
#pragma unroll
                for (int hp = 0; hp < 8; hp++) {
                    uint32_t vfh[4];
                    ldmx4t(vfh, VHs + rbase + hp*32);
                    mma16816h(oa[2*hp+0], pf[kt], vfh[0], vfh[1]);
                    mma16816h(oa[2*hp+1], pf[kt], vfh[2], vfh[3]);
                }
            }
        }
        __syncthreads();
    }

    float inv0 = 1.f / l0, inv1 = 1.f / l1;
    size_t off0 = bbase + ((size_t)(wrow + g) << 11) + hbase;
    size_t off1 = bbase + ((size_t)(wrow + g + 8) << 11) + hbase;
#pragma unroll
    for (int hp = 0; hp < 16; hp++) {
        int hd = hp*8 + 2*tg;
        *(uint32_t*)(Oh + off0 + hd) = packh2(oa[hp][0]*inv0, oa[hp][1]*inv0);
        *(uint32_t*)(Oh + off1 + hd) = packh2(oa[hp][2]*inv1, oa[hp][3]*inv1);
    }
}

// ---------------- router logits: hn @ slots_w (D x E) ----------------
__global__ void logits_kernel(const float* __restrict__ hn, const float* __restrict__ sw,
                              float* __restrict__ out) {
    int row = blockIdx.x;
    const float* hp = hn + (size_t)row * D;
    float acc[E];
#pragma unroll
    for (int e = 0; e < E; e++) acc[e] = 0.f;
#pragma unroll
    for (int i = 0; i < 8; i++) {
        int d = threadIdx.x + i*256;
        float hv = hp[d];
        const float* swp = sw + (size_t)d * E;
#pragma unroll
        for (int e = 0; e < E; e++) acc[e] += hv * swp[e];
    }
#pragma unroll
    for (int e = 0; e < E; e++)
        for (int o = 16; o > 0; o >>= 1) acc[e] += __shfl_xor_sync(0xffffffffu, acc[e], o);
    __shared__ float red[8][E];
    int warp = threadIdx.x >> 5, lane = threadIdx.x & 31;
    if (lane == 0)
#pragma unroll
        for (int e = 0; e < E; e++) red[warp][e] = acc[e];
    __syncthreads();
    if (threadIdx.x < E) {
        float s = 0.f;
#pragma unroll
        for (int w = 0; w < 8; w++) s += red[w][threadIdx.x];
        out[(size_t)row*E + threadIdx.x] = s;
    }
}

// ---------------- dispatch softmax (over T, per (b,e)) ----------------
__global__ void dispatch_softmax_kernel(const float* __restrict__ lg, float* __restrict__ out) {
    int b = blockIdx.x >> 3, e = blockIdx.x & 7;
    const float* lp = lg + (size_t)b*T*E + e;
    float v[8];
    float m = -1e30f;
#pragma unroll
    for (int i = 0; i < 8; i++) {
        v[i] = lp[(size_t)(threadIdx.x + i*256)*E];
        m = fmaxf(m, v[i]);
    }
    __shared__ float red[256];
    red[threadIdx.x] = m; __syncthreads();
    for (int s = 128; s > 0; s >>= 1) {
        if (threadIdx.x < s) red[threadIdx.x] = fmaxf(red[threadIdx.x], red[threadIdx.x + s]);
        __syncthreads();
    }
    m = red[0]; __syncthreads();
    float ssum = 0.f;
#pragma unroll
    for (int i = 0; i < 8; i++) { v[i] = __expf(v[i] - m); ssum += v[i]; }
    red[threadIdx.x] = ssum; __syncthreads();
    for (int s = 128; s > 0; s >>= 1) {
        if (threadIdx.x < s) red[threadIdx.x] += red[threadIdx.x + s];
        __syncthreads();
    }
    float inv = 1.f / red[0];
    float* op = out + (size_t)b*T*E + e;
#pragma unroll
    for (int i = 0; i < 8; i++) op[(size_t)(threadIdx.x + i*256)*E] = v[i]*inv;
}

// ---------------- combine softmax (over E, per (b,t)) ----------------
__global__ void combine_softmax_kernel(const float* __restrict__ lg, float* __restrict__ out) {
    int row = blockIdx.x*256 + threadIdx.x;
    const float* lp = lg + (size_t)row * E;
    float m = -1e30f;
#pragma unroll
    for (int e = 0; e < E; e++) m = fmaxf(m, lp[e]);
    float ve[E]; float s = 0.f;
#pragma unroll
    for (int e = 0; e < E; e++) { ve[e] = __expf(lp[e] - m); s += ve[e]; }
    float inv = 1.f / s;
    float* op = out + (size_t)row * E;
#pragma unroll
    for (int e = 0; e < E; e++) op[e] = ve[e]*inv;
}

// ---------------- slots (all experts in one pass) = dispatch^T @ hn ----------------
__global__ void slots_all_kernel(const float* __restrict__ disp, const float* __restrict__ hn,
                                 float* __restrict__ slots) {
    int d = blockIdx.x*256 + threadIdx.x;
    int b = blockIdx.y;
    __shared__ float sd[256][E];
    float acc[E];
#pragma unroll
    for (int e = 0; e < E; e++) acc[e] = 0.f;
    for (int t0 = 0; t0 < T; t0 += 256) {
        __syncthreads();
        const float4* dp = (const float4*)(disp + ((size_t)b*T + t0 + threadIdx.x)*E);
        float4 d0 = dp[0], d1 = dp[1];
        sd[threadIdx.x][0] = d0.x; sd[threadIdx.x][1] = d0.y;
        sd[threadIdx.x][2] = d0.z; sd[threadIdx.x][3] = d0.w;
        sd[threadIdx.x][4] = d1.x; sd[threadIdx.x][5] = d1.y;
        sd[threadIdx.x][6] = d1.z; sd[threadIdx.x][7] = d1.w;
        __syncthreads();
        const float* hp = hn + ((size_t)b*T + t0)*D + d;
#pragma unroll 4
        for (int tt = 0; tt < 256; tt++) {
            float hv = hp[(size_t)tt*D];
#pragma unroll
            for (int e = 0; e < E; e++) acc[e] += sd[tt][e] * hv;
        }
    }
#pragma unroll
    for (int e = 0; e < E; e++) slots[((size_t)b*E + e)*D + d] = acc[e];
}

// ---------------- expert up-proj: silu(slots@w1) * (slots@w3) ----------------
__global__ void gact_kernel(const float* __restrict__ slots, const float* __restrict__ w1,
                            const float* __restrict__ w3, float* __restrict__ gact) {
    int hcol = blockIdx.x*256 + threadIdx.x;
    int e = blockIdx.y;
    __shared__ float s0[D], s1[D];
    for (int i = threadIdx.x; i < D; i += 256) {
        s0[i] = slots[((size_t)0*E + e)*D + i];
        s1[i] = slots[((size_t)1*E + e)*D + i];
    }
    __syncthreads();
    float a10 = 0.f, a11 = 0.f, a30 = 0.f, a31 = 0.f;
    const float* w1p = w1 + (size_t)e*D*FH + hcol;
    const float* w3p = w3 + (size_t)e*D*FH + hcol;
#pragma unroll 8
    for (int dd = 0; dd < D; dd++) {
        float w1v = w1p[(size_t)dd*FH];
        float w3v = w3p[(size_t)dd*FH];
        a10 += s0[dd]*w1v; a11 += s1[dd]*w1v;
        a30 += s0[dd]*w3v; a31 += s1[dd]*w3v;
    }
    float g0 = a10 / (1.f + __expf(-a10)) * a30;
    float g1 = a11 / (1.f + __expf(-a11)) * a31;
    gact[((size_t)0*E + e)*FH + hcol] = g0;
    gact[((size_t)1*E + e)*FH + hcol] = g1;
}

// ---------------- expert down-proj, split-K partials ----------------
__global__ void w2_kernel(const float* __restrict__ gact, const float* __restrict__ w2,
                          float* __restrict__ ypart) {
    const int CH = FH / KS;
    int d = blockIdx.x*256 + threadIdx.x;
    int e = blockIdx.y;
    int kc = blockIdx.z;
    __shared__ float gg0[FH / KS], gg1[FH / KS];
    for (int i = threadIdx.x; i < CH; i += 256) {
        gg0[i] = gact[((size_t)0*E + e)*FH + kc*CH + i];
        gg1[i] = gact[((size_t)1*E + e)*FH + kc*CH + i];
    }
    __syncthreads();
    float a0 = 0.f, a1 = 0.f;
    const float* w2p = w2 + ((size_t)e*FH + (size_t)kc*CH)*D + d;
#pragma unroll 8
    for (int hh = 0; hh < CH; hh++) {
        float wv = w2p[(size_t)hh*D];
        a0 += gg0[hh]*wv; a1 += gg1[hh]*wv;
    }
    ypart[((size_t)kc*B*E + 0*E + e)*D + d] = a0;
    ypart[((size_t)kc*B*E + 1*E + e)*D + d] = a1;
}

__global__ void yreduce_kernel(const float* __restrict__ ypart, float* __restrict__ y) {
    int i = blockIdx.x*256 + threadIdx.x;
    float s = 0.f;
#pragma unroll
    for (int kc = 0; kc < KS; kc++) s += ypart[(size_t)kc*B*E*D + i];
    y[i] = s;
}

// ---------------- final: out = h + combine @ y ----------------
__global__ void final_kernel(const float* __restrict__ h, const float* __restrict__ comb,
                             const float* __restrict__ y, float* __restrict__ out) {
    int row = blockIdx.x;
    int b = row / T;
    float c[E];
    const float* cp = comb + (size_t)row*E;
#pragma unroll
    for (int e = 0; e < E; e++) c[e] = cp[e];
#pragma unroll
    for (int i = 0; i < 8; i++) {
        int d = threadIdx.x + i*256;
        float acc = h[(size_t)row*D + d];
#pragma unroll
        for (int e = 0; e < E; e++) acc += c[e] * y[((size_t)b*E + e)*D + d];
        out[(size_t)row*D + d] = acc;
    }
}

// ---------------- launch ----------------
extern "C" void kernel_launch(void* const* d_in, const int* in_sizes, int n_in,
                              void* d_out, int out_size) {
    const float* x   = (const float*)d_in[0];
    const float* fc  = (const float*)d_in[3];
    const float* wq  = (const float*)d_in[4];
    const float* wk  = (const float*)d_in[5];
    const float* wv  = (const float*)d_in[6];
    const float* wo  = (const float*)d_in[7];
    const float* sw  = (const float*)d_in[8];
    const float* w1  = (const float*)d_in[9];
    const float* w3  = (const float*)d_in[10];
    const float* w2  = (const float*)d_in[11];
    const float* anw = (const float*)d_in[12];
    const float* fnw = (const float*)d_in[13];
    const int* causal = (const int*)d_in[14];
    float* out = (float*)d_out;

    float *xn, *h, *hn, *logits, *disp, *comb, *slots, *gact, *ypart, *y;
    __half *ah, *qh, *kh, *vh, *oh, *wth;
    cudaGetSymbolAddress((void**)&xn,    g_xn);
    cudaGetSymbolAddress((void**)&h,     g_h);
    cudaGetSymbolAddress((void**)&hn,    g_hn);
    cudaGetSymbolAddress((void**)&logits,g_logits);
    cudaGetSymbolAddress((void**)&disp,  g_disp);
    cudaGetSymbolAddress((void**)&comb,  g_comb);
    cudaGetSymbolAddress((void**)&slots, g_slots);
    cudaGetSymbolAddress((void**)&gact,  g_gact);
    cudaGetSymbolAddress((void**)&ypart, g_ypart);
    cudaGetSymbolAddress((void**)&y,     g_y);
    cudaGetSymbolAddress((void**)&ah,    g_ah);
    cudaGetSymbolAddress((void**)&qh,    g_qh);
    cudaGetSymbolAddress((void**)&kh,    g_kh);
    cudaGetSymbolAddress((void**)&vh,    g_vh);
    cudaGetSymbolAddress((void**)&oh,    g_oh);
    cudaGetSymbolAddress((void**)&wth,   g_wth);

    cudaFuncSetAttribute(mma_gemm_kernel, cudaFuncAttributeMaxDynamicSharedMemorySize, MMA_SMEM);
    cudaFuncSetAttribute(fattn_kernel, cudaFuncAttributeMaxDynamicSharedMemorySize, FATTN_SMEM);

    const size_t NK = (size_t)D * D;

    rmsnorm_kernel<<<MT, 256>>>(x, anw, xn, ah);

    dim3 wgrid(D/32, D/32);
    wsplit_kernel<<<wgrid, dim3(32,8)>>>(wq, wth + 0*NK);
    wsplit_kernel<<<wgrid, dim3(32,8)>>>(wk, wth + 1*NK);
    wsplit_kernel<<<wgrid, dim3(32,8)>>>(wv, wth + 2*NK);
    wsplit_kernel<<<wgrid, dim3(32,8)>>>(wo, wth + 3*NK);

    dim3 gg(D/GN, MT/GM);
    mma_gemm_kernel<<<gg, 256, MMA_SMEM>>>(ah, wth + 0*NK, nullptr, nullptr,
                                           1, fc, qh, MT, D, D);
    mma_gemm_kernel<<<gg, 256, MMA_SMEM>>>(ah, wth + 1*NK, nullptr, nullptr,
                                           1, fc, kh, MT, D, D);
    mma_gemm_kernel<<<gg, 256, MMA_SMEM>>>(ah, wth + 2*NK, nullptr, nullptr,
                                           2, nullptr, vh, MT, D, D);

    fattn_kernel<<<dim3(T/AQ, H, B), 256, FATTN_SMEM>>>(qh, kh, vh, oh, causal);

    mma_gemm_kernel<<<gg, 256, MMA_SMEM>>>(oh, wth + 3*NK, xn, h,
                                           0, nullptr, nullptr, MT, D, D);

    rmsnorm_kernel<<<MT, 256>>>(h, fnw, hn, nullptr);

    logits_kernel<<<MT, 256>>>(hn, sw, logits);
    dispatch_softmax_kernel<<<B*E, 256>>>(logits, disp);
    combine_softmax_kernel<<<MT/256, 256>>>(logits, comb);

    slots_all_kernel<<<dim3(D/256, B), 256>>>(disp, hn, slots);
    gact_kernel<<<dim3(FH/256, E), 256>>>(slots, w1, w3, gact);
    w2_kernel<<<dim3(D/256, E, KS), 256>>>(gact, w2, ypart);
    yreduce_kernel<<<(B*E*D)/256, 256>>>(ypart, y);

    final_kernel<<<MT, 256>>>(h, comb, y, out);
}

// round 14
// speedup vs baseline: 1.9252x; 1.0924x over previous
#include <cuda_runtime.h>
#include <cuda_fp16.h>
#include <cstdint>
#include <cstddef>

#define B 2
#define T 2048
#define D 2048
#define H 16
#define HD 128
#define E 8
#define FH 8192
#define EPSV 1e-6f
#define MT (B*T)

// ---------------- scratch (device globals; no allocation) ----------------
__device__ float g_xn  [(size_t)B*T*D];
__device__ float g_h   [(size_t)B*T*D];
__device__ float g_hn  [(size_t)B*T*D];
__device__ float g_logits[(size_t)B*T*E];
__device__ float g_disp  [(size_t)B*T*E];
__device__ float g_comb  [(size_t)B*T*E];
__device__ float g_slots [(size_t)B*E*D];
__device__ float g_gact  [(size_t)B*E*FH];
#define KS 8
__device__ float g_ypart[(size_t)KS*B*E*D];
__device__ float g_y    [(size_t)B*E*D];
// fp16 operands (1-term)
__device__ __half g_ah[(size_t)MT*D];
__device__ __half g_qh[(size_t)MT*D];
__device__ __half g_kh[(size_t)MT*D];
__device__ __half g_vh[(size_t)MT*D];
__device__ __half g_oh[(size_t)MT*D];
__device__ __half g_wth[(size_t)4*D*D];   // W^T fp16: [wq|wk|wv|wo] as 4 contiguous [D,D]

// ---------------- helpers ----------------
__device__ __forceinline__ uint32_t smem_u32(const void* p) {
    uint32_t a;
    asm("{ .reg .u64 t; cvta.to.shared.u64 t, %1; cvt.u32.u64 %0, t; }" : "=r"(a) : "l"(p));
    return a;
}
__device__ __forceinline__ void cp_async16(uint32_t saddr, const void* gaddr) {
    asm volatile("cp.async.ca.shared.global [%0], [%1], 16;" :: "r"(saddr), "l"(gaddr));
}
__device__ __forceinline__ void cp_commit() {
    asm volatile("cp.async.commit_group;");
}
template<int N>
__device__ __forceinline__ void cp_wait() {
    asm volatile("cp.async.wait_group %0;" :: "n"(N));
}
__device__ __forceinline__ void ldmx4(uint32_t* r, uint32_t addr) {
    asm volatile("ldmatrix.sync.aligned.m8n8.x4.shared.b16 {%0,%1,%2,%3}, [%4];"
                 : "=r"(r[0]), "=r"(r[1]), "=r"(r[2]), "=r"(r[3]) : "r"(addr));
}
__device__ __forceinline__ void ldmx4t(uint32_t* r, uint32_t addr) {
    asm volatile("ldmatrix.sync.aligned.m8n8.x4.trans.shared.b16 {%0,%1,%2,%3}, [%4];"
                 : "=r"(r[0]), "=r"(r[1]), "=r"(r[2]), "=r"(r[3]) : "r"(addr));
}
__device__ __forceinline__ void mma16816h(float* c, const uint32_t* a, uint32_t b0, uint32_t b1) {
    asm volatile(
        "mma.sync.aligned.m16n8k16.row.col.f32.f16.f16.f32 "
        "{%0,%1,%2,%3}, {%4,%5,%6,%7}, {%8,%9}, {%0,%1,%2,%3};"
        : "+f"(c[0]), "+f"(c[1]), "+f"(c[2]), "+f"(c[3])
        : "r"(a[0]), "r"(a[1]), "r"(a[2]), "r"(a[3]), "r"(b0), "r"(b1));
}
__device__ __forceinline__ float hex2(float x) {
    float r; asm("ex2.approx.f32 %0, %1;" : "=f"(r) : "f"(x)); return r;
}
__device__ __forceinline__ uint32_t packh2(float p0, float p1) {
    __half2 hv = __floats2half2_rn(p0, p1);
    return *reinterpret_cast<uint32_t*>(&hv);
}

// ---------------- rmsnorm (optional fused fp16 convert) ----------------
__global__ void rmsnorm_kernel(const float* __restrict__ x, const float* __restrict__ w,
                               float* __restrict__ out, __half* __restrict__ hi) {
    int row = blockIdx.x;
    const float* xp = x + (size_t)row * D;
    float v[8];
    float ss = 0.f;
#pragma unroll
    for (int i = 0; i < 8; i++) { v[i] = xp[threadIdx.x + i*256]; ss += v[i]*v[i]; }
    __shared__ float red[256];
    red[threadIdx.x] = ss; __syncthreads();
    for (int s = 128; s > 0; s >>= 1) {
        if (threadIdx.x < s) red[threadIdx.x] += red[threadIdx.x + s];
        __syncthreads();
    }
    float rms = rsqrtf(red[0] / (float)D + EPSV);
    float* op = out + (size_t)row * D;
#pragma unroll
    for (int i = 0; i < 8; i++) {
        int d = threadIdx.x + i*256;
        float o = v[i]*rms*w[d];
        op[d] = o;
        if (hi) hi[(size_t)row*D + d] = __float2half_rn(o);
    }
}

// ---------------- transpose weights: W[K,N] -> WT[N,K] fp16 ----------------
__global__ void wsplit_kernel(const float* __restrict__ W, __half* __restrict__ th) {
    __shared__ float t[32][33];
    int n0 = blockIdx.x * 32, k0 = blockIdx.y * 32;
    int tx = threadIdx.x, ty = threadIdx.y;   // 32 x 8
#pragma unroll
    for (int i = 0; i < 4; i++)
        t[ty + 8*i][tx] = W[(size_t)(k0 + ty + 8*i) * D + n0 + tx];
    __syncthreads();
#pragma unroll
    for (int i = 0; i < 4; i++) {
        float v = t[tx][ty + 8*i];
        th[(size_t)(n0 + ty + 8*i) * D + k0 + tx] = __float2half_rn(v);
    }
}

// ---------------- mma.sync GEMM (fp16 1-term, GK=64): C = A16 @ B16^T ----------------
// mode 0: fp32 C (+Res). mode 3: fused QKV epilogue (rope on segs 0,1; plain seg 2).
#define GM 128
#define GN 128
#define GK 64
#define TSTR 72                            // 64 + 8 pad (fp16 elems)
#define TILE_B2 (128*TSTR*2)               // 18432
#define STG_B2 (2*TILE_B2)                 // 36864
#define MMA_SMEM (2*STG_B2)                // 73728

__global__ __launch_bounds__(256, 2)
void mma_gemm_kernel(const __half* __restrict__ Ah, const __half* __restrict__ Bh,
                     const float* __restrict__ Res, float* __restrict__ C,
                     int mode, const float* __restrict__ fc,
                     __half* __restrict__ Oq, __half* __restrict__ Ok, __half* __restrict__ Ov,
                     int Kdim) {
    extern __shared__ char smem[];
    uint32_t sb = smem_u32(smem);
    int tid = threadIdx.x, lane = tid & 31, warp = tid >> 5;
    int wm = warp & 3, wn = warp >> 2;
    int m0 = blockIdx.y * GM, n0 = blockIdx.x * GN;

    // loader geometry: tile = 128 rows x 64 cols fp16 = 1024 16B-chunks; 4/thread
    int lrow[4], lcol[4];
    uint32_t sdst[4];
#pragma unroll
    for (int p = 0; p < 4; p++) {
        int idx = tid + p*256;
        lrow[p] = idx >> 3;
        lcol[p] = (idx & 7) * 8;
        sdst[p] = (uint32_t)(lrow[p]*TSTR + lcol[p]) * 2;
    }

    const int nkt = Kdim / GK;    // 32

    auto issue = [&](int kt, int stage) {
        uint32_t s0 = sb + stage * STG_B2;
        const __half* srcs[2] = { Ah + (size_t)m0 * Kdim, Bh + (size_t)n0 * Kdim };
#pragma unroll
        for (int tl = 0; tl < 2; tl++) {
#pragma unroll
            for (int p = 0; p < 4; p++) {
                const __half* g = srcs[tl] + (size_t)lrow[p] * Kdim + kt*GK + lcol[p];
                cp_async16(s0 + tl*TILE_B2 + sdst[p], g);
            }
        }
        cp_commit();
    };

    float acc[2][8][4];
#pragma unroll
    for (int mi = 0; mi < 2; mi++)
#pragma unroll
        for (int nj = 0; nj < 8; nj++)
#pragma unroll
            for (int c = 0; c < 4; c++) acc[mi][nj][c] = 0.f;

    int lr = lane & 15, lc8 = (lane >> 4) << 3;

    issue(0, 0);

    for (int kt = 0; kt < nkt; kt++) {
        int stage = kt & 1;
        if (kt + 1 < nkt) { issue(kt + 1, stage ^ 1); cp_wait<1>(); }
        else              { cp_wait<0>(); }
        __syncthreads();

        uint32_t s0 = sb + stage * STG_B2;
        uint32_t sAh = s0, sBh = s0 + TILE_B2;

#pragma unroll
        for (int ks = 0; ks < 4; ks++) {
            int kc = ks*16 + lc8;
            uint32_t ah[2][4], bh[4][4];
#pragma unroll
            for (int mi = 0; mi < 2; mi++)
                ldmx4(ah[mi], sAh + (uint32_t)((wm*32 + mi*16 + lr)*TSTR + kc) * 2);
#pragma unroll
            for (int njp = 0; njp < 4; njp++)
                ldmx4(bh[njp], sBh + (uint32_t)((wn*64 + njp*16 + lr)*TSTR + kc) * 2);
#pragma unroll
            for (int mi = 0; mi < 2; mi++)
#pragma unroll
                for (int njp = 0; njp < 4; njp++) {
                    mma16816h(acc[mi][2*njp+0], ah[mi], bh[njp][0], bh[njp][2]);
                    mma16816h(acc[mi][2*njp+1], ah[mi], bh[njp][1], bh[njp][3]);
                }
        }
        __syncthreads();
    }

    int g = lane >> 2, tg = lane & 3;
    if (mode == 0) {
#pragma unroll
        for (int mi = 0; mi < 2; mi++) {
            size_t row0 = (size_t)(m0 + wm*32 + mi*16 + g);
#pragma unroll
            for (int nj = 0; nj < 8; nj++) {
                size_t col = (size_t)(n0 + wn*64 + nj*8 + tg*2);
                float2 v0 = make_float2(acc[mi][nj][0], acc[mi][nj][1]);
                float2 v1 = make_float2(acc[mi][nj][2], acc[mi][nj][3]);
                if (Res) {
                    float2 r0 = *(const float2*)(Res + row0*D + col);
                    float2 r1 = *(const float2*)(Res + (row0+8)*D + col);
                    v0.x += r0.x; v0.y += r0.y; v1.x += r1.x; v1.y += r1.y;
                }
                *(float2*)(C + row0*D + col) = v0;
                *(float2*)(C + (row0+8)*D + col) = v1;
            }
        }
    } else {
        // fused QKV epilogue: segment by n0
        int seg = n0 >> 11;                  // n0 / D
        int nseg0 = n0 & (D - 1);
        __half* dst = (seg == 0) ? Oq : ((seg == 1) ? Ok : Ov);
        bool do_rope = (seg < 2);
#pragma unroll
        for (int mi = 0; mi < 2; mi++) {
            size_t row0 = (size_t)(m0 + wm*32 + mi*16 + g);
            size_t row1 = row0 + 8;
#pragma unroll
            for (int nj = 0; nj < 8; nj++) {
                int col = nseg0 + wn*64 + nj*8 + tg*2;
                float2 v0 = make_float2(acc[mi][nj][0], acc[mi][nj][1]);
                float2 v1 = make_float2(acc[mi][nj][2], acc[mi][nj][3]);
                if (do_rope) {
                    int cb = col & (HD - 1);
                    float2 c0 = *(const float2*)(fc + (size_t)(row0 & (T-1))*HD + cb);
                    float2 c1 = *(const float2*)(fc + (size_t)(row1 & (T-1))*HD + cb);
                    v0 = make_float2(v0.x*c0.x - v0.y*c0.y, v0.x*c0.y + v0.y*c0.x);
                    v1 = make_float2(v1.x*c1.x - v1.y*c1.y, v1.x*c1.y + v1.y*c1.x);
                }
                *(uint32_t*)(dst + row0*D + col) = packh2(v0.x, v0.y);
                *(uint32_t*)(dst + row1*D + col) = packh2(v1.x, v1.y);
            }
        }
    }
}

// ---------------- flash attention (mma.sync fp16 1-term, MUFU exp) ----------------
#define AQ 128
#define AKV 64
#define ASTRB 272
#define ATILE_B (AKV*ASTRB)
#define ASTG_B (2*ATILE_B)
#define FATTN_SMEM (2*ASTG_B)
#define SCL2 0.12751743867f             // (1/sqrt(128)) * log2(e)

__global__ __launch_bounds__(256)
void fattn_kernel(const __half* __restrict__ Qh,
                  const __half* __restrict__ Kh, const __half* __restrict__ Vh,
                  __half* __restrict__ Oh,
                  const int* __restrict__ causal_flag) {
    extern __shared__ char smem[];
    uint32_t sb = smem_u32(smem);
    int tid = threadIdx.x, lane = tid & 31, warp = tid >> 5;
    int g = lane >> 2, tg = lane & 3;
    int q0 = (gridDim.x - 1 - blockIdx.x) * AQ;   // heavy tiles first
    int h = blockIdx.y, b = blockIdx.z;
    bool causal = (*causal_flag) != 0;
    int wrow = q0 + warp * 16;

    uint32_t s0 = sb, s1 = sb + ASTG_B;

    const size_t bbase = ((size_t)b * T) << 11;
    const size_t hbase = (size_t)h * HD;

#pragma unroll
    for (int j = 0; j < 8; j++) {
        int c = tid + j*256;
        int r = c >> 4, col = c & 15;
        cp_async16(s0 + r*ASTRB + col*16,
                   Qh + bbase + ((size_t)(q0 + r) << 11) + hbase + col*8);
    }
    cp_commit();

    auto issue_kv = [&](int kvt, uint32_t stg) {
        int k0 = kvt * AKV;
        const __half* ptrs[2] = {Kh, Vh};
#pragma unroll
        for (int tl = 0; tl < 2; tl++) {
#pragma unroll
            for (int j = 0; j < 4; j++) {
                int c = tid + j*256;
                int r = c >> 4, col = c & 15;
                cp_async16(stg + tl*ATILE_B + r*ASTRB + col*16,
                           ptrs[tl] + bbase + ((size_t)(k0 + r) << 11) + hbase + col*8);
            }
        }
        cp_commit();
    };

    int ntile = causal ? (q0 + AQ)/AKV : T/AKV;
    issue_kv(0, s1);

    cp_wait<1>();
    __syncthreads();

    int lr = lane & 15, c8 = (lane >> 4) << 3;
    uint32_t qf[8][4];
#pragma unroll
    for (int ks = 0; ks < 8; ks++)
        ldmx4(qf[ks], s0 + (warp*16 + lr)*ASTRB + (ks*16 + c8)*2);
    __syncthreads();

    float oa[16][4];
#pragma unroll
    for (int i = 0; i < 16; i++) { oa[i][0]=0.f; oa[i][1]=0.f; oa[i][2]=0.f; oa[i][3]=0.f; }
    float m0 = -1e30f, m1 = -1e30f, l0 = 0.f, l1 = 0.f;

    for (int kvt = 0; kvt < ntile; kvt++) {
        uint32_t cur = (kvt & 1) ? s0 : s1;
        uint32_t nxt = (kvt & 1) ? s1 : s0;
        if (kvt + 1 < ntile) { issue_kv(kvt + 1, nxt); cp_wait<1>(); }
        else                 { cp_wait<0>(); }
        __syncthreads();
        int k0 = kvt * AKV;

        if (!causal || k0 <= wrow + 15) {
            uint32_t KHs = cur, VHs = cur + ATILE_B;
            float sa[8][4];
#pragma unroll
            for (int nj = 0; nj < 8; nj++) { sa[nj][0]=0.f; sa[nj][1]=0.f; sa[nj][2]=0.f; sa[nj][3]=0.f; }
#pragma unroll
            for (int ks = 0; ks < 8; ks++) {
                uint32_t bh[4][4];
#pragma unroll
                for (int n4 = 0; n4 < 4; n4++)
                    ldmx4(bh[n4], KHs + (n4*16 + lr)*ASTRB + (ks*16 + c8)*2);
#pragma unroll
                for (int n4 = 0; n4 < 4; n4++) {
                    mma16816h(sa[2*n4+0], qf[ks], bh[n4][0], bh[n4][2]);
                    mma16816h(sa[2*n4+1], qf[ks], bh[n4][1], bh[n4][3]);
                }
            }
            if (causal && k0 + 63 > wrow) {
#pragma unroll
                for (int nj = 0; nj < 8; nj++) {
                    int col = k0 + nj*8 + 2*tg;
                    if (col     > wrow + g)     sa[nj][0] = -1e30f;
                    if (col + 1 > wrow + g)     sa[nj][1] = -1e30f;
                    if (col     > wrow + g + 8) sa[nj][2] = -1e30f;
                    if (col + 1 > wrow + g + 8) sa[nj][3] = -1e30f;
                }
            }
            float mt0 = -1e30f, mt1 = -1e30f;
#pragma unroll
            for (int nj = 0; nj < 8; nj++) {
                mt0 = fmaxf(mt0, fmaxf(sa[nj][0], sa[nj][1]));
                mt1 = fmaxf(mt1, fmaxf(sa[nj][2], sa[nj][3]));
            }
            mt0 = fmaxf(mt0, __shfl_xor_sync(0xffffffffu, mt0, 1));
            mt0 = fmaxf(mt0, __shfl_xor_sync(0xffffffffu, mt0, 2));
            mt1 = fmaxf(mt1, __shfl_xor_sync(0xffffffffu, mt1, 1));
            mt1 = fmaxf(mt1, __shfl_xor_sync(0xffffffffu, mt1, 2));
            float mn0 = fmaxf(m0, mt0), mn1 = fmaxf(m1, mt1);
            float al0 = hex2((m0 - mn0)*SCL2), al1 = hex2((m1 - mn1)*SCL2);
            float nb0 = mn0 * SCL2, nb1 = mn1 * SCL2;
            float ls0 = 0.f, ls1 = 0.f;
#pragma unroll
            for (int nj = 0; nj < 8; nj++) {
                float p0 = hex2(fmaf(sa[nj][0], SCL2, -nb0));
                float p1 = hex2(fmaf(sa[nj][1], SCL2, -nb0));
                float p2 = hex2(fmaf(sa[nj][2], SCL2, -nb1));
                float p3 = hex2(fmaf(sa[nj][3], SCL2, -nb1));
                sa[nj][0]=p0; sa[nj][1]=p1; sa[nj][2]=p2; sa[nj][3]=p3;
                ls0 += p0 + p1; ls1 += p2 + p3;
            }
            ls0 += __shfl_xor_sync(0xffffffffu, ls0, 1);
            ls0 += __shfl_xor_sync(0xffffffffu, ls0, 2);
            ls1 += __shfl_xor_sync(0xffffffffu, ls1, 1);
            ls1 += __shfl_xor_sync(0xffffffffu, ls1, 2);
            l0 = l0*al0 + ls0; l1 = l1*al1 + ls1;
            m0 = mn0; m1 = mn1;
#pragma unroll
            for (int i2 = 0; i2 < 16; i2++) {
                oa[i2][0]*=al0; oa[i2][1]*=al0; oa[i2][2]*=al1; oa[i2][3]*=al1;
            }
            uint32_t pf[4][4];
#pragma unroll
            for (int kt = 0; kt < 4; kt++) {
                pf[kt][0] = packh2(sa[2*kt][0],   sa[2*kt][1]);
                pf[kt][1] = packh2(sa[2*kt][2],   sa[2*kt][3]);
                pf[kt][2] = packh2(sa[2*kt+1][0], sa[2*kt+1][1]);
                pf[kt][3] = packh2(sa[2*kt+1][2], sa[2*kt+1][3]);
            }
            int mlane = lane >> 3;
            int kvr = (mlane & 1)*8 + (lane & 7);
            int hdc = (mlane >> 1)*8;
#pragma unroll
            for (int kt = 0; kt < 4; kt++) {
                uint32_t rbase = (uint32_t)((kt*16 + kvr)*ASTRB + hdc*2);
#pragma unroll
                for (int hp = 0; hp < 8; hp++) {
                    uint32_t vfh[4];
                    ldmx4t(vfh, VHs + rbase + hp*32);
                    mma16816h(oa[2*hp+0], pf[kt], vfh[0], vfh[1]);
                    mma16816h(oa[2*hp+1], pf[kt], vfh[2], vfh[3]);
                }
            }
        }
        __syncthreads();
    }

    float inv0 = 1.f / l0, inv1 = 1.f / l1;
    size_t off0 = bbase + ((size_t)(wrow + g) << 11) + hbase;
    size_t off1 = bbase + ((size_t)(wrow + g + 8) << 11) + hbase;
#pragma unroll
    for (int hp = 0; hp < 16; hp++) {
        int hd = hp*8 + 2*tg;
        *(uint32_t*)(Oh + off0 + hd) = packh2(oa[hp][0]*inv0, oa[hp][1]*inv0);
        *(uint32_t*)(Oh + off1 + hd) = packh2(oa[hp][2]*inv1, oa[hp][3]*inv1);
    }
}

// ---------------- router logits: hn @ slots_w (D x E) ----------------
__global__ void logits_kernel(const float* __restrict__ hn, const float* __restrict__ sw,
                              float* __restrict__ out) {
    int row = blockIdx.x;
    const float* hp = hn + (size_t)row * D;
    float acc[E];
#pragma unroll
    for (int e = 0; e < E; e++) acc[e] = 0.f;
#pragma unroll
    for (int i = 0; i < 8; i++) {
        int d = threadIdx.x + i*256;
        float hv = hp[d];
        const float* swp = sw + (size_t)d * E;
#pragma unroll
        for (int e = 0; e < E; e++) acc[e] += hv * swp[e];
    }
#pragma unroll
    for (int e = 0; e < E; e++)
        for (int o = 16; o > 0; o >>= 1) acc[e] += __shfl_xor_sync(0xffffffffu, acc[e], o);
    __shared__ float red[8][E];
    int warp = threadIdx.x >> 5, lane = threadIdx.x & 31;
    if (lane == 0)
#pragma unroll
        for (int e = 0; e < E; e++) red[warp][e] = acc[e];
    __syncthreads();
    if (threadIdx.x < E) {
        float s = 0.f;
#pragma unroll
        for (int w = 0; w < 8; w++) s += red[w][threadIdx.x];
        out[(size_t)row*E + threadIdx.x] = s;
    }
}

// ---------------- dispatch softmax (over T, per (b,e)) ----------------
__global__ void dispatch_softmax_kernel(const float* __restrict__ lg, float* __restrict__ out) {
    int b = blockIdx.x >> 3, e = blockIdx.x & 7;
    const float* lp = lg + (size_t)b*T*E + e;
    float v[8];
    float m = -1e30f;
#pragma unroll
    for (int i = 0; i < 8; i++) {
        v[i] = lp[(size_t)(threadIdx.x + i*256)*E];
        m = fmaxf(m, v[i]);
    }
    __shared__ float red[256];
    red[threadIdx.x] = m; __syncthreads();
    for (int s = 128; s > 0; s >>= 1) {
        if (threadIdx.x < s) red[threadIdx.x] = fmaxf(red[threadIdx.x], red[threadIdx.x + s]);
        __syncthreads();
    }
    m = red[0]; __syncthreads();
    float ssum = 0.f;
#pragma unroll
    for (int i = 0; i < 8; i++) { v[i] = __expf(v[i] - m); ssum += v[i]; }
    red[threadIdx.x] = ssum; __syncthreads();
    for (int s = 128; s > 0; s >>= 1) {
        if (threadIdx.x < s) red[threadIdx.x] += red[threadIdx.x + s];
        __syncthreads();
    }
    float inv = 1.f / red[0];
    float* op = out + (size_t)b*T*E + e;
#pragma unroll
    for (int i = 0; i < 8; i++) op[(size_t)(threadIdx.x + i*256)*E] = v[i]*inv;
}

// ---------------- combine softmax (over E, per (b,t)) ----------------
__global__ void combine_softmax_kernel(const float* __restrict__ lg, float* __restrict__ out) {
    int row = blockIdx.x*256 + threadIdx.x;
    const float* lp = lg + (size_t)row * E;
    float m = -1e30f;
#pragma unroll
    for (int e = 0; e < E; e++) m = fmaxf(m, lp[e]);
    float ve[E]; float s = 0.f;
#pragma unroll
    for (int e = 0; e < E; e++) { ve[e] = __expf(lp[e] - m); s += ve[e]; }
    float inv = 1.f / s;
    float* op = out + (size_t)row * E;
#pragma unroll
    for (int e = 0; e < E; e++) op[e] = ve[e]*inv;
}

// ---------------- slots (all experts in one pass) = dispatch^T @ hn ----------------
__global__ void slots_all_kernel(const float* __restrict__ disp, const float* __restrict__ hn,
                                 float* __restrict__ slots) {
    int d = blockIdx.x*256 + threadIdx.x;
    int b = blockIdx.y;
    __shared__ float sd[256][E];
    float acc[E];
#pragma unroll
    for (int e = 0; e < E; e++) acc[e] = 0.f;
    for (int t0 = 0; t0 < T; t0 += 256) {
        __syncthreads();
        const float4* dp = (const float4*)(disp + ((size_t)b*T + t0 + threadIdx.x)*E);
        float4 d0 = dp[0], d1 = dp[1];
        sd[threadIdx.x][0] = d0.x; sd[threadIdx.x][1] = d0.y;
        sd[threadIdx.x][2] = d0.z; sd[threadIdx.x][3] = d0.w;
        sd[threadIdx.x][4] = d1.x; sd[threadIdx.x][5] = d1.y;
        sd[threadIdx.x][6] = d1.z; sd[threadIdx.x][7] = d1.w;
        __syncthreads();
        const float* hp = hn + ((size_t)b*T + t0)*D + d;
#pragma unroll 4
        for (int tt = 0; tt < 256; tt++) {
            float hv = hp[(size_t)tt*D];
#pragma unroll
            for (int e = 0; e < E; e++) acc[e] += sd[tt][e] * hv;
        }
    }
#pragma unroll
    for (int e = 0; e < E; e++) slots[((size_t)b*E + e)*D + d] = acc[e];
}

// ---------------- expert up-proj: silu(slots@w1) * (slots@w3) ----------------
__global__ void gact_kernel(const float* __restrict__ slots, const float* __restrict__ w1,
                            const float* __restrict__ w3, float* __restrict__ gact) {
    int hcol = blockIdx.x*256 + threadIdx.x;
    int e = blockIdx.y;
    __shared__ float s0[D], s1[D];
    for (int i = threadIdx.x; i < D; i += 256) {
        s0[i] = slots[((size_t)0*E + e)*D + i];
        s1[i] = slots[((size_t)1*E + e)*D + i];
    }
    __syncthreads();
    float a10 = 0.f, a11 = 0.f, a30 = 0.f, a31 = 0.f;
    const float* w1p = w1 + (size_t)e*D*FH + hcol;
    const float* w3p = w3 + (size_t)e*D*FH + hcol;
#pragma unroll 8
    for (int dd = 0; dd < D; dd++) {
        float w1v = w1p[(size_t)dd*FH];
        float w3v = w3p[(size_t)dd*FH];
        a10 += s0[dd]*w1v; a11 += s1[dd]*w1v;
        a30 += s0[dd]*w3v; a31 += s1[dd]*w3v;
    }
    float g0 = a10 / (1.f + __expf(-a10)) * a30;
    float g1 = a11 / (1.f + __expf(-a11)) * a31;
    gact[((size_t)0*E + e)*FH + hcol] = g0;
    gact[((size_t)1*E + e)*FH + hcol] = g1;
}

// ---------------- expert down-proj, split-K partials ----------------
__global__ void w2_kernel(const float* __restrict__ gact, const float* __restrict__ w2,
                          float* __restrict__ ypart) {
    const int CH = FH / KS;
    int d = blockIdx.x*256 + threadIdx.x;
    int e = blockIdx.y;
    int kc = blockIdx.z;
    __shared__ float gg0[FH / KS], gg1[FH / KS];
    for (int i = threadIdx.x; i < CH; i += 256) {
        gg0[i] = gact[((size_t)0*E + e)*FH + kc*CH + i];
        gg1[i] = gact[((size_t)1*E + e)*FH + kc*CH + i];
    }
    __syncthreads();
    float a0 = 0.f, a1 = 0.f;
    const float* w2p = w2 + ((size_t)e*FH + (size_t)kc*CH)*D + d;
#pragma unroll 8
    for (int hh = 0; hh < CH; hh++) {
        float wv = w2p[(size_t)hh*D];
        a0 += gg0[hh]*wv; a1 += gg1[hh]*wv;
    }
    ypart[((size_t)kc*B*E + 0*E + e)*D + d] = a0;
    ypart[((size_t)kc*B*E + 1*E + e)*D + d] = a1;
}

__global__ void yreduce_kernel(const float* __restrict__ ypart, float* __restrict__ y) {
    int i = blockIdx.x*256 + threadIdx.x;
    float s = 0.f;
#pragma unroll
    for (int kc = 0; kc < KS; kc++) s += ypart[(size_t)kc*B*E*D + i];
    y[i] = s;
}

// ---------------- final: out = h + combine @ y ----------------
__global__ void final_kernel(const float* __restrict__ h, const float* __restrict__ comb,
                             const float* __restrict__ y, float* __restrict__ out) {
    int row = blockIdx.x;
    int b = row / T;
    float c[E];
    const float* cp = comb + (size_t)row*E;
#pragma unroll
    for (int e = 0; e < E; e++) c[e] = cp[e];
#pragma unroll
    for (int i = 0; i < 8; i++) {
        int d = threadIdx.x + i*256;
        float acc = h[(size_t)row*D + d];
#pragma unroll
        for (int e = 0; e < E; e++) acc += c[e] * y[((size_t)b*E + e)*D + d];
        out[(size_t)row*D + d] = acc;
    }
}

// ---------------- launch ----------------
extern "C" void kernel_launch(void* const* d_in, const int* in_sizes, int n_in,
                              void* d_out, int out_size) {
    const float* x   = (const float*)d_in[0];
    const float* fc  = (const float*)d_in[3];
    const float* wq  = (const float*)d_in[4];
    const float* wk  = (const float*)d_in[5];
    const float* wv  = (const float*)d_in[6];
    const float* wo  = (const float*)d_in[7];
    const float* sw  = (const float*)d_in[8];
    const float* w1  = (const float*)d_in[9];
    const float* w3  = (const float*)d_in[10];
    const float* w2  = (const float*)d_in[11];
    const float* anw = (const float*)d_in[12];
    const float* fnw = (const float*)d_in[13];
    const int* causal = (const int*)d_in[14];
    float* out = (float*)d_out;

    float *xn, *h, *hn, *logits, *disp, *comb, *slots, *gact, *ypart, *y;
    __half *ah, *qh, *kh, *vh, *oh, *wth;
    cudaGetSymbolAddress((void**)&xn,    g_xn);
    cudaGetSymbolAddress((void**)&h,     g_h);
    cudaGetSymbolAddress((void**)&hn,    g_hn);
    cudaGetSymbolAddress((void**)&logits,g_logits);
    cudaGetSymbolAddress((void**)&disp,  g_disp);
    cudaGetSymbolAddress((void**)&comb,  g_comb);
    cudaGetSymbolAddress((void**)&slots, g_slots);
    cudaGetSymbolAddress((void**)&gact,  g_gact);
    cudaGetSymbolAddress((void**)&ypart, g_ypart);
    cudaGetSymbolAddress((void**)&y,     g_y);
    cudaGetSymbolAddress((void**)&ah,    g_ah);
    cudaGetSymbolAddress((void**)&qh,    g_qh);
    cudaGetSymbolAddress((void**)&kh,    g_kh);
    cudaGetSymbolAddress((void**)&vh,    g_vh);
    cudaGetSymbolAddress((void**)&oh,    g_oh);
    cudaGetSymbolAddress((void**)&wth,   g_wth);

    cudaFuncSetAttribute(mma_gemm_kernel, cudaFuncAttributeMaxDynamicSharedMemorySize, MMA_SMEM);
    cudaFuncSetAttribute(fattn_kernel, cudaFuncAttributeMaxDynamicSharedMemorySize, FATTN_SMEM);

    const size_t NK = (size_t)D * D;

    rmsnorm_kernel<<<MT, 256>>>(x, anw, xn, ah);

    dim3 wgrid(D/32, D/32);
    wsplit_kernel<<<wgrid, dim3(32,8)>>>(wq, wth + 0*NK);
    wsplit_kernel<<<wgrid, dim3(32,8)>>>(wk, wth + 1*NK);
    wsplit_kernel<<<wgrid, dim3(32,8)>>>(wv, wth + 2*NK);
    wsplit_kernel<<<wgrid, dim3(32,8)>>>(wo, wth + 3*NK);

    // fused QKV: weight rows [0,3D) of wth, epilogue routes by segment
    mma_gemm_kernel<<<dim3(3*D/GN, MT/GM), 256, MMA_SMEM>>>(
        ah, wth, nullptr, nullptr, 3, fc, qh, kh, vh, D);

    fattn_kernel<<<dim3(T/AQ, H, B), 256, FATTN_SMEM>>>(qh, kh, vh, oh, causal);

    mma_gemm_kernel<<<dim3(D/GN, MT/GM), 256, MMA_SMEM>>>(
        oh, wth + 3*NK, xn, h, 0, nullptr, nullptr, nullptr, nullptr, D);

    rmsnorm_kernel<<<MT, 256>>>(h, fnw, hn, nullptr);

    logits_kernel<<<MT, 256>>>(hn, sw, logits);
    dispatch_softmax_kernel<<<B*E, 256>>>(logits, disp);
    combine_softmax_kernel<<<MT/256, 256>>>(logits, comb);

    slots_all_kernel<<<dim3(D/256, B), 256>>>(disp, hn, slots);
    gact_kernel<<<dim3(FH/256, E), 256>>>(slots, w1, w3, gact);
    w2_kernel<<<dim3(D/256, E, KS), 256>>>(gact, w2, ypart);
    yreduce_kernel<<<(B*E*D)/256, 256>>>(ypart, y);

    final_kernel<<<MT, 256>>>(h, comb, y, out);
}